// round 1
// baseline (speedup 1.0000x reference)
#include <cuda_runtime.h>
#include <cuda_bf16.h>
#include <math.h>

#define TT 16
#define NN 10000
#define EE 320000
#define EN (EE + NN)
#define FF 128
#define HH 256
#define LL 64
#define HL 256
#define LSTM_BLOCKS 8

// ---------------- device scratch (no dynamic allocation allowed) ----------------
__device__ int   d_rowptr[NN + 1];
__device__ int   d_cnt[NN];
__device__ int   d_col[EN];
__device__ float d_nrm_enc[EN];
__device__ float d_nrm_dec[EN];
__device__ float d_deg_enc[NN];
__device__ float d_deg_dec[NN];
__device__ float d_dis_enc[NN];
__device__ float d_dis_dec[NN];
__device__ float d_buf0[(size_t)TT * NN * HH];   // 160000 x 256
__device__ float d_buf1[(size_t)TT * NN * HH];
__device__ float d_gpool[TT * HH];
__device__ float d_zs[TT * LL];
__device__ float d_gates[2][4 * HL];
__device__ float d_zfin[LL];
__device__ unsigned int d_bar;
__device__ int   d_idx64;

// ---------------- edge index dtype detection (int64 vs int32) ----------------
__global__ void detect_kernel(const void* ei) {
    const unsigned int* w = (const unsigned int*)ei;
    int is64 = 1;
    for (int i = 0; i < 64; ++i) {
        if (w[2 * i + 1] != 0u) { is64 = 0; break; }
    }
    d_idx64 = is64;
}

__device__ __forceinline__ void get_edge(const void* ei, int e, int& s, int& d) {
    if (d_idx64) {
        const long long* p = (const long long*)ei;
        s = (int)p[e];
        d = (int)p[EE + e];
    } else {
        const int* p = (const int*)ei;
        s = p[e];
        d = p[EE + e];
    }
}

// ---------------- preprocessing ----------------
__global__ void zero_kernel() {
    int i = blockIdx.x * blockDim.x + threadIdx.x;
    if (i < NN) { d_deg_enc[i] = 0.f; d_deg_dec[i] = 0.f; d_cnt[i] = 0; }
    if (i < TT * HH) d_gpool[i] = 0.f;
    if (i == 0) d_bar = 0u;
}

__global__ void count_kernel(const void* ei, const float* __restrict__ ea) {
    int e = blockIdx.x * blockDim.x + threadIdx.x;
    if (e >= EN) return;
    int s, d; float w;
    if (e < EE) { get_edge(ei, e, s, d); w = ea[e]; }
    else { s = d = e - EE; w = 1.f; }
    atomicAdd(&d_deg_enc[d], w);
    atomicAdd(&d_deg_dec[d], 1.f);
    atomicAdd(&d_cnt[d], 1);
}

__global__ void scan_kernel() {
    __shared__ int sh[1024];
    int tid = threadIdx.x;
    int loc[10];
    int sum = 0;
#pragma unroll
    for (int i = 0; i < 10; ++i) {
        int idx = tid * 10 + i;
        int c = (idx < NN) ? d_cnt[idx] : 0;
        loc[i] = sum;
        sum += c;
    }
    sh[tid] = sum;
    __syncthreads();
    for (int off = 1; off < 1024; off <<= 1) {
        int v = (tid >= off) ? sh[tid - off] : 0;
        __syncthreads();
        sh[tid] += v;
        __syncthreads();
    }
    int excl = sh[tid] - sum;
#pragma unroll
    for (int i = 0; i < 10; ++i) {
        int idx = tid * 10 + i;
        if (idx < NN) {
            d_rowptr[idx] = excl + loc[i];
            d_cnt[idx] = 0;
            d_dis_enc[idx] = rsqrtf(d_deg_enc[idx]);   // deg >= 1 (self-loops)
            d_dis_dec[idx] = rsqrtf(d_deg_dec[idx]);
        }
    }
    if (tid == 1023) d_rowptr[NN] = sh[1023];
}

__global__ void fill_kernel(const void* ei, const float* __restrict__ ea) {
    int e = blockIdx.x * blockDim.x + threadIdx.x;
    if (e >= EN) return;
    int s, d; float w;
    if (e < EE) { get_edge(ei, e, s, d); w = ea[e]; }
    else { s = d = e - EE; w = 1.f; }
    int pos = d_rowptr[d] + atomicAdd(&d_cnt[d], 1);
    d_col[pos] = s;
    d_nrm_enc[pos] = d_dis_enc[s] * w * d_dis_enc[d];
    d_nrm_dec[pos] = d_dis_dec[s] * d_dis_dec[d];
}

// ---------------- CSR aggregation: dst[t,n,:] = sum_e nrm[e]*src[t,col[e],:] ----------------
template<int C, bool RELU>
__global__ void agg_kernel(const float* __restrict__ src, float* __restrict__ dst,
                           const float* __restrict__ nrm, const float* __restrict__ bias) {
    int n = blockIdx.x;
    int t = blockIdx.y;
    int f = threadIdx.x;
    const float* sb = src + (size_t)t * NN * C;
    int beg = d_rowptr[n], end = d_rowptr[n + 1];
    float acc = 0.f;
    for (int e = beg; e < end; ++e) {
        int s = __ldg(&d_col[e]);
        float w = __ldg(&nrm[e]);
        acc += w * __ldg(&sb[(size_t)s * C + f]);
    }
    if (bias) acc += bias[f];
    if (RELU) acc = fmaxf(acc, 0.f);
    dst[((size_t)t * NN + n) * C + f] = acc;
}

// agg + bias + relu + mean-pool over nodes, never materializing Y2
__global__ void agg_pool_kernel(const float* __restrict__ src, const float* __restrict__ bias) {
    int t = blockIdx.y;
    int f = threadIdx.x;   // C = 256
    const float* sb = src + (size_t)t * NN * HH;
    int n0 = blockIdx.x * 16;
    int n1 = min(n0 + 16, NN);
    float b = bias[f];
    float pacc = 0.f;
    for (int n = n0; n < n1; ++n) {
        int beg = d_rowptr[n], end = d_rowptr[n + 1];
        float acc = 0.f;
        for (int e = beg; e < end; ++e) {
            int s = __ldg(&d_col[e]);
            acc += __ldg(&d_nrm_enc[e]) * __ldg(&sb[(size_t)s * HH + f]);
        }
        pacc += fmaxf(acc + b, 0.f);
    }
    atomicAdd(&d_gpool[t * HH + f], pacc * (1.0f / NN));
}

// ---------------- fp32 GEMM: C[M,Nc] = A[M,K] @ B[K,Nc] (+bias)(+relu) ----------------
#define GBM 128
#define GBN 64
#define GBK 16

template<bool HASBIAS, bool RELU>
__global__ __launch_bounds__(256) void gemm_kernel(
    const float* __restrict__ A, const float* __restrict__ B,
    const float* __restrict__ bias, float* __restrict__ C,
    int M, int K, int Ncols)
{
    __shared__ float As[GBK][GBM + 4];
    __shared__ float Bs[GBK][GBN];
    int tid = threadIdx.x;
    int bm = blockIdx.x * GBM;
    int bn = blockIdx.y * GBN;
    int tx = tid & 15;
    int ty = tid >> 4;
    int m0 = ty * 8;
    int n0 = tx * 4;
    int arow = tid >> 2;
    int ac4  = (tid & 3) * 4;
    int brow = tid >> 4;
    int bcol = (tid & 15) * 4;

    float acc[8][4];
#pragma unroll
    for (int i = 0; i < 8; ++i)
#pragma unroll
        for (int j = 0; j < 4; ++j) acc[i][j] = 0.f;

    for (int k0 = 0; k0 < K; k0 += GBK) {
#pragma unroll
        for (int i = 0; i < 2; ++i) {
            int row = arow + i * 64;
            int g = bm + row;
            float4 v = make_float4(0.f, 0.f, 0.f, 0.f);
            if (g < M) v = *(const float4*)(A + (size_t)g * K + k0 + ac4);
            As[ac4 + 0][row] = v.x;
            As[ac4 + 1][row] = v.y;
            As[ac4 + 2][row] = v.z;
            As[ac4 + 3][row] = v.w;
        }
        *(float4*)&Bs[brow][bcol] = *(const float4*)(B + (size_t)(k0 + brow) * Ncols + bn + bcol);
        __syncthreads();
#pragma unroll
        for (int k = 0; k < GBK; ++k) {
            float4 a0 = *(const float4*)&As[k][m0];
            float4 a1 = *(const float4*)&As[k][m0 + 4];
            float4 bv = *(const float4*)&Bs[k][n0];
            float a[8] = {a0.x, a0.y, a0.z, a0.w, a1.x, a1.y, a1.z, a1.w};
            float bb[4] = {bv.x, bv.y, bv.z, bv.w};
#pragma unroll
            for (int i = 0; i < 8; ++i)
#pragma unroll
                for (int j = 0; j < 4; ++j)
                    acc[i][j] += a[i] * bb[j];
        }
        __syncthreads();
    }

    float bb[4] = {0.f, 0.f, 0.f, 0.f};
    if (HASBIAS) {
#pragma unroll
        for (int j = 0; j < 4; ++j) bb[j] = bias[bn + n0 + j];
    }
#pragma unroll
    for (int i = 0; i < 8; ++i) {
        int g = bm + m0 + i;
        if (g < M) {
            float v0 = acc[i][0] + bb[0];
            float v1 = acc[i][1] + bb[1];
            float v2 = acc[i][2] + bb[2];
            float v3 = acc[i][3] + bb[3];
            if (RELU) {
                v0 = fmaxf(v0, 0.f); v1 = fmaxf(v1, 0.f);
                v2 = fmaxf(v2, 0.f); v3 = fmaxf(v3, 0.f);
            }
            *(float4*)(C + (size_t)g * Ncols + bn + n0) = make_float4(v0, v1, v2, v3);
        }
    }
}

// ---------------- z_t = g_t @ Wfce + bfce ----------------
__global__ void proj_z_kernel(const float* __restrict__ Wfce, const float* __restrict__ bfce) {
    int t = blockIdx.x;
    int j = threadIdx.x;   // 64
    float a = bfce[j];
    for (int k = 0; k < HH; ++k)
        a += d_gpool[t * HH + k] * Wfce[k * LL + j];
    d_zs[t * LL + j] = a;
}

// ---------------- persistent 2-layer LSTM + head ----------------
__device__ __forceinline__ float sigm(float x) { return 1.f / (1.f + expf(-x)); }

__device__ __forceinline__ void grid_bar(int round) {
    __syncthreads();
    if (threadIdx.x == 0) {
        __threadfence();
        atomicAdd(&d_bar, 1u);
        unsigned tgt = (unsigned)(LSTM_BLOCKS * round);
        volatile unsigned int* vb = (volatile unsigned int*)&d_bar;
        while (*vb < tgt) { }
        __threadfence();
    }
    __syncthreads();
}

__global__ __launch_bounds__(256) void lstm_kernel(
    const float* __restrict__ Wih0, const float* __restrict__ Whh0,
    const float* __restrict__ bih0, const float* __restrict__ bhh0,
    const float* __restrict__ Wih1, const float* __restrict__ Whh1,
    const float* __restrict__ bih1, const float* __restrict__ bhh1,
    const float* __restrict__ Whead, const float* __restrict__ bhead)
{
    __shared__ float x_sh[LL];
    __shared__ float h1_sh[HL];
    __shared__ float h2_sh[HL];
    __shared__ float part[256];
    int tid = threadIdx.x;
    int b = blockIdx.x;
    int jj = tid & 127;
    int j = b * 128 + jj;
    int kh = tid >> 7;
    int kb = kh * 128;
    float c1 = 0.f, c2 = 0.f;
    h1_sh[tid] = 0.f;
    h2_sh[tid] = 0.f;
    __syncthreads();
    int round = 0;

    for (int t = 0; t < TT; ++t) {
        if (tid < LL) x_sh[tid] = d_zs[t * LL + tid];
        __syncthreads();

        // ---- layer 1 gates ----
        float p0 = 0.f, p1 = 0.f, p2 = 0.f, p3 = 0.f;
#pragma unroll 8
        for (int k = 0; k < 128; k += 4) {
            p0 += h1_sh[kb + k + 0] * Whh0[(size_t)(kb + k + 0) * 1024 + j];
            p1 += h1_sh[kb + k + 1] * Whh0[(size_t)(kb + k + 1) * 1024 + j];
            p2 += h1_sh[kb + k + 2] * Whh0[(size_t)(kb + k + 2) * 1024 + j];
            p3 += h1_sh[kb + k + 3] * Whh0[(size_t)(kb + k + 3) * 1024 + j];
        }
        if (kh == 0) {
#pragma unroll 8
            for (int k = 0; k < LL; k += 4) {
                p0 += x_sh[k + 0] * Wih0[(size_t)(k + 0) * 1024 + j];
                p1 += x_sh[k + 1] * Wih0[(size_t)(k + 1) * 1024 + j];
                p2 += x_sh[k + 2] * Wih0[(size_t)(k + 2) * 1024 + j];
                p3 += x_sh[k + 3] * Wih0[(size_t)(k + 3) * 1024 + j];
            }
        }
        part[tid] = p0 + p1 + p2 + p3;
        __syncthreads();
        int pb = round & 1;
        if (tid < 128)
            __stcg(&d_gates[pb][j], part[jj] + part[jj + 128] + bih0[j] + bhh0[j]);
        round++;
        grid_bar(round);
        {
            float gi = __ldcg(&d_gates[pb][tid]);
            float gf = __ldcg(&d_gates[pb][256 + tid]);
            float gg = __ldcg(&d_gates[pb][512 + tid]);
            float go = __ldcg(&d_gates[pb][768 + tid]);
            c1 = sigm(gf) * c1 + sigm(gi) * tanhf(gg);
            h1_sh[tid] = sigm(go) * tanhf(c1);
        }
        __syncthreads();

        // ---- layer 2 gates (x = h1) ----
        p0 = 0.f; p1 = 0.f; p2 = 0.f; p3 = 0.f;
#pragma unroll 4
        for (int k = 0; k < 128; k += 4) {
            p0 += h2_sh[kb + k + 0] * Whh1[(size_t)(kb + k + 0) * 1024 + j]
                + h1_sh[kb + k + 0] * Wih1[(size_t)(kb + k + 0) * 1024 + j];
            p1 += h2_sh[kb + k + 1] * Whh1[(size_t)(kb + k + 1) * 1024 + j]
                + h1_sh[kb + k + 1] * Wih1[(size_t)(kb + k + 1) * 1024 + j];
            p2 += h2_sh[kb + k + 2] * Whh1[(size_t)(kb + k + 2) * 1024 + j]
                + h1_sh[kb + k + 2] * Wih1[(size_t)(kb + k + 2) * 1024 + j];
            p3 += h2_sh[kb + k + 3] * Whh1[(size_t)(kb + k + 3) * 1024 + j]
                + h1_sh[kb + k + 3] * Wih1[(size_t)(kb + k + 3) * 1024 + j];
        }
        part[tid] = p0 + p1 + p2 + p3;
        __syncthreads();
        pb = round & 1;
        if (tid < 128)
            __stcg(&d_gates[pb][j], part[jj] + part[jj + 128] + bih1[j] + bhh1[j]);
        round++;
        grid_bar(round);
        {
            float gi = __ldcg(&d_gates[pb][tid]);
            float gf = __ldcg(&d_gates[pb][256 + tid]);
            float gg = __ldcg(&d_gates[pb][512 + tid]);
            float go = __ldcg(&d_gates[pb][768 + tid]);
            c2 = sigm(gf) * c2 + sigm(gi) * tanhf(gg);
            h2_sh[tid] = sigm(go) * tanhf(c2);
        }
        __syncthreads();
    }

    if (b == 0 && tid < LL) {
        float a = bhead[tid];
        for (int k = 0; k < HL; ++k)
            a += h2_sh[k] * Whead[k * LL + tid];
        d_zfin[tid] = a;
    }
}

// ---------------- decoder fc: relu(z @ Wfcd + bfcd) -> [N, L] ----------------
__global__ void fcd_kernel(const float* __restrict__ Wfcd, const float* __restrict__ bfcd,
                           float* __restrict__ out) {
    __shared__ float z[LL];
    if (threadIdx.x < LL) z[threadIdx.x] = d_zfin[threadIdx.x];
    __syncthreads();
    int p = blockIdx.x * blockDim.x + threadIdx.x;
    if (p >= NN * LL) return;
    float a = bfcd[p];
#pragma unroll 8
    for (int k = 0; k < LL; ++k)
        a += z[k] * Wfcd[(size_t)k * (NN * LL) + p];
    out[p] = fmaxf(a, 0.f);
}

// ---------------- launch ----------------
extern "C" void kernel_launch(void* const* d_in, const int* in_sizes, int n_in,
                              void* d_out, int out_size) {
    const float* xs        = (const float*)d_in[0];
    const float* edge_attr = (const float*)d_in[1];
    const float* We0  = (const float*)d_in[2];
    const float* be0  = (const float*)d_in[3];
    const float* We1  = (const float*)d_in[4];
    const float* be1  = (const float*)d_in[5];
    const float* Wfce = (const float*)d_in[6];
    const float* bfce = (const float*)d_in[7];
    const float* Wih0 = (const float*)d_in[8];
    const float* Whh0 = (const float*)d_in[9];
    const float* bih0 = (const float*)d_in[10];
    const float* bhh0 = (const float*)d_in[11];
    const float* Wih1 = (const float*)d_in[12];
    const float* Whh1 = (const float*)d_in[13];
    const float* bih1 = (const float*)d_in[14];
    const float* bhh1 = (const float*)d_in[15];
    const float* Whead = (const float*)d_in[16];
    const float* bhead = (const float*)d_in[17];
    const float* Wfcd = (const float*)d_in[18];
    const float* bfcd = (const float*)d_in[19];
    const float* Wd0  = (const float*)d_in[20];
    const float* bd0  = (const float*)d_in[21];
    const float* Wd1  = (const float*)d_in[22];
    const float* bd1  = (const float*)d_in[23];
    const float* Wd2  = (const float*)d_in[24];
    const float* bd2  = (const float*)d_in[25];
    const void*  eidx = d_in[26];

    float *buf0, *buf1, *nrm_enc, *nrm_dec;
    cudaGetSymbolAddress((void**)&buf0, d_buf0);
    cudaGetSymbolAddress((void**)&buf1, d_buf1);
    cudaGetSymbolAddress((void**)&nrm_enc, d_nrm_enc);
    cudaGetSymbolAddress((void**)&nrm_dec, d_nrm_dec);

    // ---- preprocessing: dtype detect, zero, degree/count, scan, CSR fill ----
    detect_kernel<<<1, 1>>>(eidx);
    zero_kernel<<<(NN + 255) / 256, 256>>>();
    count_kernel<<<(EN + 255) / 256, 256>>>(eidx, edge_attr);
    scan_kernel<<<1, 1024>>>();
    fill_kernel<<<(EN + 255) / 256, 256>>>(eidx, edge_attr);

    // ---- encoder (batched over T) ----
    // layer0: aggregate first (128-dim gathers), then GEMM+bias+relu
    agg_kernel<FF, false><<<dim3(NN, TT), FF>>>(xs, buf0, nrm_enc, nullptr);
    gemm_kernel<true, true><<<dim3((TT * NN) / GBM, HH / GBN), 256>>>(
        buf0, We0, be0, buf1, TT * NN, FF, HH);
    // layer1: GEMM first, then aggregate+bias+relu fused with mean-pool
    gemm_kernel<false, false><<<dim3((TT * NN) / GBM, HH / GBN), 256>>>(
        buf1, We1, nullptr, buf0, TT * NN, HH, HH);
    agg_pool_kernel<<<dim3((NN + 15) / 16, TT), HH>>>(buf0, be1);
    proj_z_kernel<<<TT, LL>>>(Wfce, bfce);

    // ---- LSTM (persistent, custom grid barrier) + head ----
    lstm_kernel<<<LSTM_BLOCKS, 256>>>(Wih0, Whh0, bih0, bhh0,
                                      Wih1, Whh1, bih1, bhh1, Whead, bhead);

    // ---- decoder ----
    fcd_kernel<<<(NN * LL) / 256, 256>>>(Wfcd, bfcd, buf1);                 // [N,64]
    agg_kernel<LL, false><<<dim3(NN, 1), LL>>>(buf1, buf0, nrm_dec, nullptr);
    gemm_kernel<true, true><<<dim3((NN + GBM - 1) / GBM, HH / GBN), 256>>>(
        buf0, Wd0, bd0, buf1, NN, LL, HH);
    gemm_kernel<false, false><<<dim3((NN + GBM - 1) / GBM, HH / GBN), 256>>>(
        buf1, Wd1, nullptr, buf0, NN, HH, HH);
    agg_kernel<HH, true><<<dim3(NN, 1), HH>>>(buf0, buf1, nrm_dec, bd1);
    gemm_kernel<false, false><<<dim3((NN + GBM - 1) / GBM, FF / GBN), 256>>>(
        buf1, Wd2, nullptr, buf0, NN, HH, FF);
    agg_kernel<FF, false><<<dim3(NN, 1), FF>>>(buf0, (float*)d_out, nrm_dec, bd2);
}

// round 2
// speedup vs baseline: 1.3132x; 1.3132x over previous
#include <cuda_runtime.h>
#include <cuda_fp16.h>
#include <cuda_bf16.h>
#include <math.h>

#define TT 16
#define NN 10000
#define EE 320000
#define EN (EE + NN)
#define FF 128
#define HH 256
#define LL 64
#define HL 256
#define LSTM_BLOCKS 8

// ---------------- device scratch (no dynamic allocation allowed) ----------------
__device__ int   d_rowptr[NN + 1];
__device__ int   d_cnt[NN];
__device__ int   d_col[EN];
__device__ float d_nrm_enc[EN];
__device__ float d_nrm_dec[EN];
__device__ float d_deg_enc[NN];
__device__ float d_deg_dec[NN];
__device__ float d_dis_enc[NN];
__device__ float d_dis_dec[NN];
__device__ __align__(16) float d_buf0[(size_t)TT * NN * HH];   // 160000 x 256
__device__ __align__(16) float d_buf1[(size_t)TT * NN * HH];
__device__ __align__(16) __half d_hbuf[(size_t)TT * NN * HH];  // half features
__device__ float d_gpool[TT * HH];
__device__ float d_zs[TT * LL];
__device__ float d_gates[2][4 * HL];
__device__ float d_zfin[LL];
__device__ unsigned int d_bar;
__device__ int   d_idx64;

// ---------------- edge index dtype detection (int64 vs int32) ----------------
__global__ void detect_kernel(const void* ei) {
    const unsigned int* w = (const unsigned int*)ei;
    int is64 = 1;
    for (int i = 0; i < 64; ++i) {
        if (w[2 * i + 1] != 0u) { is64 = 0; break; }
    }
    d_idx64 = is64;
}

__device__ __forceinline__ void get_edge(const void* ei, int e, int& s, int& d) {
    if (d_idx64) {
        const long long* p = (const long long*)ei;
        s = (int)p[e];
        d = (int)p[EE + e];
    } else {
        const int* p = (const int*)ei;
        s = p[e];
        d = p[EE + e];
    }
}

// ---------------- preprocessing ----------------
__global__ void zero_kernel() {
    int i = blockIdx.x * blockDim.x + threadIdx.x;
    if (i < NN) { d_deg_enc[i] = 0.f; d_deg_dec[i] = 0.f; d_cnt[i] = 0; }
    if (i < TT * HH) d_gpool[i] = 0.f;
    if (i == 0) d_bar = 0u;
}

__global__ void count_kernel(const void* ei, const float* __restrict__ ea) {
    int e = blockIdx.x * blockDim.x + threadIdx.x;
    if (e >= EN) return;
    int s, d; float w;
    if (e < EE) { get_edge(ei, e, s, d); w = ea[e]; }
    else { s = d = e - EE; w = 1.f; }
    atomicAdd(&d_deg_enc[d], w);
    atomicAdd(&d_deg_dec[d], 1.f);
    atomicAdd(&d_cnt[d], 1);
}

__global__ void scan_kernel() {
    __shared__ int sh[1024];
    int tid = threadIdx.x;
    int loc[10];
    int sum = 0;
#pragma unroll
    for (int i = 0; i < 10; ++i) {
        int idx = tid * 10 + i;
        int c = (idx < NN) ? d_cnt[idx] : 0;
        loc[i] = sum;
        sum += c;
    }
    sh[tid] = sum;
    __syncthreads();
    for (int off = 1; off < 1024; off <<= 1) {
        int v = (tid >= off) ? sh[tid - off] : 0;
        __syncthreads();
        sh[tid] += v;
        __syncthreads();
    }
    int excl = sh[tid] - sum;
#pragma unroll
    for (int i = 0; i < 10; ++i) {
        int idx = tid * 10 + i;
        if (idx < NN) {
            d_rowptr[idx] = excl + loc[i];
            d_cnt[idx] = 0;
            d_dis_enc[idx] = rsqrtf(d_deg_enc[idx]);   // deg >= 1 (self-loops)
            d_dis_dec[idx] = rsqrtf(d_deg_dec[idx]);
        }
    }
    if (tid == 1023) d_rowptr[NN] = sh[1023];
}

__global__ void fill_kernel(const void* ei, const float* __restrict__ ea) {
    int e = blockIdx.x * blockDim.x + threadIdx.x;
    if (e >= EN) return;
    int s, d; float w;
    if (e < EE) { get_edge(ei, e, s, d); w = ea[e]; }
    else { s = d = e - EE; w = 1.f; }
    int pos = d_rowptr[d] + atomicAdd(&d_cnt[d], 1);
    d_col[pos] = s;
    d_nrm_enc[pos] = d_dis_enc[s] * w * d_dis_enc[d];
    d_nrm_dec[pos] = d_dis_dec[s] * d_dis_dec[d];
}

// ---------------- float -> half2 conversion ----------------
__global__ void f2h_kernel(const float* __restrict__ src, __half2* __restrict__ dst, int n2) {
    int i = blockIdx.x * blockDim.x + threadIdx.x;
    if (i < n2) {
        float2 v = ((const float2*)src)[i];
        dst[i] = __floats2half2_rn(v.x, v.y);
    }
}

// ---------------- CSR aggregation (fp32 src): dst[n,:] = sum_e nrm[e]*src[col[e],:] ----------------
template<int C, bool RELU>
__global__ void agg_kernel(const float* __restrict__ src, float* __restrict__ dst,
                           const float* __restrict__ nrm, const float* __restrict__ bias) {
    int n = blockIdx.x;
    int t = blockIdx.y;
    int f = threadIdx.x;
    const float* sb = src + (size_t)t * NN * C;
    int beg = d_rowptr[n], end = d_rowptr[n + 1];
    float acc = 0.f;
    for (int e = beg; e < end; ++e) {
        int s = __ldg(&d_col[e]);
        float w = __ldg(&nrm[e]);
        acc += w * __ldg(&sb[(size_t)s * C + f]);
    }
    if (bias) acc += bias[f];
    if (RELU) acc = fmaxf(acc, 0.f);
    dst[((size_t)t * NN + n) * C + f] = acc;
}

// ---------------- CSR aggregation (half2 src, fp32 accumulate/out) ----------------
template<int C2>
__global__ void agg_half_kernel(const __half2* __restrict__ src, float* __restrict__ dst,
                                const float* __restrict__ nrm) {
    int n = blockIdx.x;
    int t = blockIdx.y;
    int f2 = threadIdx.x;            // handles features 2*f2, 2*f2+1
    const __half2* sb = src + (size_t)t * NN * C2;
    int beg = d_rowptr[n], end = d_rowptr[n + 1];
    float ax = 0.f, ay = 0.f;
    for (int e = beg; e < end; ++e) {
        int s = __ldg(&d_col[e]);
        float w = __ldg(&nrm[e]);
        float2 v = __half22float2(__ldg(&sb[(size_t)s * C2 + f2]));
        ax += w * v.x;
        ay += w * v.y;
    }
    float* o = dst + ((size_t)t * NN + n) * (2 * C2) + 2 * f2;
    o[0] = ax;
    o[1] = ay;
}

// agg(half2 src) + bias + relu + mean-pool over nodes, never materializing Y2
__global__ void agg_pool_kernel(const __half2* __restrict__ src, const float* __restrict__ bias) {
    int t = blockIdx.y;
    int f2 = threadIdx.x;   // 128 threads, half2 features
    const __half2* sb = src + (size_t)t * NN * (HH / 2);
    int n0 = blockIdx.x * 16;
    int n1 = min(n0 + 16, NN);
    float bx = bias[2 * f2], by = bias[2 * f2 + 1];
    float px = 0.f, py = 0.f;
    for (int n = n0; n < n1; ++n) {
        int beg = d_rowptr[n], end = d_rowptr[n + 1];
        float ax = 0.f, ay = 0.f;
        for (int e = beg; e < end; ++e) {
            int s = __ldg(&d_col[e]);
            float w = __ldg(&d_nrm_enc[e]);
            float2 v = __half22float2(__ldg(&sb[(size_t)s * (HH / 2) + f2]));
            ax += w * v.x;
            ay += w * v.y;
        }
        px += fmaxf(ax + bx, 0.f);
        py += fmaxf(ay + by, 0.f);
    }
    atomicAdd(&d_gpool[t * HH + 2 * f2], px * (1.0f / NN));
    atomicAdd(&d_gpool[t * HH + 2 * f2 + 1], py * (1.0f / NN));
}

// ---------------- TF32 tensor-core GEMM: C[M,Nc] = A[M,K] @ B[K,Nc] (+bias)(+relu) ----------------
__device__ __forceinline__ unsigned f2tf32(float x) {
    unsigned r;
    asm("cvt.rna.tf32.f32 %0, %1;" : "=r"(r) : "f"(x));
    return r;
}

__device__ __forceinline__ void mma_tf32(float* d, const unsigned* a, const unsigned* b) {
    asm volatile(
        "mma.sync.aligned.m16n8k8.row.col.f32.tf32.tf32.f32 "
        "{%0,%1,%2,%3}, {%4,%5,%6,%7}, {%8,%9}, {%0,%1,%2,%3};\n"
        : "+f"(d[0]), "+f"(d[1]), "+f"(d[2]), "+f"(d[3])
        : "r"(a[0]), "r"(a[1]), "r"(a[2]), "r"(a[3]), "r"(b[0]), "r"(b[1]));
}

// Block 128x128, 512 threads (16 warps, 4x4 of 32x32 warp tiles), K-stage 16, double-buffered.
template<typename OutT, bool HASBIAS, bool RELU>
__global__ __launch_bounds__(512) void mma_gemm(
    const float* __restrict__ A, const float* __restrict__ B,
    const float* __restrict__ bias, OutT* __restrict__ C,
    int M, int K, int Ncols)
{
    __shared__ __align__(16) unsigned As[2][128][20];   // [m][k], stride 20: conflict-free frags
    __shared__ __align__(16) unsigned Bs[2][16][136];   // [k][n], stride 136: conflict-free frags
    int tid = threadIdx.x;
    int bm = blockIdx.x * 128, bn = blockIdx.y * 128;
    int w = tid >> 5, lane = tid & 31;
    int wm = (w >> 2) * 32, wn = (w & 3) * 32;
    int lr = lane >> 2, lc = lane & 3;

    float acc[2][4][4];
#pragma unroll
    for (int mi = 0; mi < 2; ++mi)
#pragma unroll
        for (int nj = 0; nj < 4; ++nj)
#pragma unroll
            for (int q = 0; q < 4; ++q) acc[mi][nj][q] = 0.f;

    int ar = tid >> 2, ac = (tid & 3) * 4;        // A tile: row 0..127, k-quad
    int bkr = tid >> 5, bn4 = (tid & 31) * 4;     // B tile: k 0..15, n-quad
    bool arow_ok = (bm + ar) < M;
    const float* Aptr = A + (size_t)(bm + ar) * K + ac;
    const float* Bptr = B + (size_t)bkr * Ncols + bn + bn4;

    // stage 0
    {
        float4 av = arow_ok ? *(const float4*)Aptr : make_float4(0.f, 0.f, 0.f, 0.f);
        uint4 at = make_uint4(f2tf32(av.x), f2tf32(av.y), f2tf32(av.z), f2tf32(av.w));
        *(uint4*)&As[0][ar][ac] = at;
        float4 bv = *(const float4*)Bptr;
        uint4 bt = make_uint4(f2tf32(bv.x), f2tf32(bv.y), f2tf32(bv.z), f2tf32(bv.w));
        *(uint4*)&Bs[0][bkr][bn4] = bt;
    }
    __syncthreads();

    int nstage = K >> 4;
    for (int s = 0; s < nstage; ++s) {
        int cur = s & 1;
        uint4 at, bt;
        bool have = (s + 1 < nstage);
        if (have) {
            int k0 = (s + 1) << 4;
            float4 av = arow_ok ? *(const float4*)(Aptr + k0) : make_float4(0.f, 0.f, 0.f, 0.f);
            at = make_uint4(f2tf32(av.x), f2tf32(av.y), f2tf32(av.z), f2tf32(av.w));
            float4 bv = *(const float4*)(Bptr + (size_t)k0 * Ncols);
            bt = make_uint4(f2tf32(bv.x), f2tf32(bv.y), f2tf32(bv.z), f2tf32(bv.w));
        }
        const unsigned (*Asc)[20] = As[cur];
        const unsigned (*Bsc)[136] = Bs[cur];
#pragma unroll
        for (int ks = 0; ks < 16; ks += 8) {
            unsigned af[2][4], bf[4][2];
#pragma unroll
            for (int mi = 0; mi < 2; ++mi) {
                int r0 = wm + mi * 16 + lr;
                af[mi][0] = Asc[r0][ks + lc];
                af[mi][1] = Asc[r0 + 8][ks + lc];
                af[mi][2] = Asc[r0][ks + lc + 4];
                af[mi][3] = Asc[r0 + 8][ks + lc + 4];
            }
#pragma unroll
            for (int nj = 0; nj < 4; ++nj) {
                int c0 = wn + nj * 8 + lr;
                bf[nj][0] = Bsc[ks + lc][c0];
                bf[nj][1] = Bsc[ks + lc + 4][c0];
            }
#pragma unroll
            for (int mi = 0; mi < 2; ++mi)
#pragma unroll
                for (int nj = 0; nj < 4; ++nj)
                    mma_tf32(acc[mi][nj], af[mi], bf[nj]);
        }
        if (have) {
            *(uint4*)&As[cur ^ 1][ar][ac] = at;
            *(uint4*)&Bs[cur ^ 1][bkr][bn4] = bt;
        }
        __syncthreads();
    }

    // epilogue
#pragma unroll
    for (int mi = 0; mi < 2; ++mi) {
#pragma unroll
        for (int nj = 0; nj < 4; ++nj) {
            int row = bm + wm + mi * 16 + lr;
            int col = bn + wn + nj * 8 + 2 * lc;
            float b0 = 0.f, b1 = 0.f;
            if (HASBIAS) { b0 = bias[col]; b1 = bias[col + 1]; }
#pragma unroll
            for (int h = 0; h < 2; ++h) {
                int r = row + h * 8;
                if (r < M) {
                    float v0 = acc[mi][nj][2 * h] + b0;
                    float v1 = acc[mi][nj][2 * h + 1] + b1;
                    if (RELU) { v0 = fmaxf(v0, 0.f); v1 = fmaxf(v1, 0.f); }
                    OutT* o = C + (size_t)r * Ncols + col;
                    if (sizeof(OutT) == 2) {
                        *(__half2*)o = __floats2half2_rn(v0, v1);
                    } else {
                        ((float*)o)[0] = v0;
                        ((float*)o)[1] = v1;
                    }
                }
            }
        }
    }
}

// ---------------- z_t = g_t @ Wfce + bfce ----------------
__global__ void proj_z_kernel(const float* __restrict__ Wfce, const float* __restrict__ bfce) {
    int t = blockIdx.x;
    int j = threadIdx.x;   // 64
    float a = bfce[j];
    for (int k = 0; k < HH; ++k)
        a += d_gpool[t * HH + k] * Wfce[k * LL + j];
    d_zs[t * LL + j] = a;
}

// ---------------- persistent 2-layer LSTM + head ----------------
__device__ __forceinline__ float sigm(float x) { return 1.f / (1.f + expf(-x)); }

__device__ __forceinline__ void grid_bar(int round) {
    __syncthreads();
    if (threadIdx.x == 0) {
        __threadfence();
        atomicAdd(&d_bar, 1u);
        unsigned tgt = (unsigned)(LSTM_BLOCKS * round);
        volatile unsigned int* vb = (volatile unsigned int*)&d_bar;
        while (*vb < tgt) { }
        __threadfence();
    }
    __syncthreads();
}

__global__ __launch_bounds__(256) void lstm_kernel(
    const float* __restrict__ Wih0, const float* __restrict__ Whh0,
    const float* __restrict__ bih0, const float* __restrict__ bhh0,
    const float* __restrict__ Wih1, const float* __restrict__ Whh1,
    const float* __restrict__ bih1, const float* __restrict__ bhh1,
    const float* __restrict__ Whead, const float* __restrict__ bhead)
{
    __shared__ float x_sh[LL];
    __shared__ float h1_sh[HL];
    __shared__ float h2_sh[HL];
    __shared__ float part[256];
    int tid = threadIdx.x;
    int b = blockIdx.x;
    int jj = tid & 127;
    int j = b * 128 + jj;
    int kh = tid >> 7;
    int kb = kh * 128;
    float c1 = 0.f, c2 = 0.f;
    h1_sh[tid] = 0.f;
    h2_sh[tid] = 0.f;
    __syncthreads();
    int round = 0;

    for (int t = 0; t < TT; ++t) {
        if (tid < LL) x_sh[tid] = d_zs[t * LL + tid];
        __syncthreads();

        // ---- layer 1 gates ----
        float p0 = 0.f, p1 = 0.f, p2 = 0.f, p3 = 0.f;
#pragma unroll 8
        for (int k = 0; k < 128; k += 4) {
            p0 += h1_sh[kb + k + 0] * Whh0[(size_t)(kb + k + 0) * 1024 + j];
            p1 += h1_sh[kb + k + 1] * Whh0[(size_t)(kb + k + 1) * 1024 + j];
            p2 += h1_sh[kb + k + 2] * Whh0[(size_t)(kb + k + 2) * 1024 + j];
            p3 += h1_sh[kb + k + 3] * Whh0[(size_t)(kb + k + 3) * 1024 + j];
        }
        if (kh == 0) {
#pragma unroll 8
            for (int k = 0; k < LL; k += 4) {
                p0 += x_sh[k + 0] * Wih0[(size_t)(k + 0) * 1024 + j];
                p1 += x_sh[k + 1] * Wih0[(size_t)(k + 1) * 1024 + j];
                p2 += x_sh[k + 2] * Wih0[(size_t)(k + 2) * 1024 + j];
                p3 += x_sh[k + 3] * Wih0[(size_t)(k + 3) * 1024 + j];
            }
        }
        part[tid] = p0 + p1 + p2 + p3;
        __syncthreads();
        int pb = round & 1;
        if (tid < 128)
            __stcg(&d_gates[pb][j], part[jj] + part[jj + 128] + bih0[j] + bhh0[j]);
        round++;
        grid_bar(round);
        {
            float gi = __ldcg(&d_gates[pb][tid]);
            float gf = __ldcg(&d_gates[pb][256 + tid]);
            float gg = __ldcg(&d_gates[pb][512 + tid]);
            float go = __ldcg(&d_gates[pb][768 + tid]);
            c1 = sigm(gf) * c1 + sigm(gi) * tanhf(gg);
            h1_sh[tid] = sigm(go) * tanhf(c1);
        }
        __syncthreads();

        // ---- layer 2 gates (x = h1) ----
        p0 = 0.f; p1 = 0.f; p2 = 0.f; p3 = 0.f;
#pragma unroll 4
        for (int k = 0; k < 128; k += 4) {
            p0 += h2_sh[kb + k + 0] * Whh1[(size_t)(kb + k + 0) * 1024 + j]
                + h1_sh[kb + k + 0] * Wih1[(size_t)(kb + k + 0) * 1024 + j];
            p1 += h2_sh[kb + k + 1] * Whh1[(size_t)(kb + k + 1) * 1024 + j]
                + h1_sh[kb + k + 1] * Wih1[(size_t)(kb + k + 1) * 1024 + j];
            p2 += h2_sh[kb + k + 2] * Whh1[(size_t)(kb + k + 2) * 1024 + j]
                + h1_sh[kb + k + 2] * Wih1[(size_t)(kb + k + 2) * 1024 + j];
            p3 += h2_sh[kb + k + 3] * Whh1[(size_t)(kb + k + 3) * 1024 + j]
                + h1_sh[kb + k + 3] * Wih1[(size_t)(kb + k + 3) * 1024 + j];
        }
        part[tid] = p0 + p1 + p2 + p3;
        __syncthreads();
        pb = round & 1;
        if (tid < 128)
            __stcg(&d_gates[pb][j], part[jj] + part[jj + 128] + bih1[j] + bhh1[j]);
        round++;
        grid_bar(round);
        {
            float gi = __ldcg(&d_gates[pb][tid]);
            float gf = __ldcg(&d_gates[pb][256 + tid]);
            float gg = __ldcg(&d_gates[pb][512 + tid]);
            float go = __ldcg(&d_gates[pb][768 + tid]);
            c2 = sigm(gf) * c2 + sigm(gi) * tanhf(gg);
            h2_sh[tid] = sigm(go) * tanhf(c2);
        }
        __syncthreads();
    }

    if (b == 0 && tid < LL) {
        float a = bhead[tid];
        for (int k = 0; k < HL; ++k)
            a += h2_sh[k] * Whead[k * LL + tid];
        d_zfin[tid] = a;
    }
}

// ---------------- decoder fc: relu(z @ Wfcd + bfcd) -> [N, L] ----------------
__global__ void fcd_kernel(const float* __restrict__ Wfcd, const float* __restrict__ bfcd,
                           float* __restrict__ out) {
    __shared__ float z[LL];
    if (threadIdx.x < LL) z[threadIdx.x] = d_zfin[threadIdx.x];
    __syncthreads();
    int p = blockIdx.x * blockDim.x + threadIdx.x;
    if (p >= NN * LL) return;
    float a = bfcd[p];
#pragma unroll 8
    for (int k = 0; k < LL; ++k)
        a += z[k] * Wfcd[(size_t)k * (NN * LL) + p];
    out[p] = fmaxf(a, 0.f);
}

// ---------------- launch ----------------
extern "C" void kernel_launch(void* const* d_in, const int* in_sizes, int n_in,
                              void* d_out, int out_size) {
    const float* xs        = (const float*)d_in[0];
    const float* edge_attr = (const float*)d_in[1];
    const float* We0  = (const float*)d_in[2];
    const float* be0  = (const float*)d_in[3];
    const float* We1  = (const float*)d_in[4];
    const float* be1  = (const float*)d_in[5];
    const float* Wfce = (const float*)d_in[6];
    const float* bfce = (const float*)d_in[7];
    const float* Wih0 = (const float*)d_in[8];
    const float* Whh0 = (const float*)d_in[9];
    const float* bih0 = (const float*)d_in[10];
    const float* bhh0 = (const float*)d_in[11];
    const float* Wih1 = (const float*)d_in[12];
    const float* Whh1 = (const float*)d_in[13];
    const float* bih1 = (const float*)d_in[14];
    const float* bhh1 = (const float*)d_in[15];
    const float* Whead = (const float*)d_in[16];
    const float* bhead = (const float*)d_in[17];
    const float* Wfcd = (const float*)d_in[18];
    const float* bfcd = (const float*)d_in[19];
    const float* Wd0  = (const float*)d_in[20];
    const float* bd0  = (const float*)d_in[21];
    const float* Wd1  = (const float*)d_in[22];
    const float* bd1  = (const float*)d_in[23];
    const float* Wd2  = (const float*)d_in[24];
    const float* bd2  = (const float*)d_in[25];
    const void*  eidx = d_in[26];

    float *buf0, *buf1, *nrm_enc, *nrm_dec;
    __half* hbuf;
    cudaGetSymbolAddress((void**)&buf0, d_buf0);
    cudaGetSymbolAddress((void**)&buf1, d_buf1);
    cudaGetSymbolAddress((void**)&hbuf, d_hbuf);
    cudaGetSymbolAddress((void**)&nrm_enc, d_nrm_enc);
    cudaGetSymbolAddress((void**)&nrm_dec, d_nrm_dec);

    // ---- preprocessing: dtype detect, zero, degree/count, scan, CSR fill ----
    detect_kernel<<<1, 1>>>(eidx);
    zero_kernel<<<(NN + 255) / 256, 256>>>();
    count_kernel<<<(EN + 255) / 256, 256>>>(eidx, edge_attr);
    scan_kernel<<<1, 1024>>>();
    fill_kernel<<<(EN + 255) / 256, 256>>>(eidx, edge_attr);

    // ---- encoder (batched over T) ----
    // xs -> half2, aggregate first (half gathers), then TF32 GEMM+bias+relu
    {
        int n2 = TT * NN * FF / 2;
        f2h_kernel<<<(n2 + 255) / 256, 256>>>(xs, (__half2*)hbuf, n2);
    }
    agg_half_kernel<FF / 2><<<dim3(NN, TT), FF / 2>>>((const __half2*)hbuf, buf0, nrm_enc);
    mma_gemm<float, true, true><<<dim3(TT * NN / 128, HH / 128), 512>>>(
        buf0, We0, be0, buf1, TT * NN, FF, HH);
    // layer1: TF32 GEMM (half out), then aggregate+bias+relu fused with mean-pool
    mma_gemm<__half, false, false><<<dim3(TT * NN / 128, HH / 128), 512>>>(
        buf1, We1, nullptr, hbuf, TT * NN, HH, HH);
    agg_pool_kernel<<<dim3((NN + 15) / 16, TT), HH / 2>>>((const __half2*)hbuf, be1);
    proj_z_kernel<<<TT, LL>>>(Wfce, bfce);

    // ---- LSTM (persistent, custom grid barrier) + head ----
    lstm_kernel<<<LSTM_BLOCKS, 256>>>(Wih0, Whh0, bih0, bhh0,
                                      Wih1, Whh1, bih1, bhh1, Whead, bhead);

    // ---- decoder ----
    fcd_kernel<<<(NN * LL) / 256, 256>>>(Wfcd, bfcd, buf1);                 // [N,64]
    agg_kernel<LL, false><<<dim3(NN, 1), LL>>>(buf1, buf0, nrm_dec, nullptr);
    mma_gemm<float, true, true><<<dim3((NN + 127) / 128, HH / 128), 512>>>(
        buf0, Wd0, bd0, buf1, NN, LL, HH);
    mma_gemm<float, false, false><<<dim3((NN + 127) / 128, HH / 128), 512>>>(
        buf1, Wd1, nullptr, buf0, NN, HH, HH);
    agg_kernel<HH, true><<<dim3(NN, 1), HH>>>(buf0, buf1, nrm_dec, bd1);
    mma_gemm<float, false, false><<<dim3((NN + 127) / 128, FF / 128), 512>>>(
        buf1, Wd2, nullptr, buf0, NN, HH, FF);
    agg_kernel<FF, false><<<dim3(NN, 1), FF>>>(buf0, (float*)d_out, nrm_dec, bd2);
}

// round 3
// speedup vs baseline: 1.6321x; 1.2428x over previous
#include <cuda_runtime.h>
#include <cuda_fp16.h>
#include <cuda_bf16.h>
#include <math.h>

#define TT 16
#define NN 10000
#define EE 320000
#define EN (EE + NN)
#define FF 128
#define HH 256
#define LL 64
#define HL 256
#define LSTM_BLOCKS 8

// ---------------- device scratch (no dynamic allocation allowed) ----------------
__device__ int   d_rowptr[NN + 1];
__device__ int   d_cnt[NN];
__device__ int   d_col[EN];
__device__ float d_nrm_enc[EN];
__device__ float d_nrm_dec[EN];
__device__ float d_deg_enc[NN];
__device__ float d_deg_dec[NN];
__device__ float d_dis_enc[NN];
__device__ float d_dis_dec[NN];
__device__ __align__(16) float d_buf0[(size_t)TT * NN * HH];   // 160000 x 256 fp32 (also used as half)
__device__ __align__(16) float d_buf1[(size_t)TT * NN * HH];
__device__ __align__(16) __half d_hbuf[(size_t)TT * NN * HH];  // half features
__device__ __align__(16) __half d_We0h[FF * HH];
__device__ __align__(16) __half d_We1h[HH * HH];
__device__ float d_gpool[TT * HH];
__device__ float d_zs[TT * LL];
__device__ float d_gates[2][4 * HL];
__device__ float d_zfin[LL];
__device__ unsigned int d_bar;
__device__ int   d_idx64;

// ---------------- edge index dtype detection (int64 vs int32) ----------------
__global__ void detect_kernel(const void* ei) {
    const unsigned int* w = (const unsigned int*)ei;
    int is64 = 1;
    for (int i = 0; i < 64; ++i) {
        if (w[2 * i + 1] != 0u) { is64 = 0; break; }
    }
    d_idx64 = is64;
}

__device__ __forceinline__ void get_edge(const void* ei, int e, int& s, int& d) {
    if (d_idx64) {
        const long long* p = (const long long*)ei;
        s = (int)p[e];
        d = (int)p[EE + e];
    } else {
        const int* p = (const int*)ei;
        s = p[e];
        d = p[EE + e];
    }
}

// ---------------- preprocessing ----------------
__global__ void zero_kernel() {
    int i = blockIdx.x * blockDim.x + threadIdx.x;
    if (i < NN) { d_deg_enc[i] = 0.f; d_deg_dec[i] = 0.f; d_cnt[i] = 0; }
    if (i < TT * HH) d_gpool[i] = 0.f;
    if (i == 0) d_bar = 0u;
}

__global__ void count_kernel(const void* ei, const float* __restrict__ ea) {
    int e = blockIdx.x * blockDim.x + threadIdx.x;
    if (e >= EN) return;
    int s, d; float w;
    if (e < EE) { get_edge(ei, e, s, d); w = ea[e]; }
    else { s = d = e - EE; w = 1.f; }
    atomicAdd(&d_deg_enc[d], w);
    atomicAdd(&d_deg_dec[d], 1.f);
    atomicAdd(&d_cnt[d], 1);
}

__global__ void scan_kernel() {
    __shared__ int sh[1024];
    int tid = threadIdx.x;
    int loc[10];
    int sum = 0;
#pragma unroll
    for (int i = 0; i < 10; ++i) {
        int idx = tid * 10 + i;
        int c = (idx < NN) ? d_cnt[idx] : 0;
        loc[i] = sum;
        sum += c;
    }
    sh[tid] = sum;
    __syncthreads();
    for (int off = 1; off < 1024; off <<= 1) {
        int v = (tid >= off) ? sh[tid - off] : 0;
        __syncthreads();
        sh[tid] += v;
        __syncthreads();
    }
    int excl = sh[tid] - sum;
#pragma unroll
    for (int i = 0; i < 10; ++i) {
        int idx = tid * 10 + i;
        if (idx < NN) {
            d_rowptr[idx] = excl + loc[i];
            d_cnt[idx] = 0;
            d_dis_enc[idx] = rsqrtf(d_deg_enc[idx]);   // deg >= 1 (self-loops)
            d_dis_dec[idx] = rsqrtf(d_deg_dec[idx]);
        }
    }
    if (tid == 1023) d_rowptr[NN] = sh[1023];
}

__global__ void fill_kernel(const void* ei, const float* __restrict__ ea) {
    int e = blockIdx.x * blockDim.x + threadIdx.x;
    if (e >= EN) return;
    int s, d; float w;
    if (e < EE) { get_edge(ei, e, s, d); w = ea[e]; }
    else { s = d = e - EE; w = 1.f; }
    int pos = d_rowptr[d] + atomicAdd(&d_cnt[d], 1);
    d_col[pos] = s;
    d_nrm_enc[pos] = d_dis_enc[s] * w * d_dis_enc[d];
    d_nrm_dec[pos] = d_dis_dec[s] * d_dis_dec[d];
}

// ---------------- float -> half2 conversion ----------------
__global__ void f2h_kernel(const float* __restrict__ src, __half2* __restrict__ dst, int n2) {
    int i = blockIdx.x * blockDim.x + threadIdx.x;
    if (i < n2) {
        float2 v = ((const float2*)src)[i];
        dst[i] = __floats2half2_rn(v.x, v.y);
    }
}

// ---------------- encoder layer0 agg: all-T batched, half2 gather, half2 out ----------------
// grid NN blocks, 256 threads = 4 tslices x 64 f2-lanes; inner loop gathers 4 T-planes per index.
__global__ __launch_bounds__(256) void agg_enc0_kernel(const __half2* __restrict__ src,
                                                       __half2* __restrict__ dst) {
    int n = blockIdx.x;
    int tid = threadIdx.x;
    int f2 = tid & 63;
    int ts = tid >> 6;           // 0..3, t = ts + 4q
    int beg = d_rowptr[n], end = d_rowptr[n + 1];
    float ax[4] = {0.f, 0.f, 0.f, 0.f}, ay[4] = {0.f, 0.f, 0.f, 0.f};
    for (int e = beg; e < end; ++e) {
        int s = __ldg(&d_col[e]);
        float w = __ldg(&d_nrm_enc[e]);
        const __half2* sp = src + (size_t)s * 64 + f2;
#pragma unroll
        for (int q = 0; q < 4; ++q) {
            float2 v = __half22float2(__ldg(sp + (size_t)(ts + 4 * q) * NN * 64));
            ax[q] += w * v.x;
            ay[q] += w * v.y;
        }
    }
#pragma unroll
    for (int q = 0; q < 4; ++q) {
        dst[((size_t)(ts + 4 * q) * NN + n) * 64 + f2] = __floats2half2_rn(ax[q], ay[q]);
    }
}

// ---------------- agg + bias + relu + mean-pool, all-T batched ----------------
// grid 625, 256 threads = 2 tslices x 128 f2; 16 nodes per block; 8 T-planes gathered per index.
__global__ __launch_bounds__(256) void agg_pool_kernel(const __half2* __restrict__ src,
                                                       const float* __restrict__ bias) {
    int tid = threadIdx.x;
    int f2 = tid & 127;
    int ts = tid >> 7;           // 0..1, t = ts + 2q
    int n0 = blockIdx.x * 16;
    float bx = bias[2 * f2], by = bias[2 * f2 + 1];
    float px[8], py[8];
#pragma unroll
    for (int q = 0; q < 8; ++q) { px[q] = 0.f; py[q] = 0.f; }
    for (int n = n0; n < n0 + 16; ++n) {
        int beg = d_rowptr[n], end = d_rowptr[n + 1];
        float ax[8], ay[8];
#pragma unroll
        for (int q = 0; q < 8; ++q) { ax[q] = 0.f; ay[q] = 0.f; }
        for (int e = beg; e < end; ++e) {
            int s = __ldg(&d_col[e]);
            float w = __ldg(&d_nrm_enc[e]);
            const __half2* sp = src + (size_t)s * 128 + f2;
#pragma unroll
            for (int q = 0; q < 8; ++q) {
                float2 v = __half22float2(__ldg(sp + (size_t)(ts + 2 * q) * NN * 128));
                ax[q] += w * v.x;
                ay[q] += w * v.y;
            }
        }
#pragma unroll
        for (int q = 0; q < 8; ++q) {
            px[q] += fmaxf(ax[q] + bx, 0.f);
            py[q] += fmaxf(ay[q] + by, 0.f);
        }
    }
#pragma unroll
    for (int q = 0; q < 8; ++q) {
        atomicAdd(&d_gpool[(ts + 2 * q) * HH + 2 * f2], px[q] * (1.0f / NN));
        atomicAdd(&d_gpool[(ts + 2 * q) * HH + 2 * f2 + 1], py[q] * (1.0f / NN));
    }
}

// ---------------- fp32 CSR aggregation (decoder), 4-way unrolled ----------------
template<int C, bool RELU>
__global__ void agg_kernel(const float* __restrict__ src, float* __restrict__ dst,
                           const float* __restrict__ nrm, const float* __restrict__ bias) {
    int n = blockIdx.x;
    int f = threadIdx.x;
    int beg = d_rowptr[n], end = d_rowptr[n + 1];
    float a0 = 0.f, a1 = 0.f, a2 = 0.f, a3 = 0.f;
    int e = beg;
    for (; e + 4 <= end; e += 4) {
        int s0 = __ldg(&d_col[e]);
        int s1 = __ldg(&d_col[e + 1]);
        int s2 = __ldg(&d_col[e + 2]);
        int s3 = __ldg(&d_col[e + 3]);
        float w0 = __ldg(&nrm[e]);
        float w1 = __ldg(&nrm[e + 1]);
        float w2 = __ldg(&nrm[e + 2]);
        float w3 = __ldg(&nrm[e + 3]);
        a0 += w0 * __ldg(&src[(size_t)s0 * C + f]);
        a1 += w1 * __ldg(&src[(size_t)s1 * C + f]);
        a2 += w2 * __ldg(&src[(size_t)s2 * C + f]);
        a3 += w3 * __ldg(&src[(size_t)s3 * C + f]);
    }
    for (; e < end; ++e) {
        int s = __ldg(&d_col[e]);
        a0 += __ldg(&nrm[e]) * __ldg(&src[(size_t)s * C + f]);
    }
    float acc = (a0 + a1) + (a2 + a3);
    if (bias) acc += bias[f];
    if (RELU) acc = fmaxf(acc, 0.f);
    dst[(size_t)n * C + f] = acc;
}

// ================= FP16 HMMA GEMM (encoder): C = A[M,K] @ B[K,N] (+bias)(+relu), half out ==========
__device__ __forceinline__ void ldsm4(unsigned& r0, unsigned& r1, unsigned& r2, unsigned& r3,
                                      const void* p) {
    unsigned a = (unsigned)__cvta_generic_to_shared(p);
    asm volatile("ldmatrix.sync.aligned.m8n8.x4.shared.b16 {%0,%1,%2,%3}, [%4];"
                 : "=r"(r0), "=r"(r1), "=r"(r2), "=r"(r3) : "r"(a));
}
__device__ __forceinline__ void ldsm4t(unsigned& r0, unsigned& r1, unsigned& r2, unsigned& r3,
                                       const void* p) {
    unsigned a = (unsigned)__cvta_generic_to_shared(p);
    asm volatile("ldmatrix.sync.aligned.m8n8.x4.trans.shared.b16 {%0,%1,%2,%3}, [%4];"
                 : "=r"(r0), "=r"(r1), "=r"(r2), "=r"(r3) : "r"(a));
}
__device__ __forceinline__ void mma16816(float* d, const unsigned* a, const unsigned* b) {
    asm volatile(
        "mma.sync.aligned.m16n8k16.row.col.f32.f16.f16.f32 "
        "{%0,%1,%2,%3},{%4,%5,%6,%7},{%8,%9},{%0,%1,%2,%3};\n"
        : "+f"(d[0]), "+f"(d[1]), "+f"(d[2]), "+f"(d[3])
        : "r"(a[0]), "r"(a[1]), "r"(a[2]), "r"(a[3]), "r"(b[0]), "r"(b[1]));
}

// Block tile 128x128, K-stage 32, 256 threads = 8 warps (2m x 4n), warp tile 64x32. M%128==0.
template<bool HASBIAS, bool RELU>
__global__ __launch_bounds__(256) void hgemm(
    const __half* __restrict__ A, const __half* __restrict__ B,
    const float* __restrict__ bias, __half* __restrict__ C,
    int M, int K, int Ncols)
{
    __shared__ __align__(16) __half As[2][128][40];    // pad 40: conflict-free ldmatrix
    __shared__ __align__(16) __half Bs[2][32][136];    // pad 136: conflict-free ldmatrix.trans
    int tid = threadIdx.x;
    int bm = blockIdx.x * 128, bn = blockIdx.y * 128;
    int w = tid >> 5, lane = tid & 31;
    int wm = (w >> 2) * 64, wn = (w & 3) * 32;
    int lr16 = lane & 15, lh = lane >> 4;

    float acc[4][4][4];
#pragma unroll
    for (int mi = 0; mi < 4; ++mi)
#pragma unroll
        for (int nj = 0; nj < 4; ++nj)
#pragma unroll
            for (int q = 0; q < 4; ++q) acc[mi][nj][q] = 0.f;

    int ar = tid >> 2, ac = (tid & 3) * 8;      // A: rows ar, ar+64; 16B chunks
    int br = tid >> 4, bc = (tid & 15) * 8;     // B: rows br, br+16
    const __half* Ap = A + (size_t)(bm + ar) * K + ac;
    const __half* Bp = B + (size_t)br * Ncols + bn + bc;

    // stage 0
    {
        uint4 a0 = *(const uint4*)Ap;
        uint4 a1 = *(const uint4*)(Ap + (size_t)64 * K);
        uint4 b0 = *(const uint4*)Bp;
        uint4 b1 = *(const uint4*)(Bp + (size_t)16 * Ncols);
        *(uint4*)&As[0][ar][ac] = a0;
        *(uint4*)&As[0][ar + 64][ac] = a1;
        *(uint4*)&Bs[0][br][bc] = b0;
        *(uint4*)&Bs[0][br + 16][bc] = b1;
    }
    __syncthreads();

    int nstage = K >> 5;
    for (int s = 0; s < nstage; ++s) {
        int cur = s & 1;
        uint4 a0, a1, b0, b1;
        bool have = (s + 1 < nstage);
        if (have) {
            int k0 = (s + 1) << 5;
            a0 = *(const uint4*)(Ap + k0);
            a1 = *(const uint4*)(Ap + (size_t)64 * K + k0);
            b0 = *(const uint4*)(Bp + (size_t)k0 * Ncols);
            b1 = *(const uint4*)(Bp + (size_t)(k0 + 16) * Ncols);
        }
#pragma unroll
        for (int k16 = 0; k16 < 2; ++k16) {
            unsigned af[4][4], bf[4][2];
#pragma unroll
            for (int mi = 0; mi < 4; ++mi)
                ldsm4(af[mi][0], af[mi][1], af[mi][2], af[mi][3],
                      &As[cur][wm + mi * 16 + lr16][k16 * 16 + lh * 8]);
#pragma unroll
            for (int p = 0; p < 2; ++p) {
                unsigned r0, r1, r2, r3;
                ldsm4t(r0, r1, r2, r3, &Bs[cur][k16 * 16 + lr16][wn + p * 16 + lh * 8]);
                bf[2 * p][0] = r0; bf[2 * p][1] = r1;
                bf[2 * p + 1][0] = r2; bf[2 * p + 1][1] = r3;
            }
#pragma unroll
            for (int mi = 0; mi < 4; ++mi)
#pragma unroll
                for (int nj = 0; nj < 4; ++nj)
                    mma16816(acc[mi][nj], af[mi], bf[nj]);
        }
        if (have) {
            *(uint4*)&As[cur ^ 1][ar][ac] = a0;
            *(uint4*)&As[cur ^ 1][ar + 64][ac] = a1;
            *(uint4*)&Bs[cur ^ 1][br][bc] = b0;
            *(uint4*)&Bs[cur ^ 1][br + 16][bc] = b1;
        }
        __syncthreads();
    }

    // epilogue
    int lr = lane >> 2, lc = lane & 3;
#pragma unroll
    for (int mi = 0; mi < 4; ++mi) {
#pragma unroll
        for (int nj = 0; nj < 4; ++nj) {
            int row = bm + wm + mi * 16 + lr;
            int col = bn + wn + nj * 8 + 2 * lc;
            float b0 = 0.f, b1 = 0.f;
            if (HASBIAS) { b0 = bias[col]; b1 = bias[col + 1]; }
            float v0 = acc[mi][nj][0] + b0, v1 = acc[mi][nj][1] + b1;
            float v2 = acc[mi][nj][2] + b0, v3 = acc[mi][nj][3] + b1;
            if (RELU) {
                v0 = fmaxf(v0, 0.f); v1 = fmaxf(v1, 0.f);
                v2 = fmaxf(v2, 0.f); v3 = fmaxf(v3, 0.f);
            }
            *(__half2*)(C + (size_t)row * Ncols + col) = __floats2half2_rn(v0, v1);
            *(__half2*)(C + (size_t)(row + 8) * Ncols + col) = __floats2half2_rn(v2, v3);
        }
    }
}

// ---------------- TF32 tensor-core GEMM (decoder) ----------------
__device__ __forceinline__ unsigned f2tf32(float x) {
    unsigned r;
    asm("cvt.rna.tf32.f32 %0, %1;" : "=r"(r) : "f"(x));
    return r;
}

__device__ __forceinline__ void mma_tf32(float* d, const unsigned* a, const unsigned* b) {
    asm volatile(
        "mma.sync.aligned.m16n8k8.row.col.f32.tf32.tf32.f32 "
        "{%0,%1,%2,%3}, {%4,%5,%6,%7}, {%8,%9}, {%0,%1,%2,%3};\n"
        : "+f"(d[0]), "+f"(d[1]), "+f"(d[2]), "+f"(d[3])
        : "r"(a[0]), "r"(a[1]), "r"(a[2]), "r"(a[3]), "r"(b[0]), "r"(b[1]));
}

template<typename OutT, bool HASBIAS, bool RELU>
__global__ __launch_bounds__(512) void mma_gemm(
    const float* __restrict__ A, const float* __restrict__ B,
    const float* __restrict__ bias, OutT* __restrict__ C,
    int M, int K, int Ncols)
{
    __shared__ __align__(16) unsigned As[2][128][20];
    __shared__ __align__(16) unsigned Bs[2][16][136];
    int tid = threadIdx.x;
    int bm = blockIdx.x * 128, bn = blockIdx.y * 128;
    int w = tid >> 5, lane = tid & 31;
    int wm = (w >> 2) * 32, wn = (w & 3) * 32;
    int lr = lane >> 2, lc = lane & 3;

    float acc[2][4][4];
#pragma unroll
    for (int mi = 0; mi < 2; ++mi)
#pragma unroll
        for (int nj = 0; nj < 4; ++nj)
#pragma unroll
            for (int q = 0; q < 4; ++q) acc[mi][nj][q] = 0.f;

    int ar = tid >> 2, ac = (tid & 3) * 4;
    int bkr = tid >> 5, bn4 = (tid & 31) * 4;
    bool arow_ok = (bm + ar) < M;
    const float* Aptr = A + (size_t)(bm + ar) * K + ac;
    const float* Bptr = B + (size_t)bkr * Ncols + bn + bn4;

    {
        float4 av = arow_ok ? *(const float4*)Aptr : make_float4(0.f, 0.f, 0.f, 0.f);
        uint4 at = make_uint4(f2tf32(av.x), f2tf32(av.y), f2tf32(av.z), f2tf32(av.w));
        *(uint4*)&As[0][ar][ac] = at;
        float4 bv = *(const float4*)Bptr;
        uint4 bt = make_uint4(f2tf32(bv.x), f2tf32(bv.y), f2tf32(bv.z), f2tf32(bv.w));
        *(uint4*)&Bs[0][bkr][bn4] = bt;
    }
    __syncthreads();

    int nstage = K >> 4;
    for (int s = 0; s < nstage; ++s) {
        int cur = s & 1;
        uint4 at, bt;
        bool have = (s + 1 < nstage);
        if (have) {
            int k0 = (s + 1) << 4;
            float4 av = arow_ok ? *(const float4*)(Aptr + k0) : make_float4(0.f, 0.f, 0.f, 0.f);
            at = make_uint4(f2tf32(av.x), f2tf32(av.y), f2tf32(av.z), f2tf32(av.w));
            float4 bv = *(const float4*)(Bptr + (size_t)k0 * Ncols);
            bt = make_uint4(f2tf32(bv.x), f2tf32(bv.y), f2tf32(bv.z), f2tf32(bv.w));
        }
        const unsigned (*Asc)[20] = As[cur];
        const unsigned (*Bsc)[136] = Bs[cur];
#pragma unroll
        for (int ks = 0; ks < 16; ks += 8) {
            unsigned af[2][4], bf[4][2];
#pragma unroll
            for (int mi = 0; mi < 2; ++mi) {
                int r0 = wm + mi * 16 + lr;
                af[mi][0] = Asc[r0][ks + lc];
                af[mi][1] = Asc[r0 + 8][ks + lc];
                af[mi][2] = Asc[r0][ks + lc + 4];
                af[mi][3] = Asc[r0 + 8][ks + lc + 4];
            }
#pragma unroll
            for (int nj = 0; nj < 4; ++nj) {
                int c0 = wn + nj * 8 + lr;
                bf[nj][0] = Bsc[ks + lc][c0];
                bf[nj][1] = Bsc[ks + lc + 4][c0];
            }
#pragma unroll
            for (int mi = 0; mi < 2; ++mi)
#pragma unroll
                for (int nj = 0; nj < 4; ++nj)
                    mma_tf32(acc[mi][nj], af[mi], bf[nj]);
        }
        if (have) {
            *(uint4*)&As[cur ^ 1][ar][ac] = at;
            *(uint4*)&Bs[cur ^ 1][bkr][bn4] = bt;
        }
        __syncthreads();
    }

#pragma unroll
    for (int mi = 0; mi < 2; ++mi) {
#pragma unroll
        for (int nj = 0; nj < 4; ++nj) {
            int row = bm + wm + mi * 16 + lr;
            int col = bn + wn + nj * 8 + 2 * lc;
            float b0 = 0.f, b1 = 0.f;
            if (HASBIAS) { b0 = bias[col]; b1 = bias[col + 1]; }
#pragma unroll
            for (int h = 0; h < 2; ++h) {
                int r = row + h * 8;
                if (r < M) {
                    float v0 = acc[mi][nj][2 * h] + b0;
                    float v1 = acc[mi][nj][2 * h + 1] + b1;
                    if (RELU) { v0 = fmaxf(v0, 0.f); v1 = fmaxf(v1, 0.f); }
                    OutT* o = C + (size_t)r * Ncols + col;
                    if (sizeof(OutT) == 2) {
                        *(__half2*)o = __floats2half2_rn(v0, v1);
                    } else {
                        ((float*)o)[0] = v0;
                        ((float*)o)[1] = v1;
                    }
                }
            }
        }
    }
}

// ---------------- z_t = g_t @ Wfce + bfce ----------------
__global__ void proj_z_kernel(const float* __restrict__ Wfce, const float* __restrict__ bfce) {
    int t = blockIdx.x;
    int j = threadIdx.x;   // 64
    float a = bfce[j];
    for (int k = 0; k < HH; ++k)
        a += d_gpool[t * HH + k] * Wfce[k * LL + j];
    d_zs[t * LL + j] = a;
}

// ---------------- persistent 2-layer LSTM + head ----------------
__device__ __forceinline__ float sigm(float x) { return 1.f / (1.f + expf(-x)); }

__device__ __forceinline__ void grid_bar(int round) {
    __syncthreads();
    if (threadIdx.x == 0) {
        __threadfence();
        atomicAdd(&d_bar, 1u);
        unsigned tgt = (unsigned)(LSTM_BLOCKS * round);
        volatile unsigned int* vb = (volatile unsigned int*)&d_bar;
        while (*vb < tgt) { }
        __threadfence();
    }
    __syncthreads();
}

__global__ __launch_bounds__(256) void lstm_kernel(
    const float* __restrict__ Wih0, const float* __restrict__ Whh0,
    const float* __restrict__ bih0, const float* __restrict__ bhh0,
    const float* __restrict__ Wih1, const float* __restrict__ Whh1,
    const float* __restrict__ bih1, const float* __restrict__ bhh1,
    const float* __restrict__ Whead, const float* __restrict__ bhead)
{
    __shared__ float x_sh[LL];
    __shared__ float h1_sh[HL];
    __shared__ float h2_sh[HL];
    __shared__ float part[256];
    int tid = threadIdx.x;
    int b = blockIdx.x;
    int jj = tid & 127;
    int j = b * 128 + jj;
    int kh = tid >> 7;
    int kb = kh * 128;
    float c1 = 0.f, c2 = 0.f;
    h1_sh[tid] = 0.f;
    h2_sh[tid] = 0.f;
    __syncthreads();
    int round = 0;

    for (int t = 0; t < TT; ++t) {
        if (tid < LL) x_sh[tid] = d_zs[t * LL + tid];
        __syncthreads();

        float p0 = 0.f, p1 = 0.f, p2 = 0.f, p3 = 0.f;
#pragma unroll 8
        for (int k = 0; k < 128; k += 4) {
            p0 += h1_sh[kb + k + 0] * Whh0[(size_t)(kb + k + 0) * 1024 + j];
            p1 += h1_sh[kb + k + 1] * Whh0[(size_t)(kb + k + 1) * 1024 + j];
            p2 += h1_sh[kb + k + 2] * Whh0[(size_t)(kb + k + 2) * 1024 + j];
            p3 += h1_sh[kb + k + 3] * Whh0[(size_t)(kb + k + 3) * 1024 + j];
        }
        if (kh == 0) {
#pragma unroll 8
            for (int k = 0; k < LL; k += 4) {
                p0 += x_sh[k + 0] * Wih0[(size_t)(k + 0) * 1024 + j];
                p1 += x_sh[k + 1] * Wih0[(size_t)(k + 1) * 1024 + j];
                p2 += x_sh[k + 2] * Wih0[(size_t)(k + 2) * 1024 + j];
                p3 += x_sh[k + 3] * Wih0[(size_t)(k + 3) * 1024 + j];
            }
        }
        part[tid] = p0 + p1 + p2 + p3;
        __syncthreads();
        int pb = round & 1;
        if (tid < 128)
            __stcg(&d_gates[pb][j], part[jj] + part[jj + 128] + bih0[j] + bhh0[j]);
        round++;
        grid_bar(round);
        {
            float gi = __ldcg(&d_gates[pb][tid]);
            float gf = __ldcg(&d_gates[pb][256 + tid]);
            float gg = __ldcg(&d_gates[pb][512 + tid]);
            float go = __ldcg(&d_gates[pb][768 + tid]);
            c1 = sigm(gf) * c1 + sigm(gi) * tanhf(gg);
            h1_sh[tid] = sigm(go) * tanhf(c1);
        }
        __syncthreads();

        p0 = 0.f; p1 = 0.f; p2 = 0.f; p3 = 0.f;
#pragma unroll 4
        for (int k = 0; k < 128; k += 4) {
            p0 += h2_sh[kb + k + 0] * Whh1[(size_t)(kb + k + 0) * 1024 + j]
                + h1_sh[kb + k + 0] * Wih1[(size_t)(kb + k + 0) * 1024 + j];
            p1 += h2_sh[kb + k + 1] * Whh1[(size_t)(kb + k + 1) * 1024 + j]
                + h1_sh[kb + k + 1] * Wih1[(size_t)(kb + k + 1) * 1024 + j];
            p2 += h2_sh[kb + k + 2] * Whh1[(size_t)(kb + k + 2) * 1024 + j]
                + h1_sh[kb + k + 2] * Wih1[(size_t)(kb + k + 2) * 1024 + j];
            p3 += h2_sh[kb + k + 3] * Whh1[(size_t)(kb + k + 3) * 1024 + j]
                + h1_sh[kb + k + 3] * Wih1[(size_t)(kb + k + 3) * 1024 + j];
        }
        part[tid] = p0 + p1 + p2 + p3;
        __syncthreads();
        pb = round & 1;
        if (tid < 128)
            __stcg(&d_gates[pb][j], part[jj] + part[jj + 128] + bih1[j] + bhh1[j]);
        round++;
        grid_bar(round);
        {
            float gi = __ldcg(&d_gates[pb][tid]);
            float gf = __ldcg(&d_gates[pb][256 + tid]);
            float gg = __ldcg(&d_gates[pb][512 + tid]);
            float go = __ldcg(&d_gates[pb][768 + tid]);
            c2 = sigm(gf) * c2 + sigm(gi) * tanhf(gg);
            h2_sh[tid] = sigm(go) * tanhf(c2);
        }
        __syncthreads();
    }

    if (b == 0 && tid < LL) {
        float a = bhead[tid];
        for (int k = 0; k < HL; ++k)
            a += h2_sh[k] * Whead[k * LL + tid];
        d_zfin[tid] = a;
    }
}

// ---------------- decoder fc: relu(z @ Wfcd + bfcd) -> [N, L] ----------------
__global__ void fcd_kernel(const float* __restrict__ Wfcd, const float* __restrict__ bfcd,
                           float* __restrict__ out) {
    __shared__ float z[LL];
    if (threadIdx.x < LL) z[threadIdx.x] = d_zfin[threadIdx.x];
    __syncthreads();
    int p = blockIdx.x * blockDim.x + threadIdx.x;
    if (p >= NN * LL) return;
    float a = bfcd[p];
#pragma unroll 8
    for (int k = 0; k < LL; ++k)
        a += z[k] * Wfcd[(size_t)k * (NN * LL) + p];
    out[p] = fmaxf(a, 0.f);
}

// ---------------- launch ----------------
extern "C" void kernel_launch(void* const* d_in, const int* in_sizes, int n_in,
                              void* d_out, int out_size) {
    const float* xs        = (const float*)d_in[0];
    const float* edge_attr = (const float*)d_in[1];
    const float* We0  = (const float*)d_in[2];
    const float* be0  = (const float*)d_in[3];
    const float* We1  = (const float*)d_in[4];
    const float* be1  = (const float*)d_in[5];
    const float* Wfce = (const float*)d_in[6];
    const float* bfce = (const float*)d_in[7];
    const float* Wih0 = (const float*)d_in[8];
    const float* Whh0 = (const float*)d_in[9];
    const float* bih0 = (const float*)d_in[10];
    const float* bhh0 = (const float*)d_in[11];
    const float* Wih1 = (const float*)d_in[12];
    const float* Whh1 = (const float*)d_in[13];
    const float* bih1 = (const float*)d_in[14];
    const float* bhh1 = (const float*)d_in[15];
    const float* Whead = (const float*)d_in[16];
    const float* bhead = (const float*)d_in[17];
    const float* Wfcd = (const float*)d_in[18];
    const float* bfcd = (const float*)d_in[19];
    const float* Wd0  = (const float*)d_in[20];
    const float* bd0  = (const float*)d_in[21];
    const float* Wd1  = (const float*)d_in[22];
    const float* bd1  = (const float*)d_in[23];
    const float* Wd2  = (const float*)d_in[24];
    const float* bd2  = (const float*)d_in[25];
    const void*  eidx = d_in[26];

    float *buf0, *buf1, *nrm_enc, *nrm_dec;
    __half *hbuf, *we0h, *we1h;
    cudaGetSymbolAddress((void**)&buf0, d_buf0);
    cudaGetSymbolAddress((void**)&buf1, d_buf1);
    cudaGetSymbolAddress((void**)&hbuf, d_hbuf);
    cudaGetSymbolAddress((void**)&we0h, d_We0h);
    cudaGetSymbolAddress((void**)&we1h, d_We1h);
    cudaGetSymbolAddress((void**)&nrm_enc, d_nrm_enc);
    cudaGetSymbolAddress((void**)&nrm_dec, d_nrm_dec);

    // ---- preprocessing ----
    detect_kernel<<<1, 1>>>(eidx);
    zero_kernel<<<(NN + 255) / 256, 256>>>();
    count_kernel<<<(EN + 255) / 256, 256>>>(eidx, edge_attr);
    scan_kernel<<<1, 1024>>>();
    fill_kernel<<<(EN + 255) / 256, 256>>>(eidx, edge_attr);

    // ---- encoder ----
    // xs -> half (into hbuf), weights -> half
    {
        int n2 = TT * NN * FF / 2;
        f2h_kernel<<<(n2 + 255) / 256, 256>>>(xs, (__half2*)hbuf, n2);
        f2h_kernel<<<(FF * HH / 2 + 255) / 256, 256>>>(We0, (__half2*)we0h, FF * HH / 2);
        f2h_kernel<<<(HH * HH / 2 + 255) / 256, 256>>>(We1, (__half2*)we1h, HH * HH / 2);
    }
    // layer0: aggregate (all T batched, half), then HMMA GEMM + bias + relu (half out)
    agg_enc0_kernel<<<NN, 256>>>((const __half2*)hbuf, (__half2*)buf0);
    hgemm<true, true><<<dim3(TT * NN / 128, HH / 128), 256>>>(
        (const __half*)buf0, we0h, be0, (__half*)buf1, TT * NN, FF, HH);
    // layer1: HMMA GEMM (no bias), then aggregate+bias+relu fused with mean-pool
    hgemm<false, false><<<dim3(TT * NN / 128, HH / 128), 256>>>(
        (const __half*)buf1, we1h, nullptr, hbuf, TT * NN, HH, HH);
    agg_pool_kernel<<<625, 256>>>((const __half2*)hbuf, be1);
    proj_z_kernel<<<TT, LL>>>(Wfce, bfce);

    // ---- LSTM (persistent, custom grid barrier) + head ----
    lstm_kernel<<<LSTM_BLOCKS, 256>>>(Wih0, Whh0, bih0, bhh0,
                                      Wih1, Whh1, bih1, bhh1, Whead, bhead);

    // ---- decoder (fp32 / TF32) ----
    fcd_kernel<<<(NN * LL) / 256, 256>>>(Wfcd, bfcd, buf1);                 // [N,64]
    agg_kernel<LL, false><<<NN, LL>>>(buf1, buf0, nrm_dec, nullptr);
    mma_gemm<float, true, true><<<dim3((NN + 127) / 128, HH / 128), 512>>>(
        buf0, Wd0, bd0, buf1, NN, LL, HH);
    mma_gemm<float, false, false><<<dim3((NN + 127) / 128, HH / 128), 512>>>(
        buf1, Wd1, nullptr, buf0, NN, HH, HH);
    agg_kernel<HH, true><<<NN, HH>>>(buf0, buf1, nrm_dec, bd1);
    mma_gemm<float, false, false><<<dim3((NN + 127) / 128, FF / 128), 512>>>(
        buf1, Wd2, nullptr, buf0, NN, HH, FF);
    agg_kernel<FF, false><<<NN, FF>>>(buf0, (float*)d_out, nrm_dec, bd2);
}

// round 4
// speedup vs baseline: 1.7491x; 1.0717x over previous
#include <cuda_runtime.h>
#include <cuda_fp16.h>
#include <cuda_bf16.h>
#include <math.h>

#define TT 16
#define NN 10000
#define EE 320000
#define EN (EE + NN)
#define FF 128
#define HH 256
#define LL 64
#define HL 256
#define LSTM_BLOCKS 8

// ---------------- device scratch (no dynamic allocation allowed) ----------------
__device__ int   d_rowptr[NN + 1];
__device__ int   d_cnt[NN];
__device__ int   d_col[EN];
__device__ float d_nrm_enc[EN];
__device__ float d_nrm_dec[EN];
__device__ float d_deg_enc[NN];
__device__ float d_deg_dec[NN];
__device__ float d_dis_enc[NN];
__device__ float d_dis_dec[NN];
__device__ __align__(16) float d_buf0[(size_t)TT * NN * HH];   // also reused as half
__device__ __align__(16) float d_buf1[(size_t)TT * NN * HH];
__device__ __align__(16) __half d_hbuf[(size_t)TT * NN * HH];
__device__ __align__(16) __half d_We0h[FF * HH];
__device__ __align__(16) __half d_We1h[HH * HH];
__device__ __align__(16) __half d_Wd0h[LL * HH];
__device__ __align__(16) __half d_Wd1h[HH * HH];
__device__ __align__(16) __half d_Wd2h[HH * FF];
__device__ float d_gpool[TT * HH];
__device__ float d_zs[TT * LL];
__device__ float d_gates[2][4 * HL];
__device__ float d_zfin[LL];
__device__ int   d_idx64;

// ---------------- edge index dtype detection (int64 vs int32) ----------------
__global__ void detect_kernel(const void* ei) {
    const unsigned int* w = (const unsigned int*)ei;
    int is64 = 1;
    for (int i = 0; i < 64; ++i) {
        if (w[2 * i + 1] != 0u) { is64 = 0; break; }
    }
    d_idx64 = is64;
}

__device__ __forceinline__ void get_edge(const void* ei, int e, int& s, int& d) {
    if (d_idx64) {
        const long long* p = (const long long*)ei;
        s = (int)p[e];
        d = (int)p[EE + e];
    } else {
        const int* p = (const int*)ei;
        s = p[e];
        d = p[EE + e];
    }
}

// ---------------- preprocessing ----------------
__global__ void zero_kernel() {
    int i = blockIdx.x * blockDim.x + threadIdx.x;
    if (i < NN) { d_deg_enc[i] = 0.f; d_deg_dec[i] = 0.f; d_cnt[i] = 0; }
    if (i < TT * HH) d_gpool[i] = 0.f;
}

__global__ void count_kernel(const void* ei, const float* __restrict__ ea) {
    int e = blockIdx.x * blockDim.x + threadIdx.x;
    if (e >= EN) return;
    int s, d; float w;
    if (e < EE) { get_edge(ei, e, s, d); w = ea[e]; }
    else { s = d = e - EE; w = 1.f; }
    atomicAdd(&d_deg_enc[d], w);
    atomicAdd(&d_deg_dec[d], 1.f);
    atomicAdd(&d_cnt[d], 1);
}

__global__ void scan_kernel() {
    __shared__ int cnts[NN];       // 40 KB
    __shared__ int sh[1024];
    int tid = threadIdx.x;
    for (int i = tid; i < NN; i += 1024) cnts[i] = d_cnt[i];   // coalesced
    __syncthreads();
    int loc[10];
    int sum = 0;
#pragma unroll
    for (int i = 0; i < 10; ++i) {
        int idx = tid * 10 + i;
        int c = (idx < NN) ? cnts[idx] : 0;
        loc[i] = sum;
        sum += c;
    }
    sh[tid] = sum;
    __syncthreads();
    for (int off = 1; off < 1024; off <<= 1) {
        int v = (tid >= off) ? sh[tid - off] : 0;
        __syncthreads();
        sh[tid] += v;
        __syncthreads();
    }
    int excl = sh[tid] - sum;
#pragma unroll
    for (int i = 0; i < 10; ++i) {
        int idx = tid * 10 + i;
        if (idx < NN) d_rowptr[idx] = excl + loc[i];
    }
    if (tid == 1023) d_rowptr[NN] = sh[1023];
    // coalesced pass: reset cnt, compute rsqrt degs
    for (int i = tid; i < NN; i += 1024) {
        d_cnt[i] = 0;
        d_dis_enc[i] = rsqrtf(d_deg_enc[i]);   // deg >= 1 (self-loops)
        d_dis_dec[i] = rsqrtf(d_deg_dec[i]);
    }
}

__global__ void fill_kernel(const void* ei, const float* __restrict__ ea) {
    int e = blockIdx.x * blockDim.x + threadIdx.x;
    if (e >= EN) return;
    int s, d; float w;
    if (e < EE) { get_edge(ei, e, s, d); w = ea[e]; }
    else { s = d = e - EE; w = 1.f; }
    int pos = d_rowptr[d] + atomicAdd(&d_cnt[d], 1);
    d_col[pos] = s;
    d_nrm_enc[pos] = d_dis_enc[s] * w * d_dis_enc[d];
    d_nrm_dec[pos] = d_dis_dec[s] * d_dis_dec[d];
}

// ---------------- float -> half2 conversion ----------------
__global__ void f2h_kernel(const float* __restrict__ src, __half2* __restrict__ dst, int n2) {
    int i = blockIdx.x * blockDim.x + threadIdx.x;
    if (i < n2) {
        float2 v = ((const float2*)src)[i];
        dst[i] = __floats2half2_rn(v.x, v.y);
    }
}

// ---------------- encoder layer0 agg: all-T batched, half2 gather, half2 out ----------------
// 256 threads = 4 tslices x 64 f2-lanes; edge loop unrolled x2 (MLP 8).
__global__ __launch_bounds__(256) void agg_enc0_kernel(const __half2* __restrict__ src,
                                                       __half2* __restrict__ dst) {
    int n = blockIdx.x;
    int tid = threadIdx.x;
    int f2 = tid & 63;
    int ts = tid >> 6;           // 0..3, t = ts + 4q
    int beg = d_rowptr[n], end = d_rowptr[n + 1];
    float ax[4] = {0.f, 0.f, 0.f, 0.f}, ay[4] = {0.f, 0.f, 0.f, 0.f};
    int e = beg;
    for (; e + 2 <= end; e += 2) {
        int s0 = __ldg(&d_col[e]);
        int s1 = __ldg(&d_col[e + 1]);
        float w0 = __ldg(&d_nrm_enc[e]);
        float w1 = __ldg(&d_nrm_enc[e + 1]);
        const __half2* p0 = src + (size_t)s0 * 64 + f2;
        const __half2* p1 = src + (size_t)s1 * 64 + f2;
#pragma unroll
        for (int q = 0; q < 4; ++q) {
            size_t off = (size_t)(ts + 4 * q) * NN * 64;
            float2 v0 = __half22float2(__ldg(p0 + off));
            float2 v1 = __half22float2(__ldg(p1 + off));
            ax[q] += w0 * v0.x + w1 * v1.x;
            ay[q] += w0 * v0.y + w1 * v1.y;
        }
    }
    if (e < end) {
        int s = __ldg(&d_col[e]);
        float w = __ldg(&d_nrm_enc[e]);
        const __half2* sp = src + (size_t)s * 64 + f2;
#pragma unroll
        for (int q = 0; q < 4; ++q) {
            float2 v = __half22float2(__ldg(sp + (size_t)(ts + 4 * q) * NN * 64));
            ax[q] += w * v.x;
            ay[q] += w * v.y;
        }
    }
#pragma unroll
    for (int q = 0; q < 4; ++q)
        dst[((size_t)(ts + 4 * q) * NN + n) * 64 + f2] = __floats2half2_rn(ax[q], ay[q]);
}

// ---------------- agg + bias + relu + mean-pool, all-T batched, 8 nodes/block ----------------
__global__ __launch_bounds__(256) void agg_pool_kernel(const __half2* __restrict__ src,
                                                       const float* __restrict__ bias) {
    int tid = threadIdx.x;
    int f2 = tid & 127;
    int ts = tid >> 7;           // 0..1, t = ts + 2q
    int n0 = blockIdx.x * 8;
    float bx = bias[2 * f2], by = bias[2 * f2 + 1];
    float px[8], py[8];
#pragma unroll
    for (int q = 0; q < 8; ++q) { px[q] = 0.f; py[q] = 0.f; }
    for (int n = n0; n < n0 + 8; ++n) {
        int beg = d_rowptr[n], end = d_rowptr[n + 1];
        float ax[8], ay[8];
#pragma unroll
        for (int q = 0; q < 8; ++q) { ax[q] = 0.f; ay[q] = 0.f; }
        for (int e = beg; e < end; ++e) {
            int s = __ldg(&d_col[e]);
            float w = __ldg(&d_nrm_enc[e]);
            const __half2* sp = src + (size_t)s * 128 + f2;
#pragma unroll
            for (int q = 0; q < 8; ++q) {
                float2 v = __half22float2(__ldg(sp + (size_t)(ts + 2 * q) * NN * 128));
                ax[q] += w * v.x;
                ay[q] += w * v.y;
            }
        }
#pragma unroll
        for (int q = 0; q < 8; ++q) {
            px[q] += fmaxf(ax[q] + bx, 0.f);
            py[q] += fmaxf(ay[q] + by, 0.f);
        }
    }
#pragma unroll
    for (int q = 0; q < 8; ++q) {
        atomicAdd(&d_gpool[(ts + 2 * q) * HH + 2 * f2], px[q] * (1.0f / NN));
        atomicAdd(&d_gpool[(ts + 2 * q) * HH + 2 * f2 + 1], py[q] * (1.0f / NN));
    }
}

// ---------------- decoder CSR aggregation, half2 src, fp32 accum, half2 or float2 out ----------------
template<int C2, bool RELU, bool OUTF>
__global__ void agg_dec_kernel(const __half2* __restrict__ src, void* __restrict__ dstv,
                               const float* __restrict__ bias) {
    int n = blockIdx.x;
    int f2 = threadIdx.x;   // C2 threads
    int beg = d_rowptr[n], end = d_rowptr[n + 1];
    float ax0 = 0.f, ay0 = 0.f, ax1 = 0.f, ay1 = 0.f;
    float ax2 = 0.f, ay2 = 0.f, ax3 = 0.f, ay3 = 0.f;
    int e = beg;
    for (; e + 4 <= end; e += 4) {
        int s0 = __ldg(&d_col[e]);
        int s1 = __ldg(&d_col[e + 1]);
        int s2 = __ldg(&d_col[e + 2]);
        int s3 = __ldg(&d_col[e + 3]);
        float w0 = __ldg(&d_nrm_dec[e]);
        float w1 = __ldg(&d_nrm_dec[e + 1]);
        float w2 = __ldg(&d_nrm_dec[e + 2]);
        float w3 = __ldg(&d_nrm_dec[e + 3]);
        float2 v0 = __half22float2(__ldg(&src[(size_t)s0 * C2 + f2]));
        float2 v1 = __half22float2(__ldg(&src[(size_t)s1 * C2 + f2]));
        float2 v2 = __half22float2(__ldg(&src[(size_t)s2 * C2 + f2]));
        float2 v3 = __half22float2(__ldg(&src[(size_t)s3 * C2 + f2]));
        ax0 += w0 * v0.x; ay0 += w0 * v0.y;
        ax1 += w1 * v1.x; ay1 += w1 * v1.y;
        ax2 += w2 * v2.x; ay2 += w2 * v2.y;
        ax3 += w3 * v3.x; ay3 += w3 * v3.y;
    }
    for (; e < end; ++e) {
        int s = __ldg(&d_col[e]);
        float w = __ldg(&d_nrm_dec[e]);
        float2 v = __half22float2(__ldg(&src[(size_t)s * C2 + f2]));
        ax0 += w * v.x; ay0 += w * v.y;
    }
    float vx = (ax0 + ax1) + (ax2 + ax3);
    float vy = (ay0 + ay1) + (ay2 + ay3);
    if (bias) { vx += bias[2 * f2]; vy += bias[2 * f2 + 1]; }
    if (RELU) { vx = fmaxf(vx, 0.f); vy = fmaxf(vy, 0.f); }
    if (OUTF) {
        ((float2*)dstv)[(size_t)n * C2 + f2] = make_float2(vx, vy);
    } else {
        ((__half2*)dstv)[(size_t)n * C2 + f2] = __floats2half2_rn(vx, vy);
    }
}

// ================= FP16 HMMA GEMM: C = A[M,K] @ B[K,N] (+bias)(+relu), half out ==========
__device__ __forceinline__ void ldsm4(unsigned& r0, unsigned& r1, unsigned& r2, unsigned& r3,
                                      const void* p) {
    unsigned a = (unsigned)__cvta_generic_to_shared(p);
    asm volatile("ldmatrix.sync.aligned.m8n8.x4.shared.b16 {%0,%1,%2,%3}, [%4];"
                 : "=r"(r0), "=r"(r1), "=r"(r2), "=r"(r3) : "r"(a));
}
__device__ __forceinline__ void ldsm4t(unsigned& r0, unsigned& r1, unsigned& r2, unsigned& r3,
                                       const void* p) {
    unsigned a = (unsigned)__cvta_generic_to_shared(p);
    asm volatile("ldmatrix.sync.aligned.m8n8.x4.trans.shared.b16 {%0,%1,%2,%3}, [%4];"
                 : "=r"(r0), "=r"(r1), "=r"(r2), "=r"(r3) : "r"(a));
}
__device__ __forceinline__ void mma16816(float* d, const unsigned* a, const unsigned* b) {
    asm volatile(
        "mma.sync.aligned.m16n8k16.row.col.f32.f16.f16.f32 "
        "{%0,%1,%2,%3},{%4,%5,%6,%7},{%8,%9},{%0,%1,%2,%3};\n"
        : "+f"(d[0]), "+f"(d[1]), "+f"(d[2]), "+f"(d[3])
        : "r"(a[0]), "r"(a[1]), "r"(a[2]), "r"(a[3]), "r"(b[0]), "r"(b[1]));
}

// Block tile 128x128, K-stage 32, 256 threads = 8 warps (2m x 4n), warp tile 64x32. M%128==0.
template<bool HASBIAS, bool RELU>
__global__ __launch_bounds__(256) void hgemm(
    const __half* __restrict__ A, const __half* __restrict__ B,
    const float* __restrict__ bias, __half* __restrict__ C,
    int M, int K, int Ncols)
{
    __shared__ __align__(16) __half As[2][128][40];
    __shared__ __align__(16) __half Bs[2][32][136];
    int tid = threadIdx.x;
    int bm = blockIdx.x * 128, bn = blockIdx.y * 128;
    int w = tid >> 5, lane = tid & 31;
    int wm = (w >> 2) * 64, wn = (w & 3) * 32;
    int lr16 = lane & 15, lh = lane >> 4;

    float acc[4][4][4];
#pragma unroll
    for (int mi = 0; mi < 4; ++mi)
#pragma unroll
        for (int nj = 0; nj < 4; ++nj)
#pragma unroll
            for (int q = 0; q < 4; ++q) acc[mi][nj][q] = 0.f;

    int ar = tid >> 2, ac = (tid & 3) * 8;
    int br = tid >> 4, bc = (tid & 15) * 8;
    const __half* Ap = A + (size_t)(bm + ar) * K + ac;
    const __half* Bp = B + (size_t)br * Ncols + bn + bc;

    {
        uint4 a0 = *(const uint4*)Ap;
        uint4 a1 = *(const uint4*)(Ap + (size_t)64 * K);
        uint4 b0 = *(const uint4*)Bp;
        uint4 b1 = *(const uint4*)(Bp + (size_t)16 * Ncols);
        *(uint4*)&As[0][ar][ac] = a0;
        *(uint4*)&As[0][ar + 64][ac] = a1;
        *(uint4*)&Bs[0][br][bc] = b0;
        *(uint4*)&Bs[0][br + 16][bc] = b1;
    }
    __syncthreads();

    int nstage = K >> 5;
    for (int s = 0; s < nstage; ++s) {
        int cur = s & 1;
        uint4 a0, a1, b0, b1;
        bool have = (s + 1 < nstage);
        if (have) {
            int k0 = (s + 1) << 5;
            a0 = *(const uint4*)(Ap + k0);
            a1 = *(const uint4*)(Ap + (size_t)64 * K + k0);
            b0 = *(const uint4*)(Bp + (size_t)k0 * Ncols);
            b1 = *(const uint4*)(Bp + (size_t)(k0 + 16) * Ncols);
        }
#pragma unroll
        for (int k16 = 0; k16 < 2; ++k16) {
            unsigned af[4][4], bf[4][2];
#pragma unroll
            for (int mi = 0; mi < 4; ++mi)
                ldsm4(af[mi][0], af[mi][1], af[mi][2], af[mi][3],
                      &As[cur][wm + mi * 16 + lr16][k16 * 16 + lh * 8]);
#pragma unroll
            for (int p = 0; p < 2; ++p) {
                unsigned r0, r1, r2, r3;
                ldsm4t(r0, r1, r2, r3, &Bs[cur][k16 * 16 + lr16][wn + p * 16 + lh * 8]);
                bf[2 * p][0] = r0; bf[2 * p][1] = r1;
                bf[2 * p + 1][0] = r2; bf[2 * p + 1][1] = r3;
            }
#pragma unroll
            for (int mi = 0; mi < 4; ++mi)
#pragma unroll
                for (int nj = 0; nj < 4; ++nj)
                    mma16816(acc[mi][nj], af[mi], bf[nj]);
        }
        if (have) {
            *(uint4*)&As[cur ^ 1][ar][ac] = a0;
            *(uint4*)&As[cur ^ 1][ar + 64][ac] = a1;
            *(uint4*)&Bs[cur ^ 1][br][bc] = b0;
            *(uint4*)&Bs[cur ^ 1][br + 16][bc] = b1;
        }
        __syncthreads();
    }

    int lr = lane >> 2, lc = lane & 3;
#pragma unroll
    for (int mi = 0; mi < 4; ++mi) {
#pragma unroll
        for (int nj = 0; nj < 4; ++nj) {
            int row = bm + wm + mi * 16 + lr;
            int col = bn + wn + nj * 8 + 2 * lc;
            float b0 = 0.f, b1 = 0.f;
            if (HASBIAS) { b0 = bias[col]; b1 = bias[col + 1]; }
            float v0 = acc[mi][nj][0] + b0, v1 = acc[mi][nj][1] + b1;
            float v2 = acc[mi][nj][2] + b0, v3 = acc[mi][nj][3] + b1;
            if (RELU) {
                v0 = fmaxf(v0, 0.f); v1 = fmaxf(v1, 0.f);
                v2 = fmaxf(v2, 0.f); v3 = fmaxf(v3, 0.f);
            }
            *(__half2*)(C + (size_t)row * Ncols + col) = __floats2half2_rn(v0, v1);
            *(__half2*)(C + (size_t)(row + 8) * Ncols + col) = __floats2half2_rn(v2, v3);
        }
    }
}

// ---------------- z_t = g_t @ Wfce + bfce ----------------
__global__ void proj_z_kernel(const float* __restrict__ Wfce, const float* __restrict__ bfce) {
    int t = blockIdx.x;
    int j = threadIdx.x;   // 64
    float a = bfce[j];
    for (int k = 0; k < HH; ++k)
        a += d_gpool[t * HH + k] * Wfce[k * LL + j];
    d_zs[t * LL + j] = a;
}

// ---------------- persistent 2-layer LSTM + head (cluster of 8 CTAs) ----------------
__device__ __forceinline__ float sigm(float x) { return 1.f / (1.f + expf(-x)); }

__device__ __forceinline__ void cluster_bar() {
    asm volatile("barrier.cluster.arrive.aligned;" ::: "memory");
    asm volatile("barrier.cluster.wait.aligned;" ::: "memory");
}

__global__ __launch_bounds__(256) __cluster_dims__(LSTM_BLOCKS, 1, 1) void lstm_kernel(
    const float* __restrict__ Wih0, const float* __restrict__ Whh0,
    const float* __restrict__ bih0, const float* __restrict__ bhh0,
    const float* __restrict__ Wih1, const float* __restrict__ Whh1,
    const float* __restrict__ bih1, const float* __restrict__ bhh1,
    const float* __restrict__ Whead, const float* __restrict__ bhead)
{
    __shared__ float x_sh[LL];
    __shared__ float h1_sh[HL];
    __shared__ float h2_sh[HL];
    __shared__ float part[256];
    int tid = threadIdx.x;
    int b = blockIdx.x;
    int jj = tid & 127;
    int j = b * 128 + jj;
    int kh = tid >> 7;
    int kb = kh * 128;
    float c1 = 0.f, c2 = 0.f;
    h1_sh[tid] = 0.f;
    h2_sh[tid] = 0.f;
    __syncthreads();
    int round = 0;

    for (int t = 0; t < TT; ++t) {
        if (tid < LL) x_sh[tid] = d_zs[t * LL + tid];
        __syncthreads();

        // ---- layer 1 gates ----
        float p0 = 0.f, p1 = 0.f, p2 = 0.f, p3 = 0.f;
#pragma unroll 8
        for (int k = 0; k < 128; k += 4) {
            p0 += h1_sh[kb + k + 0] * Whh0[(size_t)(kb + k + 0) * 1024 + j];
            p1 += h1_sh[kb + k + 1] * Whh0[(size_t)(kb + k + 1) * 1024 + j];
            p2 += h1_sh[kb + k + 2] * Whh0[(size_t)(kb + k + 2) * 1024 + j];
            p3 += h1_sh[kb + k + 3] * Whh0[(size_t)(kb + k + 3) * 1024 + j];
        }
        if (kh == 0) {
#pragma unroll 8
            for (int k = 0; k < LL; k += 4) {
                p0 += x_sh[k + 0] * Wih0[(size_t)(k + 0) * 1024 + j];
                p1 += x_sh[k + 1] * Wih0[(size_t)(k + 1) * 1024 + j];
                p2 += x_sh[k + 2] * Wih0[(size_t)(k + 2) * 1024 + j];
                p3 += x_sh[k + 3] * Wih0[(size_t)(k + 3) * 1024 + j];
            }
        }
        part[tid] = p0 + p1 + p2 + p3;
        __syncthreads();
        int pb = round & 1;
        if (tid < 128)
            __stcg(&d_gates[pb][j], part[jj] + part[jj + 128] + bih0[j] + bhh0[j]);
        round++;
        __threadfence();
        cluster_bar();
        {
            float gi = __ldcg(&d_gates[pb][tid]);
            float gf = __ldcg(&d_gates[pb][256 + tid]);
            float gg = __ldcg(&d_gates[pb][512 + tid]);
            float go = __ldcg(&d_gates[pb][768 + tid]);
            c1 = sigm(gf) * c1 + sigm(gi) * tanhf(gg);
            h1_sh[tid] = sigm(go) * tanhf(c1);
        }
        __syncthreads();

        // ---- layer 2 gates (x = h1) ----
        p0 = 0.f; p1 = 0.f; p2 = 0.f; p3 = 0.f;
#pragma unroll 4
        for (int k = 0; k < 128; k += 4) {
            p0 += h2_sh[kb + k + 0] * Whh1[(size_t)(kb + k + 0) * 1024 + j]
                + h1_sh[kb + k + 0] * Wih1[(size_t)(kb + k + 0) * 1024 + j];
            p1 += h2_sh[kb + k + 1] * Whh1[(size_t)(kb + k + 1) * 1024 + j]
                + h1_sh[kb + k + 1] * Wih1[(size_t)(kb + k + 1) * 1024 + j];
            p2 += h2_sh[kb + k + 2] * Whh1[(size_t)(kb + k + 2) * 1024 + j]
                + h1_sh[kb + k + 2] * Wih1[(size_t)(kb + k + 2) * 1024 + j];
            p3 += h2_sh[kb + k + 3] * Whh1[(size_t)(kb + k + 3) * 1024 + j]
                + h1_sh[kb + k + 3] * Wih1[(size_t)(kb + k + 3) * 1024 + j];
        }
        part[tid] = p0 + p1 + p2 + p3;
        __syncthreads();
        pb = round & 1;
        if (tid < 128)
            __stcg(&d_gates[pb][j], part[jj] + part[jj + 128] + bih1[j] + bhh1[j]);
        round++;
        __threadfence();
        cluster_bar();
        {
            float gi = __ldcg(&d_gates[pb][tid]);
            float gf = __ldcg(&d_gates[pb][256 + tid]);
            float gg = __ldcg(&d_gates[pb][512 + tid]);
            float go = __ldcg(&d_gates[pb][768 + tid]);
            c2 = sigm(gf) * c2 + sigm(gi) * tanhf(gg);
            h2_sh[tid] = sigm(go) * tanhf(c2);
        }
        __syncthreads();
    }

    if (b == 0 && tid < LL) {
        float a = bhead[tid];
        for (int k = 0; k < HL; ++k)
            a += h2_sh[k] * Whead[k * LL + tid];
        d_zfin[tid] = a;
    }
}

// ---------------- decoder fc: relu(z @ Wfcd + bfcd) -> half [N, L] ----------------
__global__ void fcd_kernel(const float* __restrict__ Wfcd, const float* __restrict__ bfcd,
                           __half2* __restrict__ out) {
    __shared__ float z[LL];
    if (threadIdx.x < LL) z[threadIdx.x] = d_zfin[threadIdx.x];
    __syncthreads();
    int q = blockIdx.x * blockDim.x + threadIdx.x;   // over NN*32 half2
    if (q >= NN * LL / 2) return;
    float2 bb = ((const float2*)bfcd)[q];
    float ax = bb.x, ay = bb.y;
#pragma unroll 8
    for (int k = 0; k < LL; ++k) {
        float2 w = ((const float2*)(Wfcd + (size_t)k * (NN * LL)))[q];
        ax += z[k] * w.x;
        ay += z[k] * w.y;
    }
    out[q] = __floats2half2_rn(fmaxf(ax, 0.f), fmaxf(ay, 0.f));
}

// ---------------- launch ----------------
extern "C" void kernel_launch(void* const* d_in, const int* in_sizes, int n_in,
                              void* d_out, int out_size) {
    const float* xs        = (const float*)d_in[0];
    const float* edge_attr = (const float*)d_in[1];
    const float* We0  = (const float*)d_in[2];
    const float* be0  = (const float*)d_in[3];
    const float* We1  = (const float*)d_in[4];
    const float* be1  = (const float*)d_in[5];
    const float* Wfce = (const float*)d_in[6];
    const float* bfce = (const float*)d_in[7];
    const float* Wih0 = (const float*)d_in[8];
    const float* Whh0 = (const float*)d_in[9];
    const float* bih0 = (const float*)d_in[10];
    const float* bhh0 = (const float*)d_in[11];
    const float* Wih1 = (const float*)d_in[12];
    const float* Whh1 = (const float*)d_in[13];
    const float* bih1 = (const float*)d_in[14];
    const float* bhh1 = (const float*)d_in[15];
    const float* Whead = (const float*)d_in[16];
    const float* bhead = (const float*)d_in[17];
    const float* Wfcd = (const float*)d_in[18];
    const float* bfcd = (const float*)d_in[19];
    const float* Wd0  = (const float*)d_in[20];
    const float* bd0  = (const float*)d_in[21];
    const float* Wd1  = (const float*)d_in[22];
    const float* bd1  = (const float*)d_in[23];
    const float* Wd2  = (const float*)d_in[24];
    const float* bd2  = (const float*)d_in[25];
    const void*  eidx = d_in[26];

    float *buf0, *buf1;
    __half *hbuf, *we0h, *we1h, *wd0h, *wd1h, *wd2h;
    cudaGetSymbolAddress((void**)&buf0, d_buf0);
    cudaGetSymbolAddress((void**)&buf1, d_buf1);
    cudaGetSymbolAddress((void**)&hbuf, d_hbuf);
    cudaGetSymbolAddress((void**)&we0h, d_We0h);
    cudaGetSymbolAddress((void**)&we1h, d_We1h);
    cudaGetSymbolAddress((void**)&wd0h, d_Wd0h);
    cudaGetSymbolAddress((void**)&wd1h, d_Wd1h);
    cudaGetSymbolAddress((void**)&wd2h, d_Wd2h);

    const int MPAD = 10112;   // 79 * 128 >= NN, for hgemm M-tiling

    // ---- preprocessing ----
    detect_kernel<<<1, 1>>>(eidx);
    zero_kernel<<<(NN + 255) / 256, 256>>>();
    count_kernel<<<(EN + 255) / 256, 256>>>(eidx, edge_attr);
    scan_kernel<<<1, 1024>>>();
    fill_kernel<<<(EN + 255) / 256, 256>>>(eidx, edge_attr);

    // ---- weight conversions (independent of graph work) ----
    f2h_kernel<<<(FF * HH / 2 + 255) / 256, 256>>>(We0, (__half2*)we0h, FF * HH / 2);
    f2h_kernel<<<(HH * HH / 2 + 255) / 256, 256>>>(We1, (__half2*)we1h, HH * HH / 2);
    f2h_kernel<<<(LL * HH / 2 + 255) / 256, 256>>>(Wd0, (__half2*)wd0h, LL * HH / 2);
    f2h_kernel<<<(HH * HH / 2 + 255) / 256, 256>>>(Wd1, (__half2*)wd1h, HH * HH / 2);
    f2h_kernel<<<(HH * FF / 2 + 255) / 256, 256>>>(Wd2, (__half2*)wd2h, HH * FF / 2);

    // ---- encoder ----
    {
        int n2 = TT * NN * FF / 2;
        f2h_kernel<<<(n2 + 255) / 256, 256>>>(xs, (__half2*)hbuf, n2);
    }
    agg_enc0_kernel<<<NN, 256>>>((const __half2*)hbuf, (__half2*)buf0);
    hgemm<true, true><<<dim3(TT * NN / 128, HH / 128), 256>>>(
        (const __half*)buf0, we0h, be0, (__half*)buf1, TT * NN, FF, HH);
    hgemm<false, false><<<dim3(TT * NN / 128, HH / 128), 256>>>(
        (const __half*)buf1, we1h, nullptr, hbuf, TT * NN, HH, HH);
    agg_pool_kernel<<<1250, 256>>>((const __half2*)hbuf, be1);
    proj_z_kernel<<<TT, LL>>>(Wfce, bfce);

    // ---- LSTM (persistent, cluster barrier) + head ----
    lstm_kernel<<<LSTM_BLOCKS, 256>>>(Wih0, Whh0, bih0, bhh0,
                                      Wih1, Whh1, bih1, bhh1, Whead, bhead);

    // ---- decoder (fp16 HMMA + half gathers, fp32 accumulation) ----
    fcd_kernel<<<(NN * LL / 2 + 255) / 256, 256>>>(Wfcd, bfcd, (__half2*)hbuf);   // [N,64] half
    agg_dec_kernel<LL / 2, false, false><<<NN, LL / 2>>>(
        (const __half2*)hbuf, (__half*)buf0, nullptr);                            // [N,64] half
    hgemm<true, true><<<dim3(MPAD / 128, HH / 128), 256>>>(
        (const __half*)buf0, wd0h, bd0, (__half*)buf1, MPAD, LL, HH);             // [N,256]
    hgemm<false, false><<<dim3(MPAD / 128, HH / 128), 256>>>(
        (const __half*)buf1, wd1h, nullptr, hbuf, MPAD, HH, HH);                  // [N,256]
    agg_dec_kernel<HH / 2, true, false><<<NN, HH / 2>>>(
        (const __half2*)hbuf, (__half*)buf0, bd1);                                // [N,256] half
    hgemm<false, false><<<dim3(MPAD / 128, FF / 128), 256>>>(
        (const __half*)buf0, wd2h, nullptr, (__half*)buf1, MPAD, HH, FF);         // [N,128]
    agg_dec_kernel<FF / 2, false, true><<<NN, FF / 2>>>(
        (const __half2*)buf1, (float*)d_out, bd2);                                // [N,128] fp32
}

// round 5
// speedup vs baseline: 1.9748x; 1.1290x over previous
#include <cuda_runtime.h>
#include <cuda_fp16.h>
#include <cuda_bf16.h>
#include <math.h>

#define TT 16
#define NN 10000
#define EE 320000
#define EN (EE + NN)
#define FF 128
#define HH 256
#define LL 64
#define HL 256
#define LSTM_BLOCKS 8

// ---------------- device scratch ----------------
__device__ int   d_rowptr[NN + 1];
__device__ int   d_cnt[NN];
__device__ int   d_col[EN];
__device__ float d_nrm_enc[EN];
__device__ float d_nrm_dec[EN];
__device__ float d_deg_enc[NN];
__device__ float d_deg_dec[NN];
__device__ float d_dis_enc[NN];
__device__ float d_dis_dec[NN];
__device__ __align__(16) float d_buf0[(size_t)TT * NN * HH];
__device__ __align__(16) float d_buf1[(size_t)TT * NN * HH];
__device__ __align__(16) __half d_hbuf[(size_t)TT * NN * HH];
__device__ __align__(16) __half d_We0h[FF * HH];
__device__ __align__(16) __half d_We1h[HH * HH];
__device__ __align__(16) __half d_Wd0h[LL * HH];
__device__ __align__(16) __half d_Wd1h[HH * HH];
__device__ __align__(16) __half d_Wd2h[HH * FF];
__device__ float d_gpool[TT * HH];
__device__ float d_zs[TT * LL];
__device__ float d_gates[2][4 * HL];
__device__ float d_zfin[LL];
__device__ int   d_idx64;

__device__ __forceinline__ void get_edge(const void* ei, int e, int& s, int& d) {
    if (d_idx64) {
        const long long* p = (const long long*)ei;
        s = (int)p[e];
        d = (int)p[EE + e];
    } else {
        const int* p = (const int*)ei;
        s = p[e];
        d = p[EE + e];
    }
}

// ---------------- preprocessing ----------------
__global__ void zero_kernel(const void* ei) {
    int i = blockIdx.x * blockDim.x + threadIdx.x;
    if (i < NN) { d_deg_enc[i] = 0.f; d_deg_dec[i] = 0.f; d_cnt[i] = 0; }
    if (i < TT * HH) d_gpool[i] = 0.f;
    if (blockIdx.x == 0 && threadIdx.x == 0) {
        const unsigned int* w = (const unsigned int*)ei;
        int is64 = 1;
        for (int k = 0; k < 64; ++k)
            if (w[2 * k + 1] != 0u) { is64 = 0; break; }
        d_idx64 = is64;
    }
}

__global__ void count_kernel(const void* ei, const float* __restrict__ ea) {
    int e = blockIdx.x * blockDim.x + threadIdx.x;
    if (e >= EN) return;
    int s, d; float w;
    if (e < EE) { get_edge(ei, e, s, d); w = ea[e]; }
    else { s = d = e - EE; w = 1.f; }
    atomicAdd(&d_deg_enc[d], w);
    atomicAdd(&d_deg_dec[d], 1.f);
    atomicAdd(&d_cnt[d], 1);
}

__global__ void scan_kernel() {
    __shared__ int cnts[NN];
    __shared__ int sh[1024];
    int tid = threadIdx.x;
    for (int i = tid; i < NN; i += 1024) cnts[i] = d_cnt[i];
    __syncthreads();
    int loc[10];
    int sum = 0;
#pragma unroll
    for (int i = 0; i < 10; ++i) {
        int idx = tid * 10 + i;
        int c = (idx < NN) ? cnts[idx] : 0;
        loc[i] = sum;
        sum += c;
    }
    sh[tid] = sum;
    __syncthreads();
    for (int off = 1; off < 1024; off <<= 1) {
        int v = (tid >= off) ? sh[tid - off] : 0;
        __syncthreads();
        sh[tid] += v;
        __syncthreads();
    }
    int excl = sh[tid] - sum;
#pragma unroll
    for (int i = 0; i < 10; ++i) {
        int idx = tid * 10 + i;
        if (idx < NN) d_rowptr[idx] = excl + loc[i];
    }
    if (tid == 1023) d_rowptr[NN] = sh[1023];
    for (int i = tid; i < NN; i += 1024) {
        d_cnt[i] = 0;
        d_dis_enc[i] = rsqrtf(d_deg_enc[i]);
        d_dis_dec[i] = rsqrtf(d_deg_dec[i]);
    }
}

__global__ void fill_kernel(const void* ei, const float* __restrict__ ea) {
    int e = blockIdx.x * blockDim.x + threadIdx.x;
    if (e >= EN) return;
    int s, d; float w;
    if (e < EE) { get_edge(ei, e, s, d); w = ea[e]; }
    else { s = d = e - EE; w = 1.f; }
    int pos = d_rowptr[d] + atomicAdd(&d_cnt[d], 1);
    d_col[pos] = s;
    d_nrm_enc[pos] = d_dis_enc[s] * w * d_dis_enc[d];
    d_nrm_dec[pos] = d_dis_dec[s] * d_dis_dec[d];
}

// ---------------- fused float -> half2 conversion of xs + all weights ----------------
#define N2_XS   (TT * NN * FF / 2)
#define N2_WE0  (FF * HH / 2)
#define N2_WE1  (HH * HH / 2)
#define N2_WD0  (LL * HH / 2)
#define N2_WD1  (HH * HH / 2)
#define N2_WD2  (HH * FF / 2)
#define N2_TOT  (N2_XS + N2_WE0 + N2_WE1 + N2_WD0 + N2_WD1 + N2_WD2)

__global__ void f2h_all_kernel(const float* xs, const float* We0, const float* We1,
                               const float* Wd0, const float* Wd1, const float* Wd2,
                               __half2* hxs, __half2* hwe0, __half2* hwe1,
                               __half2* hwd0, __half2* hwd1, __half2* hwd2) {
    int i = blockIdx.x * blockDim.x + threadIdx.x;
    const float* src; __half2* dst; int off;
    if (i < N2_XS) { src = xs; dst = hxs; off = i; }
    else if (i < N2_XS + N2_WE0) { src = We0; dst = hwe0; off = i - N2_XS; }
    else if (i < N2_XS + N2_WE0 + N2_WE1) { src = We1; dst = hwe1; off = i - N2_XS - N2_WE0; }
    else if (i < N2_XS + N2_WE0 + N2_WE1 + N2_WD0) { src = Wd0; dst = hwd0; off = i - N2_XS - N2_WE0 - N2_WE1; }
    else if (i < N2_XS + N2_WE0 + N2_WE1 + N2_WD0 + N2_WD1) { src = Wd1; dst = hwd1; off = i - N2_XS - N2_WE0 - N2_WE1 - N2_WD0; }
    else if (i < N2_TOT) { src = Wd2; dst = hwd2; off = i - N2_XS - N2_WE0 - N2_WE1 - N2_WD0 - N2_WD1; }
    else return;
    float2 v = ((const float2*)src)[off];
    dst[off] = __floats2half2_rn(v.x, v.y);
}

// ---------------- encoder layer0 agg: 16B-vector gathers, all T batched ----------------
// 256 threads = 16 f4-lanes x 16 ts. Each thread: one uint4 (8 halves) per edge from its plane.
__global__ __launch_bounds__(256) void agg_enc0_kernel(const uint4* __restrict__ src,
                                                       uint4* __restrict__ dst) {
    int n = blockIdx.x;
    int tid = threadIdx.x;
    int f4 = tid & 15;           // 128 half = 16 uint4 per node-plane
    int ts = tid >> 4;           // 0..15 = t
    int beg = d_rowptr[n], end = d_rowptr[n + 1];
    size_t pb = (size_t)ts * NN * 16;
    float a[8];
#pragma unroll
    for (int i = 0; i < 8; ++i) a[i] = 0.f;
    int e = beg;
    for (; e + 2 <= end; e += 2) {
        int s0 = __ldg(&d_col[e]);
        int s1 = __ldg(&d_col[e + 1]);
        float w0 = __ldg(&d_nrm_enc[e]);
        float w1 = __ldg(&d_nrm_enc[e + 1]);
        uint4 v0 = __ldg(src + pb + (size_t)s0 * 16 + f4);
        uint4 v1 = __ldg(src + pb + (size_t)s1 * 16 + f4);
        const __half2* h0 = (const __half2*)&v0;
        const __half2* h1 = (const __half2*)&v1;
#pragma unroll
        for (int p = 0; p < 4; ++p) {
            float2 u0 = __half22float2(h0[p]);
            float2 u1 = __half22float2(h1[p]);
            a[2 * p] += w0 * u0.x + w1 * u1.x;
            a[2 * p + 1] += w0 * u0.y + w1 * u1.y;
        }
    }
    if (e < end) {
        int s = __ldg(&d_col[e]);
        float w = __ldg(&d_nrm_enc[e]);
        uint4 v = __ldg(src + pb + (size_t)s * 16 + f4);
        const __half2* h = (const __half2*)&v;
#pragma unroll
        for (int p = 0; p < 4; ++p) {
            float2 u = __half22float2(h[p]);
            a[2 * p] += w * u.x;
            a[2 * p + 1] += w * u.y;
        }
    }
    uint4 o;
    __half2* oh = (__half2*)&o;
#pragma unroll
    for (int p = 0; p < 4; ++p) oh[p] = __floats2half2_rn(a[2 * p], a[2 * p + 1]);
    dst[pb + (size_t)n * 16 + f4] = o;
}

// ---------------- agg + bias + relu + mean-pool: 16B gathers, 8 nodes/block ----------------
// 256 threads = 32 f4-lanes x 8 ts; q in {0,1}: t = ts + 8q.
__global__ __launch_bounds__(256) void agg_pool_kernel(const uint4* __restrict__ src,
                                                       const float* __restrict__ bias) {
    int tid = threadIdx.x;
    int f4 = tid & 31;           // 256 half = 32 uint4 per node-plane
    int ts = tid >> 5;           // 0..7
    int n0 = blockIdx.x * 8;
    float b[8];
#pragma unroll
    for (int i = 0; i < 8; ++i) b[i] = bias[f4 * 8 + i];
    float pool[2][8];
#pragma unroll
    for (int q = 0; q < 2; ++q)
#pragma unroll
        for (int i = 0; i < 8; ++i) pool[q][i] = 0.f;
    size_t pb0 = (size_t)ts * NN * 32;
    size_t pb1 = (size_t)(ts + 8) * NN * 32;
    for (int n = n0; n < n0 + 8; ++n) {
        int beg = d_rowptr[n], end = d_rowptr[n + 1];
        float acc[2][8];
#pragma unroll
        for (int q = 0; q < 2; ++q)
#pragma unroll
            for (int i = 0; i < 8; ++i) acc[q][i] = 0.f;
        int e = beg;
        for (; e + 2 <= end; e += 2) {
            int s0 = __ldg(&d_col[e]);
            int s1 = __ldg(&d_col[e + 1]);
            float w0 = __ldg(&d_nrm_enc[e]);
            float w1 = __ldg(&d_nrm_enc[e + 1]);
            uint4 v00 = __ldg(src + pb0 + (size_t)s0 * 32 + f4);
            uint4 v01 = __ldg(src + pb1 + (size_t)s0 * 32 + f4);
            uint4 v10 = __ldg(src + pb0 + (size_t)s1 * 32 + f4);
            uint4 v11 = __ldg(src + pb1 + (size_t)s1 * 32 + f4);
            const __half2* h00 = (const __half2*)&v00;
            const __half2* h01 = (const __half2*)&v01;
            const __half2* h10 = (const __half2*)&v10;
            const __half2* h11 = (const __half2*)&v11;
#pragma unroll
            for (int p = 0; p < 4; ++p) {
                float2 u;
                u = __half22float2(h00[p]); acc[0][2*p] += w0*u.x; acc[0][2*p+1] += w0*u.y;
                u = __half22float2(h10[p]); acc[0][2*p] += w1*u.x; acc[0][2*p+1] += w1*u.y;
                u = __half22float2(h01[p]); acc[1][2*p] += w0*u.x; acc[1][2*p+1] += w0*u.y;
                u = __half22float2(h11[p]); acc[1][2*p] += w1*u.x; acc[1][2*p+1] += w1*u.y;
            }
        }
        if (e < end) {
            int s = __ldg(&d_col[e]);
            float w = __ldg(&d_nrm_enc[e]);
            uint4 v0 = __ldg(src + pb0 + (size_t)s * 32 + f4);
            uint4 v1 = __ldg(src + pb1 + (size_t)s * 32 + f4);
            const __half2* h0 = (const __half2*)&v0;
            const __half2* h1 = (const __half2*)&v1;
#pragma unroll
            for (int p = 0; p < 4; ++p) {
                float2 u;
                u = __half22float2(h0[p]); acc[0][2*p] += w*u.x; acc[0][2*p+1] += w*u.y;
                u = __half22float2(h1[p]); acc[1][2*p] += w*u.x; acc[1][2*p+1] += w*u.y;
            }
        }
#pragma unroll
        for (int q = 0; q < 2; ++q)
#pragma unroll
            for (int i = 0; i < 8; ++i)
                pool[q][i] += fmaxf(acc[q][i] + b[i], 0.f);
    }
#pragma unroll
    for (int q = 0; q < 2; ++q)
#pragma unroll
        for (int i = 0; i < 8; ++i)
            atomicAdd(&d_gpool[(ts + 8 * q) * HH + f4 * 8 + i], pool[q][i] * (1.0f / NN));
}

// ---------------- decoder CSR aggregation, half2 src, fp32 accum ----------------
template<int C2, bool RELU, bool OUTF>
__global__ void agg_dec_kernel(const __half2* __restrict__ src, void* __restrict__ dstv,
                               const float* __restrict__ bias) {
    int n = blockIdx.x;
    int f2 = threadIdx.x;
    int beg = d_rowptr[n], end = d_rowptr[n + 1];
    float ax0 = 0.f, ay0 = 0.f, ax1 = 0.f, ay1 = 0.f;
    float ax2 = 0.f, ay2 = 0.f, ax3 = 0.f, ay3 = 0.f;
    int e = beg;
    for (; e + 4 <= end; e += 4) {
        int s0 = __ldg(&d_col[e]);
        int s1 = __ldg(&d_col[e + 1]);
        int s2 = __ldg(&d_col[e + 2]);
        int s3 = __ldg(&d_col[e + 3]);
        float w0 = __ldg(&d_nrm_dec[e]);
        float w1 = __ldg(&d_nrm_dec[e + 1]);
        float w2 = __ldg(&d_nrm_dec[e + 2]);
        float w3 = __ldg(&d_nrm_dec[e + 3]);
        float2 v0 = __half22float2(__ldg(&src[(size_t)s0 * C2 + f2]));
        float2 v1 = __half22float2(__ldg(&src[(size_t)s1 * C2 + f2]));
        float2 v2 = __half22float2(__ldg(&src[(size_t)s2 * C2 + f2]));
        float2 v3 = __half22float2(__ldg(&src[(size_t)s3 * C2 + f2]));
        ax0 += w0 * v0.x; ay0 += w0 * v0.y;
        ax1 += w1 * v1.x; ay1 += w1 * v1.y;
        ax2 += w2 * v2.x; ay2 += w2 * v2.y;
        ax3 += w3 * v3.x; ay3 += w3 * v3.y;
    }
    for (; e < end; ++e) {
        int s = __ldg(&d_col[e]);
        float w = __ldg(&d_nrm_dec[e]);
        float2 v = __half22float2(__ldg(&src[(size_t)s * C2 + f2]));
        ax0 += w * v.x; ay0 += w * v.y;
    }
    float vx = (ax0 + ax1) + (ax2 + ax3);
    float vy = (ay0 + ay1) + (ay2 + ay3);
    if (bias) { vx += bias[2 * f2]; vy += bias[2 * f2 + 1]; }
    if (RELU) { vx = fmaxf(vx, 0.f); vy = fmaxf(vy, 0.f); }
    if (OUTF) {
        ((float2*)dstv)[(size_t)n * C2 + f2] = make_float2(vx, vy);
    } else {
        ((__half2*)dstv)[(size_t)n * C2 + f2] = __floats2half2_rn(vx, vy);
    }
}

// ================= FP16 HMMA GEMM with cp.async pipeline ==========
__device__ __forceinline__ void cp16(void* smem_dst, const void* gsrc) {
    unsigned d = (unsigned)__cvta_generic_to_shared(smem_dst);
    asm volatile("cp.async.cg.shared.global [%0], [%1], 16;" :: "r"(d), "l"(gsrc));
}
__device__ __forceinline__ void cp_commit() { asm volatile("cp.async.commit_group;"); }
__device__ __forceinline__ void cp_wait0() { asm volatile("cp.async.wait_group 0;"); }

__device__ __forceinline__ void ldsm4(unsigned& r0, unsigned& r1, unsigned& r2, unsigned& r3,
                                      const void* p) {
    unsigned a = (unsigned)__cvta_generic_to_shared(p);
    asm volatile("ldmatrix.sync.aligned.m8n8.x4.shared.b16 {%0,%1,%2,%3}, [%4];"
                 : "=r"(r0), "=r"(r1), "=r"(r2), "=r"(r3) : "r"(a));
}
__device__ __forceinline__ void ldsm4t(unsigned& r0, unsigned& r1, unsigned& r2, unsigned& r3,
                                       const void* p) {
    unsigned a = (unsigned)__cvta_generic_to_shared(p);
    asm volatile("ldmatrix.sync.aligned.m8n8.x4.trans.shared.b16 {%0,%1,%2,%3}, [%4];"
                 : "=r"(r0), "=r"(r1), "=r"(r2), "=r"(r3) : "r"(a));
}
__device__ __forceinline__ void mma16816(float* d, const unsigned* a, const unsigned* b) {
    asm volatile(
        "mma.sync.aligned.m16n8k16.row.col.f32.f16.f16.f32 "
        "{%0,%1,%2,%3},{%4,%5,%6,%7},{%8,%9},{%0,%1,%2,%3};\n"
        : "+f"(d[0]), "+f"(d[1]), "+f"(d[2]), "+f"(d[3])
        : "r"(a[0]), "r"(a[1]), "r"(a[2]), "r"(a[3]), "r"(b[0]), "r"(b[1]));
}

// Block tile 128x128, K-stage 32, 256 threads = 8 warps (2m x 4n), warp tile 64x32. M%128==0.
template<bool HASBIAS, bool RELU>
__global__ __launch_bounds__(256) void hgemm(
    const __half* __restrict__ A, const __half* __restrict__ B,
    const float* __restrict__ bias, __half* __restrict__ C,
    int M, int K, int Ncols)
{
    __shared__ __align__(16) __half As[2][128][40];
    __shared__ __align__(16) __half Bs[2][32][136];
    int tid = threadIdx.x;
    int bm = blockIdx.x * 128, bn = blockIdx.y * 128;
    int w = tid >> 5, lane = tid & 31;
    int wm = (w >> 2) * 64, wn = (w & 3) * 32;
    int lr16 = lane & 15, lh = lane >> 4;

    float acc[4][4][4];
#pragma unroll
    for (int mi = 0; mi < 4; ++mi)
#pragma unroll
        for (int nj = 0; nj < 4; ++nj)
#pragma unroll
            for (int q = 0; q < 4; ++q) acc[mi][nj][q] = 0.f;

    int ar = tid >> 2, ac = (tid & 3) * 8;
    int br = tid >> 4, bc = (tid & 15) * 8;
    const __half* Ap = A + (size_t)(bm + ar) * K + ac;
    const __half* Bp = B + (size_t)br * Ncols + bn + bc;

    cp16(&As[0][ar][ac], Ap);
    cp16(&As[0][ar + 64][ac], Ap + (size_t)64 * K);
    cp16(&Bs[0][br][bc], Bp);
    cp16(&Bs[0][br + 16][bc], Bp + (size_t)16 * Ncols);
    cp_commit();

    int nstage = K >> 5;
    for (int s = 0; s < nstage; ++s) {
        int cur = s & 1;
        cp_wait0();
        __syncthreads();
        if (s + 1 < nstage) {
            int k0 = (s + 1) << 5;
            int nxt = cur ^ 1;
            cp16(&As[nxt][ar][ac], Ap + k0);
            cp16(&As[nxt][ar + 64][ac], Ap + (size_t)64 * K + k0);
            cp16(&Bs[nxt][br][bc], Bp + (size_t)k0 * Ncols);
            cp16(&Bs[nxt][br + 16][bc], Bp + (size_t)(k0 + 16) * Ncols);
            cp_commit();
        }
#pragma unroll
        for (int k16 = 0; k16 < 2; ++k16) {
            unsigned af[4][4], bf[4][2];
#pragma unroll
            for (int mi = 0; mi < 4; ++mi)
                ldsm4(af[mi][0], af[mi][1], af[mi][2], af[mi][3],
                      &As[cur][wm + mi * 16 + lr16][k16 * 16 + lh * 8]);
#pragma unroll
            for (int p = 0; p < 2; ++p) {
                unsigned r0, r1, r2, r3;
                ldsm4t(r0, r1, r2, r3, &Bs[cur][k16 * 16 + lr16][wn + p * 16 + lh * 8]);
                bf[2 * p][0] = r0; bf[2 * p][1] = r1;
                bf[2 * p + 1][0] = r2; bf[2 * p + 1][1] = r3;
            }
#pragma unroll
            for (int mi = 0; mi < 4; ++mi)
#pragma unroll
                for (int nj = 0; nj < 4; ++nj)
                    mma16816(acc[mi][nj], af[mi], bf[nj]);
        }
        __syncthreads();
    }

    int lr = lane >> 2, lc = lane & 3;
#pragma unroll
    for (int mi = 0; mi < 4; ++mi) {
#pragma unroll
        for (int nj = 0; nj < 4; ++nj) {
            int row = bm + wm + mi * 16 + lr;
            int col = bn + wn + nj * 8 + 2 * lc;
            float b0 = 0.f, b1 = 0.f;
            if (HASBIAS) { b0 = bias[col]; b1 = bias[col + 1]; }
            float v0 = acc[mi][nj][0] + b0, v1 = acc[mi][nj][1] + b1;
            float v2 = acc[mi][nj][2] + b0, v3 = acc[mi][nj][3] + b1;
            if (RELU) {
                v0 = fmaxf(v0, 0.f); v1 = fmaxf(v1, 0.f);
                v2 = fmaxf(v2, 0.f); v3 = fmaxf(v3, 0.f);
            }
            *(__half2*)(C + (size_t)row * Ncols + col) = __floats2half2_rn(v0, v1);
            *(__half2*)(C + (size_t)(row + 8) * Ncols + col) = __floats2half2_rn(v2, v3);
        }
    }
}

// ---------------- z_t = g_t @ Wfce + bfce (256 threads, 4-way K split) ----------------
__global__ __launch_bounds__(256) void proj_z_kernel(const float* __restrict__ Wfce,
                                                     const float* __restrict__ bfce) {
    __shared__ float part[256];
    int t = blockIdx.x;
    int tid = threadIdx.x;
    int j = tid & 63;
    int kq = tid >> 6;           // 0..3
    float a = 0.f;
#pragma unroll 8
    for (int k = kq * 64; k < kq * 64 + 64; ++k)
        a += d_gpool[t * HH + k] * __ldg(&Wfce[k * LL + j]);
    part[tid] = a;
    __syncthreads();
    if (tid < 64)
        d_zs[t * LL + tid] = part[tid] + part[64 + tid] + part[128 + tid] + part[192 + tid]
                             + bfce[tid];
}

// ---------------- persistent 2-layer LSTM + head (cluster of 8 CTAs) ----------------
__device__ __forceinline__ float sigm(float x) { return 1.f / (1.f + expf(-x)); }

__device__ __forceinline__ void cluster_bar() {
    asm volatile("barrier.cluster.arrive.aligned;" ::: "memory");
    asm volatile("barrier.cluster.wait.aligned;" ::: "memory");
}

__global__ __launch_bounds__(256) __cluster_dims__(LSTM_BLOCKS, 1, 1) void lstm_kernel(
    const float* __restrict__ Wih0, const float* __restrict__ Whh0,
    const float* __restrict__ bih0, const float* __restrict__ bhh0,
    const float* __restrict__ Wih1, const float* __restrict__ Whh1,
    const float* __restrict__ bih1, const float* __restrict__ bhh1,
    const float* __restrict__ Whead, const float* __restrict__ bhead)
{
    __shared__ float x_sh[LL];
    __shared__ float h1_sh[HL];
    __shared__ float h2_sh[HL];
    __shared__ float part[256];
    int tid = threadIdx.x;
    int b = blockIdx.x;
    int jj = tid & 127;
    int j = b * 128 + jj;
    int kh = tid >> 7;
    int kb = kh * 128;
    float c1 = 0.f, c2 = 0.f;
    h1_sh[tid] = 0.f;
    h2_sh[tid] = 0.f;
    __syncthreads();
    int round = 0;

    for (int t = 0; t < TT; ++t) {
        if (tid < LL) x_sh[tid] = d_zs[t * LL + tid];
        __syncthreads();

        float p0 = 0.f, p1 = 0.f, p2 = 0.f, p3 = 0.f;
#pragma unroll 8
        for (int k = 0; k < 128; k += 4) {
            p0 += h1_sh[kb + k + 0] * Whh0[(size_t)(kb + k + 0) * 1024 + j];
            p1 += h1_sh[kb + k + 1] * Whh0[(size_t)(kb + k + 1) * 1024 + j];
            p2 += h1_sh[kb + k + 2] * Whh0[(size_t)(kb + k + 2) * 1024 + j];
            p3 += h1_sh[kb + k + 3] * Whh0[(size_t)(kb + k + 3) * 1024 + j];
        }
        if (kh == 0) {
#pragma unroll 8
            for (int k = 0; k < LL; k += 4) {
                p0 += x_sh[k + 0] * Wih0[(size_t)(k + 0) * 1024 + j];
                p1 += x_sh[k + 1] * Wih0[(size_t)(k + 1) * 1024 + j];
                p2 += x_sh[k + 2] * Wih0[(size_t)(k + 2) * 1024 + j];
                p3 += x_sh[k + 3] * Wih0[(size_t)(k + 3) * 1024 + j];
            }
        }
        part[tid] = p0 + p1 + p2 + p3;
        __syncthreads();
        int pb = round & 1;
        if (tid < 128)
            __stcg(&d_gates[pb][j], part[jj] + part[jj + 128] + bih0[j] + bhh0[j]);
        round++;
        __threadfence();
        cluster_bar();
        {
            float gi = __ldcg(&d_gates[pb][tid]);
            float gf = __ldcg(&d_gates[pb][256 + tid]);
            float gg = __ldcg(&d_gates[pb][512 + tid]);
            float go = __ldcg(&d_gates[pb][768 + tid]);
            c1 = sigm(gf) * c1 + sigm(gi) * tanhf(gg);
            h1_sh[tid] = sigm(go) * tanhf(c1);
        }
        __syncthreads();

        p0 = 0.f; p1 = 0.f; p2 = 0.f; p3 = 0.f;
#pragma unroll 4
        for (int k = 0; k < 128; k += 4) {
            p0 += h2_sh[kb + k + 0] * Whh1[(size_t)(kb + k + 0) * 1024 + j]
                + h1_sh[kb + k + 0] * Wih1[(size_t)(kb + k + 0) * 1024 + j];
            p1 += h2_sh[kb + k + 1] * Whh1[(size_t)(kb + k + 1) * 1024 + j]
                + h1_sh[kb + k + 1] * Wih1[(size_t)(kb + k + 1) * 1024 + j];
            p2 += h2_sh[kb + k + 2] * Whh1[(size_t)(kb + k + 2) * 1024 + j]
                + h1_sh[kb + k + 2] * Wih1[(size_t)(kb + k + 2) * 1024 + j];
            p3 += h2_sh[kb + k + 3] * Whh1[(size_t)(kb + k + 3) * 1024 + j]
                + h1_sh[kb + k + 3] * Wih1[(size_t)(kb + k + 3) * 1024 + j];
        }
        part[tid] = p0 + p1 + p2 + p3;
        __syncthreads();
        pb = round & 1;
        if (tid < 128)
            __stcg(&d_gates[pb][j], part[jj] + part[jj + 128] + bih1[j] + bhh1[j]);
        round++;
        __threadfence();
        cluster_bar();
        {
            float gi = __ldcg(&d_gates[pb][tid]);
            float gf = __ldcg(&d_gates[pb][256 + tid]);
            float gg = __ldcg(&d_gates[pb][512 + tid]);
            float go = __ldcg(&d_gates[pb][768 + tid]);
            c2 = sigm(gf) * c2 + sigm(gi) * tanhf(gg);
            h2_sh[tid] = sigm(go) * tanhf(c2);
        }
        __syncthreads();
    }

    if (b == 0 && tid < LL) {
        float a = bhead[tid];
        for (int k = 0; k < HL; ++k)
            a += h2_sh[k] * Whead[k * LL + tid];
        d_zfin[tid] = a;
    }
}

// ---------------- decoder fc: relu(z @ Wfcd + bfcd) -> half [N, L] ----------------
__global__ void fcd_kernel(const float* __restrict__ Wfcd, const float* __restrict__ bfcd,
                           __half2* __restrict__ out) {
    __shared__ float z[LL];
    if (threadIdx.x < LL) z[threadIdx.x] = d_zfin[threadIdx.x];
    __syncthreads();
    int q = blockIdx.x * blockDim.x + threadIdx.x;
    if (q >= NN * LL / 2) return;
    float2 bb = ((const float2*)bfcd)[q];
    float ax = bb.x, ay = bb.y;
#pragma unroll 8
    for (int k = 0; k < LL; ++k) {
        float2 w = ((const float2*)(Wfcd + (size_t)k * (NN * LL)))[q];
        ax += z[k] * w.x;
        ay += z[k] * w.y;
    }
    out[q] = __floats2half2_rn(fmaxf(ax, 0.f), fmaxf(ay, 0.f));
}

// ---------------- launch ----------------
extern "C" void kernel_launch(void* const* d_in, const int* in_sizes, int n_in,
                              void* d_out, int out_size) {
    const float* xs        = (const float*)d_in[0];
    const float* edge_attr = (const float*)d_in[1];
    const float* We0  = (const float*)d_in[2];
    const float* be0  = (const float*)d_in[3];
    const float* We1  = (const float*)d_in[4];
    const float* be1  = (const float*)d_in[5];
    const float* Wfce = (const float*)d_in[6];
    const float* bfce = (const float*)d_in[7];
    const float* Wih0 = (const float*)d_in[8];
    const float* Whh0 = (const float*)d_in[9];
    const float* bih0 = (const float*)d_in[10];
    const float* bhh0 = (const float*)d_in[11];
    const float* Wih1 = (const float*)d_in[12];
    const float* Whh1 = (const float*)d_in[13];
    const float* bih1 = (const float*)d_in[14];
    const float* bhh1 = (const float*)d_in[15];
    const float* Whead = (const float*)d_in[16];
    const float* bhead = (const float*)d_in[17];
    const float* Wfcd = (const float*)d_in[18];
    const float* bfcd = (const float*)d_in[19];
    const float* Wd0  = (const float*)d_in[20];
    const float* bd0  = (const float*)d_in[21];
    const float* Wd1  = (const float*)d_in[22];
    const float* bd1  = (const float*)d_in[23];
    const float* Wd2  = (const float*)d_in[24];
    const float* bd2  = (const float*)d_in[25];
    const void*  eidx = d_in[26];

    float *buf0, *buf1;
    __half *hbuf, *we0h, *we1h, *wd0h, *wd1h, *wd2h;
    cudaGetSymbolAddress((void**)&buf0, d_buf0);
    cudaGetSymbolAddress((void**)&buf1, d_buf1);
    cudaGetSymbolAddress((void**)&hbuf, d_hbuf);
    cudaGetSymbolAddress((void**)&we0h, d_We0h);
    cudaGetSymbolAddress((void**)&we1h, d_We1h);
    cudaGetSymbolAddress((void**)&wd0h, d_Wd0h);
    cudaGetSymbolAddress((void**)&wd1h, d_Wd1h);
    cudaGetSymbolAddress((void**)&wd2h, d_Wd2h);

    const int MPAD = 10112;   // 79 * 128 >= NN

    // ---- preprocessing ----
    zero_kernel<<<(NN + 255) / 256, 256>>>(eidx);
    count_kernel<<<(EN + 255) / 256, 256>>>(eidx, edge_attr);
    scan_kernel<<<1, 1024>>>();
    fill_kernel<<<(EN + 255) / 256, 256>>>(eidx, edge_attr);

    // ---- fused conversions (xs + all fp16 weights) ----
    f2h_all_kernel<<<(N2_TOT + 255) / 256, 256>>>(
        xs, We0, We1, Wd0, Wd1, Wd2,
        (__half2*)hbuf, (__half2*)we0h, (__half2*)we1h,
        (__half2*)wd0h, (__half2*)wd1h, (__half2*)wd2h);

    // ---- encoder ----
    agg_enc0_kernel<<<NN, 256>>>((const uint4*)hbuf, (uint4*)buf0);
    hgemm<true, true><<<dim3(TT * NN / 128, HH / 128), 256>>>(
        (const __half*)buf0, we0h, be0, (__half*)buf1, TT * NN, FF, HH);
    hgemm<false, false><<<dim3(TT * NN / 128, HH / 128), 256>>>(
        (const __half*)buf1, we1h, nullptr, hbuf, TT * NN, HH, HH);
    agg_pool_kernel<<<1250, 256>>>((const uint4*)hbuf, be1);
    proj_z_kernel<<<TT, 256>>>(Wfce, bfce);

    // ---- LSTM + head ----
    lstm_kernel<<<LSTM_BLOCKS, 256>>>(Wih0, Whh0, bih0, bhh0,
                                      Wih1, Whh1, bih1, bhh1, Whead, bhead);

    // ---- decoder ----
    fcd_kernel<<<(NN * LL / 2 + 255) / 256, 256>>>(Wfcd, bfcd, (__half2*)hbuf);
    agg_dec_kernel<LL / 2, false, false><<<NN, LL / 2>>>(
        (const __half2*)hbuf, (__half*)buf0, nullptr);
    hgemm<true, true><<<dim3(MPAD / 128, HH / 128), 256>>>(
        (const __half*)buf0, wd0h, bd0, (__half*)buf1, MPAD, LL, HH);
    hgemm<false, false><<<dim3(MPAD / 128, HH / 128), 256>>>(
        (const __half*)buf1, wd1h, nullptr, hbuf, MPAD, HH, HH);
    agg_dec_kernel<HH / 2, true, false><<<NN, HH / 2>>>(
        (const __half2*)hbuf, (__half*)buf0, bd1);
    hgemm<false, false><<<dim3(MPAD / 128, FF / 128), 256>>>(
        (const __half*)buf0, wd2h, nullptr, (__half*)buf1, MPAD, HH, FF);
    agg_dec_kernel<FF / 2, false, true><<<NN, FF / 2>>>(
        (const __half2*)buf1, (float*)d_out, bd2);
}

// round 6
// speedup vs baseline: 2.3429x; 1.1864x over previous
#include <cuda_runtime.h>
#include <cuda_fp16.h>
#include <cuda_bf16.h>
#include <math.h>

#define TT 16
#define NN 10000
#define EE 320000
#define EN (EE + NN)
#define FF 128
#define HH 256
#define LL 64
#define HL 256
#define LSTM_BLOCKS 8

// ---------------- device scratch ----------------
__device__ int   d_rowptr[NN + 1];
__device__ int   d_cnt[NN];
__device__ int   d_bsum[10];
__device__ int   d_boff[10];
__device__ int   d_col[EN];
__device__ float d_nrm_enc[EN];
__device__ float d_nrm_dec[EN];
__device__ float d_deg_enc[NN];
__device__ float d_deg_dec[NN];
__device__ float d_dis_enc[NN];
__device__ float d_dis_dec[NN];
__device__ __align__(16) float d_buf0[(size_t)TT * NN * HH];
__device__ __align__(16) float d_buf1[(size_t)TT * NN * HH];
__device__ __align__(16) __half d_hbuf[(size_t)TT * NN * HH];
__device__ __align__(16) __half d_We0h[FF * HH];
__device__ __align__(16) __half d_We1h[HH * HH];
__device__ __align__(16) __half d_Wd0h[LL * HH];
__device__ __align__(16) __half d_Wd1h[HH * HH];
__device__ __align__(16) __half d_Wd2h[HH * FF];
__device__ __align__(16) __half d_Wih0h[LL * 4 * HL];
__device__ __align__(16) __half d_Whh0h[HL * 4 * HL];
__device__ __align__(16) __half d_Wih1h[HL * 4 * HL];
__device__ __align__(16) __half d_Whh1h[HL * 4 * HL];
__device__ float d_gpool[TT * HH];
__device__ float d_zs[TT * LL];
__device__ __align__(16) float d_gates[2][4 * HL];
__device__ float d_zfin[LL];
__device__ int   d_idx64;

__device__ __forceinline__ void get_edge(const void* ei, int e, int& s, int& d) {
    if (d_idx64) {
        const long long* p = (const long long*)ei;
        s = (int)p[e];
        d = (int)p[EE + e];
    } else {
        const int* p = (const int*)ei;
        s = p[e];
        d = p[EE + e];
    }
}

// ---------------- preprocessing ----------------
__global__ void zero_kernel(const void* ei) {
    int i = blockIdx.x * blockDim.x + threadIdx.x;
    if (i < NN) { d_deg_enc[i] = 0.f; d_deg_dec[i] = 0.f; d_cnt[i] = 0; }
    if (i < TT * HH) d_gpool[i] = 0.f;
    if (blockIdx.x == 0 && threadIdx.x == 0) {
        const unsigned int* w = (const unsigned int*)ei;
        int is64 = 1;
        for (int k = 0; k < 64; ++k)
            if (w[2 * k + 1] != 0u) { is64 = 0; break; }
        d_idx64 = is64;
    }
}

__global__ void count_kernel(const void* ei, const float* __restrict__ ea) {
    int e = blockIdx.x * blockDim.x + threadIdx.x;
    if (e >= EN) return;
    int s, d; float w;
    if (e < EE) { get_edge(ei, e, s, d); w = ea[e]; }
    else { s = d = e - EE; w = 1.f; }
    atomicAdd(&d_deg_enc[d], w);
    atomicAdd(&d_deg_dec[d], 1.f);   // also serves as integer edge count (exact in fp32)
}

// phase A: per-block (1000 nodes) local exclusive scan + block sums + rsqrt pass
__global__ __launch_bounds__(1024) void scanA_kernel() {
    __shared__ int sh[1024];
    int blk = blockIdx.x, tid = threadIdx.x;
    int idx = blk * 1000 + tid;
    int c = (tid < 1000) ? (int)d_deg_dec[idx] : 0;
    sh[tid] = c;
    __syncthreads();
    for (int off = 1; off < 1024; off <<= 1) {
        int v = (tid >= off) ? sh[tid - off] : 0;
        __syncthreads();
        sh[tid] += v;
        __syncthreads();
    }
    if (tid < 1000) {
        d_rowptr[idx] = sh[tid] - c;
        d_dis_enc[idx] = rsqrtf(d_deg_enc[idx]);
        d_dis_dec[idx] = rsqrtf(d_deg_dec[idx]);
    }
    if (tid == 1023) d_bsum[blk] = sh[1023];
}

// phase B: scan the 10 block sums (one warp)
__global__ void scanB_kernel() {
    int lane = threadIdx.x;
    int v = (lane < 10) ? d_bsum[lane] : 0;
    int orig = v;
    for (int o = 1; o < 32; o <<= 1) {
        int u = __shfl_up_sync(0xffffffffu, v, o);
        if (lane >= o) v += u;
    }
    if (lane < 10) d_boff[lane] = v - orig;
    if (lane == 31) d_rowptr[NN] = v;
}

// phase C: add block offsets
__global__ __launch_bounds__(1024) void scanC_kernel() {
    int blk = blockIdx.x, tid = threadIdx.x;
    int idx = blk * 1000 + tid;
    if (tid < 1000) d_rowptr[idx] += d_boff[blk];
}

__global__ void fill_kernel(const void* ei, const float* __restrict__ ea) {
    int e = blockIdx.x * blockDim.x + threadIdx.x;
    if (e >= EN) return;
    int s, d; float w;
    if (e < EE) { get_edge(ei, e, s, d); w = ea[e]; }
    else { s = d = e - EE; w = 1.f; }
    int pos = d_rowptr[d] + atomicAdd(&d_cnt[d], 1);
    d_col[pos] = s;
    d_nrm_enc[pos] = d_dis_enc[s] * w * d_dis_enc[d];
    d_nrm_dec[pos] = d_dis_dec[s] * d_dis_dec[d];
}

// ---------------- fused float -> half2 conversion of xs + all weights ----------------
#define N2_XS    (TT * NN * FF / 2)
#define N2_WE0   (FF * HH / 2)
#define N2_WE1   (HH * HH / 2)
#define N2_WD0   (LL * HH / 2)
#define N2_WD1   (HH * HH / 2)
#define N2_WD2   (HH * FF / 2)
#define N2_WIH0  (LL * 4 * HL / 2)
#define N2_WHH0  (HL * 4 * HL / 2)
#define N2_WIH1  (HL * 4 * HL / 2)
#define N2_WHH1  (HL * 4 * HL / 2)
#define N2_TOT   (N2_XS + N2_WE0 + N2_WE1 + N2_WD0 + N2_WD1 + N2_WD2 + \
                  N2_WIH0 + N2_WHH0 + N2_WIH1 + N2_WHH1)

__global__ void f2h_all_kernel(const float* xs, const float* We0, const float* We1,
                               const float* Wd0, const float* Wd1, const float* Wd2,
                               const float* Wih0, const float* Whh0,
                               const float* Wih1, const float* Whh1,
                               __half2* hxs, __half2* hwe0, __half2* hwe1,
                               __half2* hwd0, __half2* hwd1, __half2* hwd2,
                               __half2* hwih0, __half2* hwhh0,
                               __half2* hwih1, __half2* hwhh1) {
    int i = blockIdx.x * blockDim.x + threadIdx.x;
    const float* src; __half2* dst; int off = i;
    if (off < N2_XS) { src = xs; dst = hxs; }
    else if ((off -= N2_XS) < N2_WE0) { src = We0; dst = hwe0; }
    else if ((off -= N2_WE0) < N2_WE1) { src = We1; dst = hwe1; }
    else if ((off -= N2_WE1) < N2_WD0) { src = Wd0; dst = hwd0; }
    else if ((off -= N2_WD0) < N2_WD1) { src = Wd1; dst = hwd1; }
    else if ((off -= N2_WD1) < N2_WD2) { src = Wd2; dst = hwd2; }
    else if ((off -= N2_WD2) < N2_WIH0) { src = Wih0; dst = hwih0; }
    else if ((off -= N2_WIH0) < N2_WHH0) { src = Whh0; dst = hwhh0; }
    else if ((off -= N2_WHH0) < N2_WIH1) { src = Wih1; dst = hwih1; }
    else if ((off -= N2_WIH1) < N2_WHH1) { src = Whh1; dst = hwhh1; }
    else return;
    float2 v = ((const float2*)src)[off];
    dst[off] = __floats2half2_rn(v.x, v.y);
}

// ---------------- encoder layer0 agg: 16B-vector gathers, all T batched ----------------
__global__ __launch_bounds__(256) void agg_enc0_kernel(const uint4* __restrict__ src,
                                                       uint4* __restrict__ dst) {
    int n = blockIdx.x;
    int tid = threadIdx.x;
    int f4 = tid & 15;
    int ts = tid >> 4;
    int beg = d_rowptr[n], end = d_rowptr[n + 1];
    size_t pb = (size_t)ts * NN * 16;
    float a[8];
#pragma unroll
    for (int i = 0; i < 8; ++i) a[i] = 0.f;
    int e = beg;
    for (; e + 2 <= end; e += 2) {
        int s0 = __ldg(&d_col[e]);
        int s1 = __ldg(&d_col[e + 1]);
        float w0 = __ldg(&d_nrm_enc[e]);
        float w1 = __ldg(&d_nrm_enc[e + 1]);
        uint4 v0 = __ldg(src + pb + (size_t)s0 * 16 + f4);
        uint4 v1 = __ldg(src + pb + (size_t)s1 * 16 + f4);
        const __half2* h0 = (const __half2*)&v0;
        const __half2* h1 = (const __half2*)&v1;
#pragma unroll
        for (int p = 0; p < 4; ++p) {
            float2 u0 = __half22float2(h0[p]);
            float2 u1 = __half22float2(h1[p]);
            a[2 * p] += w0 * u0.x + w1 * u1.x;
            a[2 * p + 1] += w0 * u0.y + w1 * u1.y;
        }
    }
    if (e < end) {
        int s = __ldg(&d_col[e]);
        float w = __ldg(&d_nrm_enc[e]);
        uint4 v = __ldg(src + pb + (size_t)s * 16 + f4);
        const __half2* h = (const __half2*)&v;
#pragma unroll
        for (int p = 0; p < 4; ++p) {
            float2 u = __half22float2(h[p]);
            a[2 * p] += w * u.x;
            a[2 * p + 1] += w * u.y;
        }
    }
    uint4 o;
    __half2* oh = (__half2*)&o;
#pragma unroll
    for (int p = 0; p < 4; ++p) oh[p] = __floats2half2_rn(a[2 * p], a[2 * p + 1]);
    dst[pb + (size_t)n * 16 + f4] = o;
}

// ---------------- agg + bias + relu + mean-pool ----------------
__global__ __launch_bounds__(256) void agg_pool_kernel(const uint4* __restrict__ src,
                                                       const float* __restrict__ bias) {
    int tid = threadIdx.x;
    int f4 = tid & 31;
    int ts = tid >> 5;
    int n0 = blockIdx.x * 8;
    float b[8];
#pragma unroll
    for (int i = 0; i < 8; ++i) b[i] = bias[f4 * 8 + i];
    float pool[2][8];
#pragma unroll
    for (int q = 0; q < 2; ++q)
#pragma unroll
        for (int i = 0; i < 8; ++i) pool[q][i] = 0.f;
    size_t pb0 = (size_t)ts * NN * 32;
    size_t pb1 = (size_t)(ts + 8) * NN * 32;
    for (int n = n0; n < n0 + 8; ++n) {
        int beg = d_rowptr[n], end = d_rowptr[n + 1];
        float acc[2][8];
#pragma unroll
        for (int q = 0; q < 2; ++q)
#pragma unroll
            for (int i = 0; i < 8; ++i) acc[q][i] = 0.f;
        int e = beg;
        for (; e + 2 <= end; e += 2) {
            int s0 = __ldg(&d_col[e]);
            int s1 = __ldg(&d_col[e + 1]);
            float w0 = __ldg(&d_nrm_enc[e]);
            float w1 = __ldg(&d_nrm_enc[e + 1]);
            uint4 v00 = __ldg(src + pb0 + (size_t)s0 * 32 + f4);
            uint4 v01 = __ldg(src + pb1 + (size_t)s0 * 32 + f4);
            uint4 v10 = __ldg(src + pb0 + (size_t)s1 * 32 + f4);
            uint4 v11 = __ldg(src + pb1 + (size_t)s1 * 32 + f4);
            const __half2* h00 = (const __half2*)&v00;
            const __half2* h01 = (const __half2*)&v01;
            const __half2* h10 = (const __half2*)&v10;
            const __half2* h11 = (const __half2*)&v11;
#pragma unroll
            for (int p = 0; p < 4; ++p) {
                float2 u;
                u = __half22float2(h00[p]); acc[0][2*p] += w0*u.x; acc[0][2*p+1] += w0*u.y;
                u = __half22float2(h10[p]); acc[0][2*p] += w1*u.x; acc[0][2*p+1] += w1*u.y;
                u = __half22float2(h01[p]); acc[1][2*p] += w0*u.x; acc[1][2*p+1] += w0*u.y;
                u = __half22float2(h11[p]); acc[1][2*p] += w1*u.x; acc[1][2*p+1] += w1*u.y;
            }
        }
        if (e < end) {
            int s = __ldg(&d_col[e]);
            float w = __ldg(&d_nrm_enc[e]);
            uint4 v0 = __ldg(src + pb0 + (size_t)s * 32 + f4);
            uint4 v1 = __ldg(src + pb1 + (size_t)s * 32 + f4);
            const __half2* h0 = (const __half2*)&v0;
            const __half2* h1 = (const __half2*)&v1;
#pragma unroll
            for (int p = 0; p < 4; ++p) {
                float2 u;
                u = __half22float2(h0[p]); acc[0][2*p] += w*u.x; acc[0][2*p+1] += w*u.y;
                u = __half22float2(h1[p]); acc[1][2*p] += w*u.x; acc[1][2*p+1] += w*u.y;
            }
        }
#pragma unroll
        for (int q = 0; q < 2; ++q)
#pragma unroll
            for (int i = 0; i < 8; ++i)
                pool[q][i] += fmaxf(acc[q][i] + b[i], 0.f);
    }
#pragma unroll
    for (int q = 0; q < 2; ++q)
#pragma unroll
        for (int i = 0; i < 8; ++i)
            atomicAdd(&d_gpool[(ts + 8 * q) * HH + f4 * 8 + i], pool[q][i] * (1.0f / NN));
}

// ---------------- decoder CSR aggregation: NPB nodes per block ----------------
template<int C2, int NPB, bool RELU, bool OUTF>
__global__ void agg_dec_kernel(const __half2* __restrict__ src, void* __restrict__ dstv,
                               const float* __restrict__ bias) {
    int tid = threadIdx.x;
    int n = blockIdx.x * NPB + tid / C2;
    int f2 = tid % C2;
    if (n >= NN) return;
    int beg = d_rowptr[n], end = d_rowptr[n + 1];
    float ax0 = 0.f, ay0 = 0.f, ax1 = 0.f, ay1 = 0.f;
    float ax2 = 0.f, ay2 = 0.f, ax3 = 0.f, ay3 = 0.f;
    int e = beg;
    for (; e + 4 <= end; e += 4) {
        int s0 = __ldg(&d_col[e]);
        int s1 = __ldg(&d_col[e + 1]);
        int s2 = __ldg(&d_col[e + 2]);
        int s3 = __ldg(&d_col[e + 3]);
        float w0 = __ldg(&d_nrm_dec[e]);
        float w1 = __ldg(&d_nrm_dec[e + 1]);
        float w2 = __ldg(&d_nrm_dec[e + 2]);
        float w3 = __ldg(&d_nrm_dec[e + 3]);
        float2 v0 = __half22float2(__ldg(&src[(size_t)s0 * C2 + f2]));
        float2 v1 = __half22float2(__ldg(&src[(size_t)s1 * C2 + f2]));
        float2 v2 = __half22float2(__ldg(&src[(size_t)s2 * C2 + f2]));
        float2 v3 = __half22float2(__ldg(&src[(size_t)s3 * C2 + f2]));
        ax0 += w0 * v0.x; ay0 += w0 * v0.y;
        ax1 += w1 * v1.x; ay1 += w1 * v1.y;
        ax2 += w2 * v2.x; ay2 += w2 * v2.y;
        ax3 += w3 * v3.x; ay3 += w3 * v3.y;
    }
    for (; e < end; ++e) {
        int s = __ldg(&d_col[e]);
        float w = __ldg(&d_nrm_dec[e]);
        float2 v = __half22float2(__ldg(&src[(size_t)s * C2 + f2]));
        ax0 += w * v.x; ay0 += w * v.y;
    }
    float vx = (ax0 + ax1) + (ax2 + ax3);
    float vy = (ay0 + ay1) + (ay2 + ay3);
    if (bias) { vx += bias[2 * f2]; vy += bias[2 * f2 + 1]; }
    if (RELU) { vx = fmaxf(vx, 0.f); vy = fmaxf(vy, 0.f); }
    if (OUTF) {
        ((float2*)dstv)[(size_t)n * C2 + f2] = make_float2(vx, vy);
    } else {
        ((__half2*)dstv)[(size_t)n * C2 + f2] = __floats2half2_rn(vx, vy);
    }
}

// ================= FP16 HMMA GEMM with cp.async pipeline ==========
__device__ __forceinline__ void cp16(void* smem_dst, const void* gsrc) {
    unsigned d = (unsigned)__cvta_generic_to_shared(smem_dst);
    asm volatile("cp.async.cg.shared.global [%0], [%1], 16;" :: "r"(d), "l"(gsrc));
}
__device__ __forceinline__ void cp_commit() { asm volatile("cp.async.commit_group;"); }
__device__ __forceinline__ void cp_wait0() { asm volatile("cp.async.wait_group 0;"); }

__device__ __forceinline__ void ldsm4(unsigned& r0, unsigned& r1, unsigned& r2, unsigned& r3,
                                      const void* p) {
    unsigned a = (unsigned)__cvta_generic_to_shared(p);
    asm volatile("ldmatrix.sync.aligned.m8n8.x4.shared.b16 {%0,%1,%2,%3}, [%4];"
                 : "=r"(r0), "=r"(r1), "=r"(r2), "=r"(r3) : "r"(a));
}
__device__ __forceinline__ void ldsm4t(unsigned& r0, unsigned& r1, unsigned& r2, unsigned& r3,
                                       const void* p) {
    unsigned a = (unsigned)__cvta_generic_to_shared(p);
    asm volatile("ldmatrix.sync.aligned.m8n8.x4.trans.shared.b16 {%0,%1,%2,%3}, [%4];"
                 : "=r"(r0), "=r"(r1), "=r"(r2), "=r"(r3) : "r"(a));
}
__device__ __forceinline__ void mma16816(float* d, const unsigned* a, const unsigned* b) {
    asm volatile(
        "mma.sync.aligned.m16n8k16.row.col.f32.f16.f16.f32 "
        "{%0,%1,%2,%3},{%4,%5,%6,%7},{%8,%9},{%0,%1,%2,%3};\n"
        : "+f"(d[0]), "+f"(d[1]), "+f"(d[2]), "+f"(d[3])
        : "r"(a[0]), "r"(a[1]), "r"(a[2]), "r"(a[3]), "r"(b[0]), "r"(b[1]));
}

template<bool HASBIAS, bool RELU>
__global__ __launch_bounds__(256) void hgemm(
    const __half* __restrict__ A, const __half* __restrict__ B,
    const float* __restrict__ bias, __half* __restrict__ C,
    int M, int K, int Ncols)
{
    __shared__ __align__(16) __half As[2][128][40];
    __shared__ __align__(16) __half Bs[2][32][136];
    int tid = threadIdx.x;
    int bm = blockIdx.x * 128, bn = blockIdx.y * 128;
    int w = tid >> 5, lane = tid & 31;
    int wm = (w >> 2) * 64, wn = (w & 3) * 32;
    int lr16 = lane & 15, lh = lane >> 4;

    float acc[4][4][4];
#pragma unroll
    for (int mi = 0; mi < 4; ++mi)
#pragma unroll
        for (int nj = 0; nj < 4; ++nj)
#pragma unroll
            for (int q = 0; q < 4; ++q) acc[mi][nj][q] = 0.f;

    int ar = tid >> 2, ac = (tid & 3) * 8;
    int br = tid >> 4, bc = (tid & 15) * 8;
    const __half* Ap = A + (size_t)(bm + ar) * K + ac;
    const __half* Bp = B + (size_t)br * Ncols + bn + bc;

    cp16(&As[0][ar][ac], Ap);
    cp16(&As[0][ar + 64][ac], Ap + (size_t)64 * K);
    cp16(&Bs[0][br][bc], Bp);
    cp16(&Bs[0][br + 16][bc], Bp + (size_t)16 * Ncols);
    cp_commit();

    int nstage = K >> 5;
    for (int s = 0; s < nstage; ++s) {
        int cur = s & 1;
        cp_wait0();
        __syncthreads();
        if (s + 1 < nstage) {
            int k0 = (s + 1) << 5;
            int nxt = cur ^ 1;
            cp16(&As[nxt][ar][ac], Ap + k0);
            cp16(&As[nxt][ar + 64][ac], Ap + (size_t)64 * K + k0);
            cp16(&Bs[nxt][br][bc], Bp + (size_t)k0 * Ncols);
            cp16(&Bs[nxt][br + 16][bc], Bp + (size_t)(k0 + 16) * Ncols);
            cp_commit();
        }
#pragma unroll
        for (int k16 = 0; k16 < 2; ++k16) {
            unsigned af[4][4], bf[4][2];
#pragma unroll
            for (int mi = 0; mi < 4; ++mi)
                ldsm4(af[mi][0], af[mi][1], af[mi][2], af[mi][3],
                      &As[cur][wm + mi * 16 + lr16][k16 * 16 + lh * 8]);
#pragma unroll
            for (int p = 0; p < 2; ++p) {
                unsigned r0, r1, r2, r3;
                ldsm4t(r0, r1, r2, r3, &Bs[cur][k16 * 16 + lr16][wn + p * 16 + lh * 8]);
                bf[2 * p][0] = r0; bf[2 * p][1] = r1;
                bf[2 * p + 1][0] = r2; bf[2 * p + 1][1] = r3;
            }
#pragma unroll
            for (int mi = 0; mi < 4; ++mi)
#pragma unroll
                for (int nj = 0; nj < 4; ++nj)
                    mma16816(acc[mi][nj], af[mi], bf[nj]);
        }
        __syncthreads();
    }

    int lr = lane >> 2, lc = lane & 3;
#pragma unroll
    for (int mi = 0; mi < 4; ++mi) {
#pragma unroll
        for (int nj = 0; nj < 4; ++nj) {
            int row = bm + wm + mi * 16 + lr;
            int col = bn + wn + nj * 8 + 2 * lc;
            float b0 = 0.f, b1 = 0.f;
            if (HASBIAS) { b0 = bias[col]; b1 = bias[col + 1]; }
            float v0 = acc[mi][nj][0] + b0, v1 = acc[mi][nj][1] + b1;
            float v2 = acc[mi][nj][2] + b0, v3 = acc[mi][nj][3] + b1;
            if (RELU) {
                v0 = fmaxf(v0, 0.f); v1 = fmaxf(v1, 0.f);
                v2 = fmaxf(v2, 0.f); v3 = fmaxf(v3, 0.f);
            }
            *(__half2*)(C + (size_t)row * Ncols + col) = __floats2half2_rn(v0, v1);
            *(__half2*)(C + (size_t)(row + 8) * Ncols + col) = __floats2half2_rn(v2, v3);
        }
    }
}

// ---------------- z_t = g_t @ Wfce + bfce ----------------
__global__ __launch_bounds__(256) void proj_z_kernel(const float* __restrict__ Wfce,
                                                     const float* __restrict__ bfce) {
    __shared__ float part[256];
    int t = blockIdx.x;
    int tid = threadIdx.x;
    int j = tid & 63;
    int kq = tid >> 6;
    float a = 0.f;
#pragma unroll 8
    for (int k = kq * 64; k < kq * 64 + 64; ++k)
        a += d_gpool[t * HH + k] * __ldg(&Wfce[k * LL + j]);
    part[tid] = a;
    __syncthreads();
    if (tid < 64)
        d_zs[t * LL + tid] = part[tid] + part[64 + tid] + part[128 + tid] + part[192 + tid]
                             + bfce[tid];
}

// ---------------- persistent 2-layer LSTM + head (cluster of 8 CTAs, fp16 weights) ----------------
__device__ __forceinline__ float sigm(float x) { return 1.f / (1.f + expf(-x)); }

__device__ __forceinline__ void cluster_bar() {
    asm volatile("barrier.cluster.arrive.aligned;" ::: "memory");
    asm volatile("barrier.cluster.wait.aligned;" ::: "memory");
}

__global__ __launch_bounds__(256) __cluster_dims__(LSTM_BLOCKS, 1, 1) void lstm_kernel(
    const __half2* __restrict__ Wih0, const __half2* __restrict__ Whh0,
    const float* __restrict__ bih0, const float* __restrict__ bhh0,
    const __half2* __restrict__ Wih1, const __half2* __restrict__ Whh1,
    const float* __restrict__ bih1, const float* __restrict__ bhh1,
    const float* __restrict__ Whead, const float* __restrict__ bhead)
{
    __shared__ float x_sh[LL];
    __shared__ float h1_sh[HL];
    __shared__ float h2_sh[HL];
    __shared__ float2 part[256];
    int tid = threadIdx.x;
    int b = blockIdx.x;
    int p = tid & 63;            // output-pair within CTA
    int kq = tid >> 6;           // 0..3
    int jp = b * 64 + p;         // global half2 column (512 total)
    float c1 = 0.f, c2 = 0.f;
    if (tid < HL) { h1_sh[tid] = 0.f; h2_sh[tid] = 0.f; }
    __syncthreads();
    int round = 0;

    for (int t = 0; t < TT; ++t) {
        if (tid < LL) x_sh[tid] = d_zs[t * LL + tid];
        __syncthreads();

        // ---- layer 1 gates ----
        float ax = 0.f, ay = 0.f;
#pragma unroll 8
        for (int k = kq * 64; k < kq * 64 + 64; ++k) {
            float h = h1_sh[k];
            float2 w = __half22float2(Whh0[(size_t)k * 512 + jp]);
            ax += h * w.x; ay += h * w.y;
        }
#pragma unroll 8
        for (int k = kq * 16; k < kq * 16 + 16; ++k) {
            float x = x_sh[k];
            float2 w = __half22float2(Wih0[(size_t)k * 512 + jp]);
            ax += x * w.x; ay += x * w.y;
        }
        part[tid] = make_float2(ax, ay);
        __syncthreads();
        int pb = round & 1;
        if (tid < 64) {
            float2 a0 = part[tid], a1 = part[64 + tid], a2 = part[128 + tid], a3 = part[192 + tid];
            float2 bi = ((const float2*)bih0)[b * 64 + tid];
            float2 bh = ((const float2*)bhh0)[b * 64 + tid];
            float2 g = make_float2(a0.x + a1.x + a2.x + a3.x + bi.x + bh.x,
                                   a0.y + a1.y + a2.y + a3.y + bi.y + bh.y);
            __stcg(&((float2*)&d_gates[pb][0])[b * 64 + tid], g);
        }
        round++;
        __threadfence();
        cluster_bar();
        {
            float gi = __ldcg(&d_gates[pb][tid]);
            float gf = __ldcg(&d_gates[pb][256 + tid]);
            float gg = __ldcg(&d_gates[pb][512 + tid]);
            float go = __ldcg(&d_gates[pb][768 + tid]);
            c1 = sigm(gf) * c1 + sigm(gi) * tanhf(gg);
            h1_sh[tid] = sigm(go) * tanhf(c1);
        }
        __syncthreads();

        // ---- layer 2 gates (x = h1) ----
        ax = 0.f; ay = 0.f;
#pragma unroll 8
        for (int k = kq * 64; k < kq * 64 + 64; ++k) {
            float h2v = h2_sh[k];
            float h1v = h1_sh[k];
            float2 wh = __half22float2(Whh1[(size_t)k * 512 + jp]);
            float2 wi = __half22float2(Wih1[(size_t)k * 512 + jp]);
            ax += h2v * wh.x + h1v * wi.x;
            ay += h2v * wh.y + h1v * wi.y;
        }
        part[tid] = make_float2(ax, ay);
        __syncthreads();
        pb = round & 1;
        if (tid < 64) {
            float2 a0 = part[tid], a1 = part[64 + tid], a2 = part[128 + tid], a3 = part[192 + tid];
            float2 bi = ((const float2*)bih1)[b * 64 + tid];
            float2 bh = ((const float2*)bhh1)[b * 64 + tid];
            float2 g = make_float2(a0.x + a1.x + a2.x + a3.x + bi.x + bh.x,
                                   a0.y + a1.y + a2.y + a3.y + bi.y + bh.y);
            __stcg(&((float2*)&d_gates[pb][0])[b * 64 + tid], g);
        }
        round++;
        __threadfence();
        cluster_bar();
        {
            float gi = __ldcg(&d_gates[pb][tid]);
            float gf = __ldcg(&d_gates[pb][256 + tid]);
            float gg = __ldcg(&d_gates[pb][512 + tid]);
            float go = __ldcg(&d_gates[pb][768 + tid]);
            c2 = sigm(gf) * c2 + sigm(gi) * tanhf(gg);
            h2_sh[tid] = sigm(go) * tanhf(c2);
        }
        __syncthreads();
    }

    if (b == 0 && tid < LL) {
        float a = bhead[tid];
        for (int k = 0; k < HL; ++k)
            a += h2_sh[k] * Whead[k * LL + tid];
        d_zfin[tid] = a;
    }
}

// ---------------- decoder fc: relu(z @ Wfcd + bfcd) -> half [N, L] ----------------
__global__ void fcd_kernel(const float* __restrict__ Wfcd, const float* __restrict__ bfcd,
                           __half2* __restrict__ out) {
    __shared__ float z[LL];
    if (threadIdx.x < LL) z[threadIdx.x] = d_zfin[threadIdx.x];
    __syncthreads();
    int q = blockIdx.x * blockDim.x + threadIdx.x;
    if (q >= NN * LL / 2) return;
    float2 bb = ((const float2*)bfcd)[q];
    float ax = bb.x, ay = bb.y;
#pragma unroll 8
    for (int k = 0; k < LL; ++k) {
        float2 w = ((const float2*)(Wfcd + (size_t)k * (NN * LL)))[q];
        ax += z[k] * w.x;
        ay += z[k] * w.y;
    }
    out[q] = __floats2half2_rn(fmaxf(ax, 0.f), fmaxf(ay, 0.f));
}

// ---------------- launch ----------------
extern "C" void kernel_launch(void* const* d_in, const int* in_sizes, int n_in,
                              void* d_out, int out_size) {
    const float* xs        = (const float*)d_in[0];
    const float* edge_attr = (const float*)d_in[1];
    const float* We0  = (const float*)d_in[2];
    const float* be0  = (const float*)d_in[3];
    const float* We1  = (const float*)d_in[4];
    const float* be1  = (const float*)d_in[5];
    const float* Wfce = (const float*)d_in[6];
    const float* bfce = (const float*)d_in[7];
    const float* Wih0 = (const float*)d_in[8];
    const float* Whh0 = (const float*)d_in[9];
    const float* bih0 = (const float*)d_in[10];
    const float* bhh0 = (const float*)d_in[11];
    const float* Wih1 = (const float*)d_in[12];
    const float* Whh1 = (const float*)d_in[13];
    const float* bih1 = (const float*)d_in[14];
    const float* bhh1 = (const float*)d_in[15];
    const float* Whead = (const float*)d_in[16];
    const float* bhead = (const float*)d_in[17];
    const float* Wfcd = (const float*)d_in[18];
    const float* bfcd = (const float*)d_in[19];
    const float* Wd0  = (const float*)d_in[20];
    const float* bd0  = (const float*)d_in[21];
    const float* Wd1  = (const float*)d_in[22];
    const float* bd1  = (const float*)d_in[23];
    const float* Wd2  = (const float*)d_in[24];
    const float* bd2  = (const float*)d_in[25];
    const void*  eidx = d_in[26];

    float *buf0, *buf1;
    __half *hbuf, *we0h, *we1h, *wd0h, *wd1h, *wd2h, *wih0h, *whh0h, *wih1h, *whh1h;
    cudaGetSymbolAddress((void**)&buf0, d_buf0);
    cudaGetSymbolAddress((void**)&buf1, d_buf1);
    cudaGetSymbolAddress((void**)&hbuf, d_hbuf);
    cudaGetSymbolAddress((void**)&we0h, d_We0h);
    cudaGetSymbolAddress((void**)&we1h, d_We1h);
    cudaGetSymbolAddress((void**)&wd0h, d_Wd0h);
    cudaGetSymbolAddress((void**)&wd1h, d_Wd1h);
    cudaGetSymbolAddress((void**)&wd2h, d_Wd2h);
    cudaGetSymbolAddress((void**)&wih0h, d_Wih0h);
    cudaGetSymbolAddress((void**)&whh0h, d_Whh0h);
    cudaGetSymbolAddress((void**)&wih1h, d_Wih1h);
    cudaGetSymbolAddress((void**)&whh1h, d_Whh1h);

    const int MPAD = 10112;

    // side stream + fork/join events (created once; host-side only)
    static cudaStream_t s2 = [](){ cudaStream_t t; cudaStreamCreateWithFlags(&t, cudaStreamNonBlocking); return t; }();
    static cudaEvent_t evFork = [](){ cudaEvent_t e; cudaEventCreateWithFlags(&e, cudaEventDisableTiming); return e; }();
    static cudaEvent_t evJoin = [](){ cudaEvent_t e; cudaEventCreateWithFlags(&e, cudaEventDisableTiming); return e; }();

    // fork: conversions run concurrently with graph preprocessing
    cudaEventRecord(evFork, 0);
    cudaStreamWaitEvent(s2, evFork, 0);
    f2h_all_kernel<<<(N2_TOT + 255) / 256, 256, 0, s2>>>(
        xs, We0, We1, Wd0, Wd1, Wd2, Wih0, Whh0, Wih1, Whh1,
        (__half2*)hbuf, (__half2*)we0h, (__half2*)we1h,
        (__half2*)wd0h, (__half2*)wd1h, (__half2*)wd2h,
        (__half2*)wih0h, (__half2*)whh0h, (__half2*)wih1h, (__half2*)whh1h);
    cudaEventRecord(evJoin, s2);

    // ---- preprocessing (main stream) ----
    zero_kernel<<<(NN + 255) / 256, 256>>>(eidx);
    count_kernel<<<(EN + 255) / 256, 256>>>(eidx, edge_attr);
    scanA_kernel<<<10, 1024>>>();
    scanB_kernel<<<1, 32>>>();
    scanC_kernel<<<10, 1024>>>();
    fill_kernel<<<(EN + 255) / 256, 256>>>(eidx, edge_attr);

    // join
    cudaStreamWaitEvent(0, evJoin, 0);

    // ---- encoder ----
    agg_enc0_kernel<<<NN, 256>>>((const uint4*)hbuf, (uint4*)buf0);
    hgemm<true, true><<<dim3(TT * NN / 128, HH / 128), 256>>>(
        (const __half*)buf0, we0h, be0, (__half*)buf1, TT * NN, FF, HH);
    hgemm<false, false><<<dim3(TT * NN / 128, HH / 128), 256>>>(
        (const __half*)buf1, we1h, nullptr, hbuf, TT * NN, HH, HH);
    agg_pool_kernel<<<1250, 256>>>((const uint4*)hbuf, be1);
    proj_z_kernel<<<TT, 256>>>(Wfce, bfce);

    // ---- LSTM + head (fp16 weights) ----
    lstm_kernel<<<LSTM_BLOCKS, 256>>>(
        (const __half2*)wih0h, (const __half2*)whh0h, bih0, bhh0,
        (const __half2*)wih1h, (const __half2*)whh1h, bih1, bhh1, Whead, bhead);

    // ---- decoder ----
    fcd_kernel<<<(NN * LL / 2 + 255) / 256, 256>>>(Wfcd, bfcd, (__half2*)hbuf);
    agg_dec_kernel<LL / 2, 4, false, false><<<(NN + 3) / 4, 128>>>(
        (const __half2*)hbuf, (__half*)buf0, nullptr);
    hgemm<true, true><<<dim3(MPAD / 128, HH / 128), 256>>>(
        (const __half*)buf0, wd0h, bd0, (__half*)buf1, MPAD, LL, HH);
    hgemm<false, false><<<dim3(MPAD / 128, HH / 128), 256>>>(
        (const __half*)buf1, wd1h, nullptr, hbuf, MPAD, HH, HH);
    agg_dec_kernel<HH / 2, 2, true, false><<<(NN + 1) / 2, 256>>>(
        (const __half2*)hbuf, (__half*)buf0, bd1);
    hgemm<false, false><<<dim3(MPAD / 128, FF / 128), 256>>>(
        (const __half*)buf0, wd2h, nullptr, (__half*)buf1, MPAD, HH, FF);
    agg_dec_kernel<FF / 2, 2, false, true><<<(NN + 1) / 2, 128>>>(
        (const __half2*)buf1, (float*)d_out, bd2);
}

// round 7
// speedup vs baseline: 2.4835x; 1.0600x over previous
#include <cuda_runtime.h>
#include <cuda_fp16.h>
#include <cuda_fp8.h>
#include <cuda_bf16.h>
#include <math.h>

#define TT 16
#define NN 10000
#define EE 320000
#define EN (EE + NN)
#define FF 128
#define HH 256
#define LL 64
#define HL 256
#define LSTM_BLOCKS 8

// ---------------- device scratch ----------------
__device__ int   d_rowptr[NN + 1];
__device__ int   d_cnt[NN];
__device__ int   d_bsum[10];
__device__ int   d_boff[10];
__device__ int   d_col[EN];
__device__ float d_nrm_enc[EN];
__device__ float d_nrm_dec[EN];
__device__ float d_deg_enc[NN];
__device__ float d_deg_dec[NN];
__device__ float d_dis_enc[NN];
__device__ float d_dis_dec[NN];
__device__ __align__(16) float d_buf0[(size_t)TT * NN * HH];
__device__ __align__(16) float d_buf1[(size_t)TT * NN * HH];
__device__ __align__(16) __half d_hbuf[(size_t)TT * NN * HH];
__device__ __align__(16) unsigned char d_x8[(size_t)TT * NN * FF];   // xs in e4m3
__device__ __align__(16) unsigned char d_h8[(size_t)TT * NN * HH];   // GEMM2 out in e4m3
__device__ __align__(16) __half d_We0h[FF * HH];
__device__ __align__(16) __half d_We1h[HH * HH];
__device__ __align__(16) __half d_Wd0h[LL * HH];
__device__ __align__(16) __half d_Wd1h[HH * HH];
__device__ __align__(16) __half d_Wd2h[HH * FF];
__device__ __align__(16) __half d_Wih0h[LL * 4 * HL];
__device__ __align__(16) __half d_Whh0h[HL * 4 * HL];
__device__ __align__(16) __half d_Wih1h[HL * 4 * HL];
__device__ __align__(16) __half d_Whh1h[HL * 4 * HL];
__device__ float d_gpool[TT * HH];
__device__ float d_zs[TT * LL];
__device__ __align__(16) float d_gates[2][4 * HL];
__device__ float d_zfin[LL];
__device__ int   d_idx64;

__device__ __forceinline__ void get_edge(const void* ei, int e, int& s, int& d) {
    if (d_idx64) {
        const long long* p = (const long long*)ei;
        s = (int)p[e];
        d = (int)p[EE + e];
    } else {
        const int* p = (const int*)ei;
        s = p[e];
        d = p[EE + e];
    }
}

// ---------------- preprocessing ----------------
__global__ void zero_kernel(const void* ei) {
    int i = blockIdx.x * blockDim.x + threadIdx.x;
    if (i < NN) { d_deg_enc[i] = 0.f; d_deg_dec[i] = 0.f; d_cnt[i] = 0; }
    if (i < TT * HH) d_gpool[i] = 0.f;
    if (blockIdx.x == 0 && threadIdx.x == 0) {
        const unsigned int* w = (const unsigned int*)ei;
        int is64 = 1;
        for (int k = 0; k < 64; ++k)
            if (w[2 * k + 1] != 0u) { is64 = 0; break; }
        d_idx64 = is64;
    }
}

__global__ void count_kernel(const void* ei, const float* __restrict__ ea) {
    int e = blockIdx.x * blockDim.x + threadIdx.x;
    if (e >= EN) return;
    int s, d; float w;
    if (e < EE) { get_edge(ei, e, s, d); w = ea[e]; }
    else { s = d = e - EE; w = 1.f; }
    atomicAdd(&d_deg_enc[d], w);
    atomicAdd(&d_deg_dec[d], 1.f);
}

__global__ __launch_bounds__(1024) void scanA_kernel() {
    __shared__ int sh[1024];
    int blk = blockIdx.x, tid = threadIdx.x;
    int idx = blk * 1000 + tid;
    int c = (tid < 1000) ? (int)d_deg_dec[idx] : 0;
    sh[tid] = c;
    __syncthreads();
    for (int off = 1; off < 1024; off <<= 1) {
        int v = (tid >= off) ? sh[tid - off] : 0;
        __syncthreads();
        sh[tid] += v;
        __syncthreads();
    }
    if (tid < 1000) {
        d_rowptr[idx] = sh[tid] - c;
        d_dis_enc[idx] = rsqrtf(d_deg_enc[idx]);
        d_dis_dec[idx] = rsqrtf(d_deg_dec[idx]);
    }
    if (tid == 1023) d_bsum[blk] = sh[1023];
}

__global__ void scanB_kernel() {
    int lane = threadIdx.x;
    int v = (lane < 10) ? d_bsum[lane] : 0;
    int orig = v;
    for (int o = 1; o < 32; o <<= 1) {
        int u = __shfl_up_sync(0xffffffffu, v, o);
        if (lane >= o) v += u;
    }
    if (lane < 10) d_boff[lane] = v - orig;
    if (lane == 31) d_rowptr[NN] = v;
}

__global__ __launch_bounds__(1024) void scanC_kernel() {
    int blk = blockIdx.x, tid = threadIdx.x;
    int idx = blk * 1000 + tid;
    if (tid < 1000) d_rowptr[idx] += d_boff[blk];
}

__global__ void fill_kernel(const void* ei, const float* __restrict__ ea) {
    int e = blockIdx.x * blockDim.x + threadIdx.x;
    if (e >= EN) return;
    int s, d; float w;
    if (e < EE) { get_edge(ei, e, s, d); w = ea[e]; }
    else { s = d = e - EE; w = 1.f; }
    int pos = d_rowptr[d] + atomicAdd(&d_cnt[d], 1);
    d_col[pos] = s;
    d_nrm_enc[pos] = d_dis_enc[s] * w * d_dis_enc[d];
    d_nrm_dec[pos] = d_dis_dec[s] * d_dis_dec[d];
}

// ---------------- fused conversions: xs -> fp8, all weights -> fp16 ----------------
#define N2_XS    (TT * NN * FF / 2)
#define N2_WE0   (FF * HH / 2)
#define N2_WE1   (HH * HH / 2)
#define N2_WD0   (LL * HH / 2)
#define N2_WD1   (HH * HH / 2)
#define N2_WD2   (HH * FF / 2)
#define N2_WIH0  (LL * 4 * HL / 2)
#define N2_WHH0  (HL * 4 * HL / 2)
#define N2_WIH1  (HL * 4 * HL / 2)
#define N2_WHH1  (HL * 4 * HL / 2)
#define N2_TOT   (N2_XS + N2_WE0 + N2_WE1 + N2_WD0 + N2_WD1 + N2_WD2 + \
                  N2_WIH0 + N2_WHH0 + N2_WIH1 + N2_WHH1)

__global__ void f2h_all_kernel(const float* xs, const float* We0, const float* We1,
                               const float* Wd0, const float* Wd1, const float* Wd2,
                               const float* Wih0, const float* Whh0,
                               const float* Wih1, const float* Whh1,
                               unsigned short* hx8, __half2* hwe0, __half2* hwe1,
                               __half2* hwd0, __half2* hwd1, __half2* hwd2,
                               __half2* hwih0, __half2* hwhh0,
                               __half2* hwih1, __half2* hwhh1) {
    int i = blockIdx.x * blockDim.x + threadIdx.x;
    int off = i;
    if (off < N2_XS) {
        float2 v = ((const float2*)xs)[off];
        hx8[off] = __nv_cvt_float2_to_fp8x2(v, __NV_SATFINITE, __NV_E4M3);
        return;
    }
    const float* src; __half2* dst;
    off -= N2_XS;
    if (off < N2_WE0) { src = We0; dst = hwe0; }
    else if ((off -= N2_WE0) < N2_WE1) { src = We1; dst = hwe1; }
    else if ((off -= N2_WE1) < N2_WD0) { src = Wd0; dst = hwd0; }
    else if ((off -= N2_WD0) < N2_WD1) { src = Wd1; dst = hwd1; }
    else if ((off -= N2_WD1) < N2_WD2) { src = Wd2; dst = hwd2; }
    else if ((off -= N2_WD2) < N2_WIH0) { src = Wih0; dst = hwih0; }
    else if ((off -= N2_WIH0) < N2_WHH0) { src = Whh0; dst = hwhh0; }
    else if ((off -= N2_WHH0) < N2_WIH1) { src = Wih1; dst = hwih1; }
    else if ((off -= N2_WIH1) < N2_WHH1) { src = Whh1; dst = hwhh1; }
    else return;
    float2 v = ((const float2*)src)[off];
    dst[off] = __floats2half2_rn(v.x, v.y);
}

// ---------------- fp8 decode helper: 16 e4m3 -> 16 floats ----------------
__device__ __forceinline__ void fp8x16_to_f32(const uint4& v, float* out) {
    const unsigned short* p = (const unsigned short*)&v;
#pragma unroll
    for (int i = 0; i < 8; ++i) {
        __half2_raw hr = __nv_cvt_fp8x2_to_halfraw2((__nv_fp8x2_storage_t)p[i], __NV_E4M3);
        float2 f = __half22float2(*(__half2*)&hr);
        out[2 * i] = f.x;
        out[2 * i + 1] = f.y;
    }
}

// ---------------- encoder layer0 agg: fp8 gathers (16B = 16 feat), fp16 out ----------------
// 128 threads = 16 ts x 8 f4-lanes (128 fp8 per plane = 8 uint4).
__global__ __launch_bounds__(128) void agg_enc0_kernel(const uint4* __restrict__ src,
                                                       __half2* __restrict__ dst) {
    int n = blockIdx.x;
    int tid = threadIdx.x;
    int f4 = tid & 7;
    int ts = tid >> 3;
    int beg = d_rowptr[n], end = d_rowptr[n + 1];
    size_t pb = (size_t)ts * NN * 8;     // uint4 units
    float a[16];
#pragma unroll
    for (int i = 0; i < 16; ++i) a[i] = 0.f;
    int e = beg;
    for (; e + 2 <= end; e += 2) {
        int s0 = __ldg(&d_col[e]);
        int s1 = __ldg(&d_col[e + 1]);
        float w0 = __ldg(&d_nrm_enc[e]);
        float w1 = __ldg(&d_nrm_enc[e + 1]);
        uint4 v0 = __ldg(src + pb + (size_t)s0 * 8 + f4);
        uint4 v1 = __ldg(src + pb + (size_t)s1 * 8 + f4);
        float f0[16], f1[16];
        fp8x16_to_f32(v0, f0);
        fp8x16_to_f32(v1, f1);
#pragma unroll
        for (int i = 0; i < 16; ++i) a[i] += w0 * f0[i] + w1 * f1[i];
    }
    if (e < end) {
        int s = __ldg(&d_col[e]);
        float w = __ldg(&d_nrm_enc[e]);
        uint4 v = __ldg(src + pb + (size_t)s * 8 + f4);
        float f[16];
        fp8x16_to_f32(v, f);
#pragma unroll
        for (int i = 0; i < 16; ++i) a[i] += w * f[i];
    }
    // write 16 halves = 2 uint4
    uint4 o[2];
    __half2* oh = (__half2*)o;
#pragma unroll
    for (int p = 0; p < 8; ++p) oh[p] = __floats2half2_rn(a[2 * p], a[2 * p + 1]);
    uint4* dp = (uint4*)dst + ((size_t)ts * NN + n) * 16 + f4 * 2;
    dp[0] = o[0];
    dp[1] = o[1];
}

// ---------------- agg + bias + relu + mean-pool: fp8 gathers, 8 nodes/block ----------------
// 256 threads = 16 ts x 16 f4-lanes (256 fp8 per plane = 16 uint4).
__global__ __launch_bounds__(256) void agg_pool_kernel(const uint4* __restrict__ src,
                                                       const float* __restrict__ bias) {
    int tid = threadIdx.x;
    int f4 = tid & 15;
    int ts = tid >> 4;
    int n0 = blockIdx.x * 8;
    float b[16];
#pragma unroll
    for (int i = 0; i < 16; ++i) b[i] = bias[f4 * 16 + i];
    float pool[16];
#pragma unroll
    for (int i = 0; i < 16; ++i) pool[i] = 0.f;
    size_t pb = (size_t)ts * NN * 16;    // uint4 units
    for (int n = n0; n < n0 + 8; ++n) {
        int beg = d_rowptr[n], end = d_rowptr[n + 1];
        float acc[16];
#pragma unroll
        for (int i = 0; i < 16; ++i) acc[i] = 0.f;
        int e = beg;
        for (; e + 2 <= end; e += 2) {
            int s0 = __ldg(&d_col[e]);
            int s1 = __ldg(&d_col[e + 1]);
            float w0 = __ldg(&d_nrm_enc[e]);
            float w1 = __ldg(&d_nrm_enc[e + 1]);
            uint4 v0 = __ldg(src + pb + (size_t)s0 * 16 + f4);
            uint4 v1 = __ldg(src + pb + (size_t)s1 * 16 + f4);
            float f0[16], f1[16];
            fp8x16_to_f32(v0, f0);
            fp8x16_to_f32(v1, f1);
#pragma unroll
            for (int i = 0; i < 16; ++i) acc[i] += w0 * f0[i] + w1 * f1[i];
        }
        if (e < end) {
            int s = __ldg(&d_col[e]);
            float w = __ldg(&d_nrm_enc[e]);
            uint4 v = __ldg(src + pb + (size_t)s * 16 + f4);
            float f[16];
            fp8x16_to_f32(v, f);
#pragma unroll
            for (int i = 0; i < 16; ++i) acc[i] += w * f[i];
        }
#pragma unroll
        for (int i = 0; i < 16; ++i) pool[i] += fmaxf(acc[i] + b[i], 0.f);
    }
#pragma unroll
    for (int i = 0; i < 16; ++i)
        atomicAdd(&d_gpool[ts * HH + f4 * 16 + i], pool[i] * (1.0f / NN));
}

// ---------------- decoder CSR aggregation (fp16): NPB nodes per block ----------------
template<int C2, int NPB, bool RELU, bool OUTF>
__global__ void agg_dec_kernel(const __half2* __restrict__ src, void* __restrict__ dstv,
                               const float* __restrict__ bias) {
    int tid = threadIdx.x;
    int n = blockIdx.x * NPB + tid / C2;
    int f2 = tid % C2;
    if (n >= NN) return;
    int beg = d_rowptr[n], end = d_rowptr[n + 1];
    float ax0 = 0.f, ay0 = 0.f, ax1 = 0.f, ay1 = 0.f;
    float ax2 = 0.f, ay2 = 0.f, ax3 = 0.f, ay3 = 0.f;
    int e = beg;
    for (; e + 4 <= end; e += 4) {
        int s0 = __ldg(&d_col[e]);
        int s1 = __ldg(&d_col[e + 1]);
        int s2 = __ldg(&d_col[e + 2]);
        int s3 = __ldg(&d_col[e + 3]);
        float w0 = __ldg(&d_nrm_dec[e]);
        float w1 = __ldg(&d_nrm_dec[e + 1]);
        float w2 = __ldg(&d_nrm_dec[e + 2]);
        float w3 = __ldg(&d_nrm_dec[e + 3]);
        float2 v0 = __half22float2(__ldg(&src[(size_t)s0 * C2 + f2]));
        float2 v1 = __half22float2(__ldg(&src[(size_t)s1 * C2 + f2]));
        float2 v2 = __half22float2(__ldg(&src[(size_t)s2 * C2 + f2]));
        float2 v3 = __half22float2(__ldg(&src[(size_t)s3 * C2 + f2]));
        ax0 += w0 * v0.x; ay0 += w0 * v0.y;
        ax1 += w1 * v1.x; ay1 += w1 * v1.y;
        ax2 += w2 * v2.x; ay2 += w2 * v2.y;
        ax3 += w3 * v3.x; ay3 += w3 * v3.y;
    }
    for (; e < end; ++e) {
        int s = __ldg(&d_col[e]);
        float w = __ldg(&d_nrm_dec[e]);
        float2 v = __half22float2(__ldg(&src[(size_t)s * C2 + f2]));
        ax0 += w * v.x; ay0 += w * v.y;
    }
    float vx = (ax0 + ax1) + (ax2 + ax3);
    float vy = (ay0 + ay1) + (ay2 + ay3);
    if (bias) { vx += bias[2 * f2]; vy += bias[2 * f2 + 1]; }
    if (RELU) { vx = fmaxf(vx, 0.f); vy = fmaxf(vy, 0.f); }
    if (OUTF) {
        ((float2*)dstv)[(size_t)n * C2 + f2] = make_float2(vx, vy);
    } else {
        ((__half2*)dstv)[(size_t)n * C2 + f2] = __floats2half2_rn(vx, vy);
    }
}

// ================= FP16 HMMA GEMM with cp.async pipeline ==========
__device__ __forceinline__ void cp16(void* smem_dst, const void* gsrc) {
    unsigned d = (unsigned)__cvta_generic_to_shared(smem_dst);
    asm volatile("cp.async.cg.shared.global [%0], [%1], 16;" :: "r"(d), "l"(gsrc));
}
__device__ __forceinline__ void cp_commit() { asm volatile("cp.async.commit_group;"); }
__device__ __forceinline__ void cp_wait0() { asm volatile("cp.async.wait_group 0;"); }

__device__ __forceinline__ void ldsm4(unsigned& r0, unsigned& r1, unsigned& r2, unsigned& r3,
                                      const void* p) {
    unsigned a = (unsigned)__cvta_generic_to_shared(p);
    asm volatile("ldmatrix.sync.aligned.m8n8.x4.shared.b16 {%0,%1,%2,%3}, [%4];"
                 : "=r"(r0), "=r"(r1), "=r"(r2), "=r"(r3) : "r"(a));
}
__device__ __forceinline__ void ldsm4t(unsigned& r0, unsigned& r1, unsigned& r2, unsigned& r3,
                                       const void* p) {
    unsigned a = (unsigned)__cvta_generic_to_shared(p);
    asm volatile("ldmatrix.sync.aligned.m8n8.x4.trans.shared.b16 {%0,%1,%2,%3}, [%4];"
                 : "=r"(r0), "=r"(r1), "=r"(r2), "=r"(r3) : "r"(a));
}
__device__ __forceinline__ void mma16816(float* d, const unsigned* a, const unsigned* b) {
    asm volatile(
        "mma.sync.aligned.m16n8k16.row.col.f32.f16.f16.f32 "
        "{%0,%1,%2,%3},{%4,%5,%6,%7},{%8,%9},{%0,%1,%2,%3};\n"
        : "+f"(d[0]), "+f"(d[1]), "+f"(d[2]), "+f"(d[3])
        : "r"(a[0]), "r"(a[1]), "r"(a[2]), "r"(a[3]), "r"(b[0]), "r"(b[1]));
}

// OUTMODE: 0 = half, 1 = e4m3 fp8
template<bool HASBIAS, bool RELU, int OUTMODE>
__global__ __launch_bounds__(256) void hgemm(
    const __half* __restrict__ A, const __half* __restrict__ B,
    const float* __restrict__ bias, void* __restrict__ Cv,
    int M, int K, int Ncols)
{
    __shared__ __align__(16) __half As[2][128][40];
    __shared__ __align__(16) __half Bs[2][32][136];
    int tid = threadIdx.x;
    int bm = blockIdx.x * 128, bn = blockIdx.y * 128;
    int w = tid >> 5, lane = tid & 31;
    int wm = (w >> 2) * 64, wn = (w & 3) * 32;
    int lr16 = lane & 15, lh = lane >> 4;

    float acc[4][4][4];
#pragma unroll
    for (int mi = 0; mi < 4; ++mi)
#pragma unroll
        for (int nj = 0; nj < 4; ++nj)
#pragma unroll
            for (int q = 0; q < 4; ++q) acc[mi][nj][q] = 0.f;

    int ar = tid >> 2, ac = (tid & 3) * 8;
    int br = tid >> 4, bc = (tid & 15) * 8;
    const __half* Ap = A + (size_t)(bm + ar) * K + ac;
    const __half* Bp = B + (size_t)br * Ncols + bn + bc;

    cp16(&As[0][ar][ac], Ap);
    cp16(&As[0][ar + 64][ac], Ap + (size_t)64 * K);
    cp16(&Bs[0][br][bc], Bp);
    cp16(&Bs[0][br + 16][bc], Bp + (size_t)16 * Ncols);
    cp_commit();

    int nstage = K >> 5;
    for (int s = 0; s < nstage; ++s) {
        int cur = s & 1;
        cp_wait0();
        __syncthreads();
        if (s + 1 < nstage) {
            int k0 = (s + 1) << 5;
            int nxt = cur ^ 1;
            cp16(&As[nxt][ar][ac], Ap + k0);
            cp16(&As[nxt][ar + 64][ac], Ap + (size_t)64 * K + k0);
            cp16(&Bs[nxt][br][bc], Bp + (size_t)k0 * Ncols);
            cp16(&Bs[nxt][br + 16][bc], Bp + (size_t)(k0 + 16) * Ncols);
            cp_commit();
        }
#pragma unroll
        for (int k16 = 0; k16 < 2; ++k16) {
            unsigned af[4][4], bf[4][2];
#pragma unroll
            for (int mi = 0; mi < 4; ++mi)
                ldsm4(af[mi][0], af[mi][1], af[mi][2], af[mi][3],
                      &As[cur][wm + mi * 16 + lr16][k16 * 16 + lh * 8]);
#pragma unroll
            for (int p = 0; p < 2; ++p) {
                unsigned r0, r1, r2, r3;
                ldsm4t(r0, r1, r2, r3, &Bs[cur][k16 * 16 + lr16][wn + p * 16 + lh * 8]);
                bf[2 * p][0] = r0; bf[2 * p][1] = r1;
                bf[2 * p + 1][0] = r2; bf[2 * p + 1][1] = r3;
            }
#pragma unroll
            for (int mi = 0; mi < 4; ++mi)
#pragma unroll
                for (int nj = 0; nj < 4; ++nj)
                    mma16816(acc[mi][nj], af[mi], bf[nj]);
        }
        __syncthreads();
    }

    int lr = lane >> 2, lc = lane & 3;
#pragma unroll
    for (int mi = 0; mi < 4; ++mi) {
#pragma unroll
        for (int nj = 0; nj < 4; ++nj) {
            int row = bm + wm + mi * 16 + lr;
            int col = bn + wn + nj * 8 + 2 * lc;
            float b0 = 0.f, b1 = 0.f;
            if (HASBIAS) { b0 = bias[col]; b1 = bias[col + 1]; }
            float v0 = acc[mi][nj][0] + b0, v1 = acc[mi][nj][1] + b1;
            float v2 = acc[mi][nj][2] + b0, v3 = acc[mi][nj][3] + b1;
            if (RELU) {
                v0 = fmaxf(v0, 0.f); v1 = fmaxf(v1, 0.f);
                v2 = fmaxf(v2, 0.f); v3 = fmaxf(v3, 0.f);
            }
            if (OUTMODE == 0) {
                __half* C = (__half*)Cv;
                *(__half2*)(C + (size_t)row * Ncols + col) = __floats2half2_rn(v0, v1);
                *(__half2*)(C + (size_t)(row + 8) * Ncols + col) = __floats2half2_rn(v2, v3);
            } else {
                unsigned char* C8 = (unsigned char*)Cv;
                *(unsigned short*)(C8 + (size_t)row * Ncols + col) =
                    __nv_cvt_float2_to_fp8x2(make_float2(v0, v1), __NV_SATFINITE, __NV_E4M3);
                *(unsigned short*)(C8 + (size_t)(row + 8) * Ncols + col) =
                    __nv_cvt_float2_to_fp8x2(make_float2(v2, v3), __NV_SATFINITE, __NV_E4M3);
            }
        }
    }
}

// ---------------- z_t = g_t @ Wfce + bfce ----------------
__global__ __launch_bounds__(256) void proj_z_kernel(const float* __restrict__ Wfce,
                                                     const float* __restrict__ bfce) {
    __shared__ float part[256];
    int t = blockIdx.x;
    int tid = threadIdx.x;
    int j = tid & 63;
    int kq = tid >> 6;
    float a = 0.f;
#pragma unroll 8
    for (int k = kq * 64; k < kq * 64 + 64; ++k)
        a += d_gpool[t * HH + k] * __ldg(&Wfce[k * LL + j]);
    part[tid] = a;
    __syncthreads();
    if (tid < 64)
        d_zs[t * LL + tid] = part[tid] + part[64 + tid] + part[128 + tid] + part[192 + tid]
                             + bfce[tid];
}

// ---------------- persistent 2-layer LSTM + head (cluster of 8 CTAs, fp16 weights) ----------------
__device__ __forceinline__ float sigm(float x) { return 1.f / (1.f + expf(-x)); }

__device__ __forceinline__ void cluster_bar() {
    asm volatile("barrier.cluster.arrive.aligned;" ::: "memory");
    asm volatile("barrier.cluster.wait.aligned;" ::: "memory");
}

__global__ __launch_bounds__(256) __cluster_dims__(LSTM_BLOCKS, 1, 1) void lstm_kernel(
    const __half2* __restrict__ Wih0, const __half2* __restrict__ Whh0,
    const float* __restrict__ bih0, const float* __restrict__ bhh0,
    const __half2* __restrict__ Wih1, const __half2* __restrict__ Whh1,
    const float* __restrict__ bih1, const float* __restrict__ bhh1,
    const float* __restrict__ Whead, const float* __restrict__ bhead)
{
    __shared__ float x_sh[LL];
    __shared__ float h1_sh[HL];
    __shared__ float h2_sh[HL];
    __shared__ float2 part[256];
    int tid = threadIdx.x;
    int b = blockIdx.x;
    int p = tid & 63;
    int kq = tid >> 6;
    int jp = b * 64 + p;
    float c1 = 0.f, c2 = 0.f;
    if (tid < HL) { h1_sh[tid] = 0.f; h2_sh[tid] = 0.f; }
    __syncthreads();
    int round = 0;

    for (int t = 0; t < TT; ++t) {
        if (tid < LL) x_sh[tid] = d_zs[t * LL + tid];
        __syncthreads();

        float ax = 0.f, ay = 0.f;
#pragma unroll 8
        for (int k = kq * 64; k < kq * 64 + 64; ++k) {
            float h = h1_sh[k];
            float2 w = __half22float2(Whh0[(size_t)k * 512 + jp]);
            ax += h * w.x; ay += h * w.y;
        }
#pragma unroll 8
        for (int k = kq * 16; k < kq * 16 + 16; ++k) {
            float x = x_sh[k];
            float2 w = __half22float2(Wih0[(size_t)k * 512 + jp]);
            ax += x * w.x; ay += x * w.y;
        }
        part[tid] = make_float2(ax, ay);
        __syncthreads();
        int pb = round & 1;
        if (tid < 64) {
            float2 a0 = part[tid], a1 = part[64 + tid], a2 = part[128 + tid], a3 = part[192 + tid];
            float2 bi = ((const float2*)bih0)[b * 64 + tid];
            float2 bh = ((const float2*)bhh0)[b * 64 + tid];
            float2 g = make_float2(a0.x + a1.x + a2.x + a3.x + bi.x + bh.x,
                                   a0.y + a1.y + a2.y + a3.y + bi.y + bh.y);
            __stcg(&((float2*)&d_gates[pb][0])[b * 64 + tid], g);
        }
        round++;
        __threadfence();
        cluster_bar();
        {
            float gi = __ldcg(&d_gates[pb][tid]);
            float gf = __ldcg(&d_gates[pb][256 + tid]);
            float gg = __ldcg(&d_gates[pb][512 + tid]);
            float go = __ldcg(&d_gates[pb][768 + tid]);
            c1 = sigm(gf) * c1 + sigm(gi) * tanhf(gg);
            h1_sh[tid] = sigm(go) * tanhf(c1);
        }
        __syncthreads();

        ax = 0.f; ay = 0.f;
#pragma unroll 8
        for (int k = kq * 64; k < kq * 64 + 64; ++k) {
            float h2v = h2_sh[k];
            float h1v = h1_sh[k];
            float2 wh = __half22float2(Whh1[(size_t)k * 512 + jp]);
            float2 wi = __half22float2(Wih1[(size_t)k * 512 + jp]);
            ax += h2v * wh.x + h1v * wi.x;
            ay += h2v * wh.y + h1v * wi.y;
        }
        part[tid] = make_float2(ax, ay);
        __syncthreads();
        pb = round & 1;
        if (tid < 64) {
            float2 a0 = part[tid], a1 = part[64 + tid], a2 = part[128 + tid], a3 = part[192 + tid];
            float2 bi = ((const float2*)bih1)[b * 64 + tid];
            float2 bh = ((const float2*)bhh1)[b * 64 + tid];
            float2 g = make_float2(a0.x + a1.x + a2.x + a3.x + bi.x + bh.x,
                                   a0.y + a1.y + a2.y + a3.y + bi.y + bh.y);
            __stcg(&((float2*)&d_gates[pb][0])[b * 64 + tid], g);
        }
        round++;
        __threadfence();
        cluster_bar();
        {
            float gi = __ldcg(&d_gates[pb][tid]);
            float gf = __ldcg(&d_gates[pb][256 + tid]);
            float gg = __ldcg(&d_gates[pb][512 + tid]);
            float go = __ldcg(&d_gates[pb][768 + tid]);
            c2 = sigm(gf) * c2 + sigm(gi) * tanhf(gg);
            h2_sh[tid] = sigm(go) * tanhf(c2);
        }
        __syncthreads();
    }

    if (b == 0 && tid < LL) {
        float a = bhead[tid];
        for (int k = 0; k < HL; ++k)
            a += h2_sh[k] * Whead[k * LL + tid];
        d_zfin[tid] = a;
    }
}

// ---------------- decoder fc: relu(z @ Wfcd + bfcd) -> half [N, L] ----------------
__global__ void fcd_kernel(const float* __restrict__ Wfcd, const float* __restrict__ bfcd,
                           __half2* __restrict__ out) {
    __shared__ float z[LL];
    if (threadIdx.x < LL) z[threadIdx.x] = d_zfin[threadIdx.x];
    __syncthreads();
    int q = blockIdx.x * blockDim.x + threadIdx.x;
    if (q >= NN * LL / 2) return;
    float2 bb = ((const float2*)bfcd)[q];
    float ax = bb.x, ay = bb.y;
#pragma unroll 8
    for (int k = 0; k < LL; ++k) {
        float2 w = ((const float2*)(Wfcd + (size_t)k * (NN * LL)))[q];
        ax += z[k] * w.x;
        ay += z[k] * w.y;
    }
    out[q] = __floats2half2_rn(fmaxf(ax, 0.f), fmaxf(ay, 0.f));
}

// ---------------- launch ----------------
extern "C" void kernel_launch(void* const* d_in, const int* in_sizes, int n_in,
                              void* d_out, int out_size) {
    const float* xs        = (const float*)d_in[0];
    const float* edge_attr = (const float*)d_in[1];
    const float* We0  = (const float*)d_in[2];
    const float* be0  = (const float*)d_in[3];
    const float* We1  = (const float*)d_in[4];
    const float* be1  = (const float*)d_in[5];
    const float* Wfce = (const float*)d_in[6];
    const float* bfce = (const float*)d_in[7];
    const float* Wih0 = (const float*)d_in[8];
    const float* Whh0 = (const float*)d_in[9];
    const float* bih0 = (const float*)d_in[10];
    const float* bhh0 = (const float*)d_in[11];
    const float* Wih1 = (const float*)d_in[12];
    const float* Whh1 = (const float*)d_in[13];
    const float* bih1 = (const float*)d_in[14];
    const float* bhh1 = (const float*)d_in[15];
    const float* Whead = (const float*)d_in[16];
    const float* bhead = (const float*)d_in[17];
    const float* Wfcd = (const float*)d_in[18];
    const float* bfcd = (const float*)d_in[19];
    const float* Wd0  = (const float*)d_in[20];
    const float* bd0  = (const float*)d_in[21];
    const float* Wd1  = (const float*)d_in[22];
    const float* bd1  = (const float*)d_in[23];
    const float* Wd2  = (const float*)d_in[24];
    const float* bd2  = (const float*)d_in[25];
    const void*  eidx = d_in[26];

    float *buf0, *buf1;
    __half *hbuf, *we0h, *we1h, *wd0h, *wd1h, *wd2h, *wih0h, *whh0h, *wih1h, *whh1h;
    unsigned char *x8, *h8;
    cudaGetSymbolAddress((void**)&buf0, d_buf0);
    cudaGetSymbolAddress((void**)&buf1, d_buf1);
    cudaGetSymbolAddress((void**)&hbuf, d_hbuf);
    cudaGetSymbolAddress((void**)&x8, d_x8);
    cudaGetSymbolAddress((void**)&h8, d_h8);
    cudaGetSymbolAddress((void**)&we0h, d_We0h);
    cudaGetSymbolAddress((void**)&we1h, d_We1h);
    cudaGetSymbolAddress((void**)&wd0h, d_Wd0h);
    cudaGetSymbolAddress((void**)&wd1h, d_Wd1h);
    cudaGetSymbolAddress((void**)&wd2h, d_Wd2h);
    cudaGetSymbolAddress((void**)&wih0h, d_Wih0h);
    cudaGetSymbolAddress((void**)&whh0h, d_Whh0h);
    cudaGetSymbolAddress((void**)&wih1h, d_Wih1h);
    cudaGetSymbolAddress((void**)&whh1h, d_Whh1h);

    const int MPAD = 10112;

    static cudaStream_t s2 = [](){ cudaStream_t t; cudaStreamCreateWithFlags(&t, cudaStreamNonBlocking); return t; }();
    static cudaEvent_t evFork = [](){ cudaEvent_t e; cudaEventCreateWithFlags(&e, cudaEventDisableTiming); return e; }();
    static cudaEvent_t evJoin = [](){ cudaEvent_t e; cudaEventCreateWithFlags(&e, cudaEventDisableTiming); return e; }();

    cudaEventRecord(evFork, 0);
    cudaStreamWaitEvent(s2, evFork, 0);
    f2h_all_kernel<<<(N2_TOT + 255) / 256, 256, 0, s2>>>(
        xs, We0, We1, Wd0, Wd1, Wd2, Wih0, Whh0, Wih1, Whh1,
        (unsigned short*)x8, (__half2*)we0h, (__half2*)we1h,
        (__half2*)wd0h, (__half2*)wd1h, (__half2*)wd2h,
        (__half2*)wih0h, (__half2*)whh0h, (__half2*)wih1h, (__half2*)whh1h);
    cudaEventRecord(evJoin, s2);

    // ---- preprocessing (main stream) ----
    zero_kernel<<<(NN + 255) / 256, 256>>>(eidx);
    count_kernel<<<(EN + 255) / 256, 256>>>(eidx, edge_attr);
    scanA_kernel<<<10, 1024>>>();
    scanB_kernel<<<1, 32>>>();
    scanC_kernel<<<10, 1024>>>();
    fill_kernel<<<(EN + 255) / 256, 256>>>(eidx, edge_attr);

    cudaStreamWaitEvent(0, evJoin, 0);

    // ---- encoder (fp8 gathers) ----
    agg_enc0_kernel<<<NN, 128>>>((const uint4*)x8, (__half2*)buf0);
    hgemm<true, true, 0><<<dim3(TT * NN / 128, HH / 128), 256>>>(
        (const __half*)buf0, we0h, be0, buf1, TT * NN, FF, HH);
    hgemm<false, false, 1><<<dim3(TT * NN / 128, HH / 128), 256>>>(
        (const __half*)buf1, we1h, nullptr, h8, TT * NN, HH, HH);
    agg_pool_kernel<<<1250, 256>>>((const uint4*)h8, be1);
    proj_z_kernel<<<TT, 256>>>(Wfce, bfce);

    // ---- LSTM + head ----
    lstm_kernel<<<LSTM_BLOCKS, 256>>>(
        (const __half2*)wih0h, (const __half2*)whh0h, bih0, bhh0,
        (const __half2*)wih1h, (const __half2*)whh1h, bih1, bhh1, Whead, bhead);

    // ---- decoder (fp16) ----
    fcd_kernel<<<(NN * LL / 2 + 255) / 256, 256>>>(Wfcd, bfcd, (__half2*)hbuf);
    agg_dec_kernel<LL / 2, 4, false, false><<<(NN + 3) / 4, 128>>>(
        (const __half2*)hbuf, (__half*)buf0, nullptr);
    hgemm<true, true, 0><<<dim3(MPAD / 128, HH / 128), 256>>>(
        (const __half*)buf0, wd0h, bd0, buf1, MPAD, LL, HH);
    hgemm<false, false, 0><<<dim3(MPAD / 128, HH / 128), 256>>>(
        (const __half*)buf1, wd1h, nullptr, hbuf, MPAD, HH, HH);
    agg_dec_kernel<HH / 2, 2, true, false><<<(NN + 1) / 2, 256>>>(
        (const __half2*)hbuf, (__half*)buf0, bd1);
    hgemm<false, false, 0><<<dim3(MPAD / 128, FF / 128), 256>>>(
        (const __half*)buf0, wd2h, nullptr, buf1, MPAD, HH, FF);
    agg_dec_kernel<FF / 2, 2, false, true><<<(NN + 1) / 2, 128>>>(
        (const __half2*)buf1, (float*)d_out, bd2);
}

// round 8
// speedup vs baseline: 2.7316x; 1.0999x over previous
#include <cuda_runtime.h>
#include <cuda_fp16.h>
#include <cuda_fp8.h>
#include <cuda_bf16.h>
#include <math.h>

#define TT 16
#define NN 10000
#define EE 320000
#define EN (EE + NN)
#define FF 128
#define HH 256
#define LL 64
#define HL 256
#define LSTM_BLOCKS 8

// ---------------- device scratch ----------------
__device__ int   d_rowptr[NN + 1];
__device__ int   d_cnt[NN];
__device__ int   d_bsum[10];
__device__ int   d_boff[10];
__device__ int   d_col[EN];
__device__ float d_nrm_enc[EN];
__device__ float d_nrm_dec[EN];
__device__ float d_deg_enc[NN];
__device__ float d_deg_dec[NN];
__device__ float d_dis_enc[NN];
__device__ float d_dis_dec[NN];
__device__ __align__(16) float d_buf0[(size_t)TT * NN * HH];
__device__ __align__(16) float d_buf1[(size_t)TT * NN * HH];
__device__ __align__(16) __half d_hbuf[(size_t)TT * NN * HH];
__device__ __align__(16) unsigned char d_x8[(size_t)TT * NN * FF];   // xs in e4m3
__device__ __align__(16) unsigned char d_h8[(size_t)TT * NN * HH];   // GEMM2 out in e4m3
__device__ __align__(16) __half d_We0h[FF * HH];
__device__ __align__(16) __half d_We1h[HH * HH];
__device__ __align__(16) __half d_Wd0h[LL * HH];
__device__ __align__(16) __half d_Wd1h[HH * HH];
__device__ __align__(16) __half d_Wd2h[HH * FF];
__device__ __align__(16) __half d_Wih0h[LL * 4 * HL];
__device__ __align__(16) __half d_Whh0h[HL * 4 * HL];
__device__ __align__(16) __half d_Wih1h[HL * 4 * HL];
__device__ __align__(16) __half d_Whh1h[HL * 4 * HL];
__device__ float d_gpool[TT * HH];
__device__ float d_zs[TT * LL];
__device__ __align__(16) float d_gates[2][4 * HL];
__device__ float d_zfin[LL];
__device__ int   d_idx64;

__device__ __forceinline__ void get_edge(const void* ei, int e, int& s, int& d) {
    if (d_idx64) {
        const long long* p = (const long long*)ei;
        s = (int)p[e];
        d = (int)p[EE + e];
    } else {
        const int* p = (const int*)ei;
        s = p[e];
        d = p[EE + e];
    }
}

// ---------------- preprocessing ----------------
__global__ void zero_kernel(const void* ei) {
    int i = blockIdx.x * blockDim.x + threadIdx.x;
    if (i < NN) { d_deg_enc[i] = 0.f; d_deg_dec[i] = 0.f; d_cnt[i] = 0; }
    if (i < TT * HH) d_gpool[i] = 0.f;
    if (blockIdx.x == 0 && threadIdx.x == 0) {
        const unsigned int* w = (const unsigned int*)ei;
        int is64 = 1;
        for (int k = 0; k < 64; ++k)
            if (w[2 * k + 1] != 0u) { is64 = 0; break; }
        d_idx64 = is64;
    }
}

__global__ void count_kernel(const void* ei, const float* __restrict__ ea) {
    int e = blockIdx.x * blockDim.x + threadIdx.x;
    if (e >= EN) return;
    int s, d; float w;
    if (e < EE) { get_edge(ei, e, s, d); w = ea[e]; }
    else { s = d = e - EE; w = 1.f; }
    atomicAdd(&d_deg_enc[d], w);
    atomicAdd(&d_deg_dec[d], 1.f);
}

__global__ __launch_bounds__(1024) void scanA_kernel() {
    __shared__ int sh[1024];
    int blk = blockIdx.x, tid = threadIdx.x;
    int idx = blk * 1000 + tid;
    int c = (tid < 1000) ? (int)d_deg_dec[idx] : 0;
    sh[tid] = c;
    __syncthreads();
    for (int off = 1; off < 1024; off <<= 1) {
        int v = (tid >= off) ? sh[tid - off] : 0;
        __syncthreads();
        sh[tid] += v;
        __syncthreads();
    }
    if (tid < 1000) {
        d_rowptr[idx] = sh[tid] - c;
        d_dis_enc[idx] = rsqrtf(d_deg_enc[idx]);
        d_dis_dec[idx] = rsqrtf(d_deg_dec[idx]);
    }
    if (tid == 1023) d_bsum[blk] = sh[1023];
}

__global__ void scanB_kernel() {
    int lane = threadIdx.x;
    int v = (lane < 10) ? d_bsum[lane] : 0;
    int orig = v;
    for (int o = 1; o < 32; o <<= 1) {
        int u = __shfl_up_sync(0xffffffffu, v, o);
        if (lane >= o) v += u;
    }
    if (lane < 10) d_boff[lane] = v - orig;
    if (lane == 31) d_rowptr[NN] = v;
}

__global__ __launch_bounds__(1024) void scanC_kernel() {
    int blk = blockIdx.x, tid = threadIdx.x;
    int idx = blk * 1000 + tid;
    if (tid < 1000) d_rowptr[idx] += d_boff[blk];
}

__global__ void fill_kernel(const void* ei, const float* __restrict__ ea) {
    int e = blockIdx.x * blockDim.x + threadIdx.x;
    if (e >= EN) return;
    int s, d; float w;
    if (e < EE) { get_edge(ei, e, s, d); w = ea[e]; }
    else { s = d = e - EE; w = 1.f; }
    int pos = d_rowptr[d] + atomicAdd(&d_cnt[d], 1);
    d_col[pos] = s;
    d_nrm_enc[pos] = d_dis_enc[s] * w * d_dis_enc[d];
    d_nrm_dec[pos] = d_dis_dec[s] * d_dis_dec[d];
}

// ---------------- fused conversions: xs -> fp8, all weights -> fp16 ----------------
#define N2_XS    (TT * NN * FF / 2)
#define N2_WE0   (FF * HH / 2)
#define N2_WE1   (HH * HH / 2)
#define N2_WD0   (LL * HH / 2)
#define N2_WD1   (HH * HH / 2)
#define N2_WD2   (HH * FF / 2)
#define N2_WIH0  (LL * 4 * HL / 2)
#define N2_WHH0  (HL * 4 * HL / 2)
#define N2_WIH1  (HL * 4 * HL / 2)
#define N2_WHH1  (HL * 4 * HL / 2)
#define N2_TOT   (N2_XS + N2_WE0 + N2_WE1 + N2_WD0 + N2_WD1 + N2_WD2 + \
                  N2_WIH0 + N2_WHH0 + N2_WIH1 + N2_WHH1)

__global__ void f2h_all_kernel(const float* xs, const float* We0, const float* We1,
                               const float* Wd0, const float* Wd1, const float* Wd2,
                               const float* Wih0, const float* Whh0,
                               const float* Wih1, const float* Whh1,
                               unsigned short* hx8, __half2* hwe0, __half2* hwe1,
                               __half2* hwd0, __half2* hwd1, __half2* hwd2,
                               __half2* hwih0, __half2* hwhh0,
                               __half2* hwih1, __half2* hwhh1) {
    int i = blockIdx.x * blockDim.x + threadIdx.x;
    int off = i;
    if (off < N2_XS) {
        float2 v = ((const float2*)xs)[off];
        hx8[off] = __nv_cvt_float2_to_fp8x2(v, __NV_SATFINITE, __NV_E4M3);
        return;
    }
    const float* src; __half2* dst;
    off -= N2_XS;
    if (off < N2_WE0) { src = We0; dst = hwe0; }
    else if ((off -= N2_WE0) < N2_WE1) { src = We1; dst = hwe1; }
    else if ((off -= N2_WE1) < N2_WD0) { src = Wd0; dst = hwd0; }
    else if ((off -= N2_WD0) < N2_WD1) { src = Wd1; dst = hwd1; }
    else if ((off -= N2_WD1) < N2_WD2) { src = Wd2; dst = hwd2; }
    else if ((off -= N2_WD2) < N2_WIH0) { src = Wih0; dst = hwih0; }
    else if ((off -= N2_WIH0) < N2_WHH0) { src = Whh0; dst = hwhh0; }
    else if ((off -= N2_WHH0) < N2_WIH1) { src = Wih1; dst = hwih1; }
    else if ((off -= N2_WIH1) < N2_WHH1) { src = Whh1; dst = hwhh1; }
    else return;
    float2 v = ((const float2*)src)[off];
    dst[off] = __floats2half2_rn(v.x, v.y);
}

// ---------------- fp8x2 -> half2 ----------------
__device__ __forceinline__ __half2 fp8x2_h2(unsigned short s) {
    __half2_raw hr = __nv_cvt_fp8x2_to_halfraw2((__nv_fp8x2_storage_t)s, __NV_E4M3);
    return *(__half2*)&hr;
}

// ---------------- encoder layer0 agg: fp8 gathers, HFMA2 accumulate, half2 out ----------------
// 128 threads = 16 ts x 8 f4-lanes (128 fp8 per plane = 8 uint4).
__global__ __launch_bounds__(128) void agg_enc0_kernel(const uint4* __restrict__ src,
                                                       uint4* __restrict__ dst) {
    int n = blockIdx.x;
    int tid = threadIdx.x;
    int f4 = tid & 7;
    int ts = tid >> 3;
    int beg = d_rowptr[n], end = d_rowptr[n + 1];
    size_t pb = (size_t)ts * NN * 8;     // uint4 units
    __half2 acc[8];
#pragma unroll
    for (int i = 0; i < 8; ++i) acc[i] = __floats2half2_rn(0.f, 0.f);
    int e = beg;
    for (; e + 2 <= end; e += 2) {
        int s0 = __ldg(&d_col[e]);
        int s1 = __ldg(&d_col[e + 1]);
        float w0 = __ldg(&d_nrm_enc[e]);
        float w1 = __ldg(&d_nrm_enc[e + 1]);
        __half2 w02 = __floats2half2_rn(w0, w0);
        __half2 w12 = __floats2half2_rn(w1, w1);
        uint4 v0 = __ldg(src + pb + (size_t)s0 * 8 + f4);
        uint4 v1 = __ldg(src + pb + (size_t)s1 * 8 + f4);
        const unsigned short* p0 = (const unsigned short*)&v0;
        const unsigned short* p1 = (const unsigned short*)&v1;
#pragma unroll
        for (int p = 0; p < 8; ++p) {
            acc[p] = __hfma2(fp8x2_h2(p0[p]), w02, acc[p]);
            acc[p] = __hfma2(fp8x2_h2(p1[p]), w12, acc[p]);
        }
    }
    if (e < end) {
        int s = __ldg(&d_col[e]);
        float w = __ldg(&d_nrm_enc[e]);
        __half2 w2 = __floats2half2_rn(w, w);
        uint4 v = __ldg(src + pb + (size_t)s * 8 + f4);
        const unsigned short* p = (const unsigned short*)&v;
#pragma unroll
        for (int q = 0; q < 8; ++q)
            acc[q] = __hfma2(fp8x2_h2(p[q]), w2, acc[q]);
    }
    // acc already half2 = GEMM input dtype: write 2 uint4
    uint4 o[2];
    __half2* oh = (__half2*)o;
#pragma unroll
    for (int p = 0; p < 8; ++p) oh[p] = acc[p];
    uint4* dp = dst + ((size_t)ts * NN + n) * 16 + f4 * 2;
    dp[0] = o[0];
    dp[1] = o[1];
}

// ---------------- agg + bias + relu + mean-pool: fp8 gathers, HFMA2, 8 nodes/block ----------------
// 256 threads = 16 ts x 16 f4-lanes (256 fp8 per plane = 16 uint4).
__global__ __launch_bounds__(256) void agg_pool_kernel(const uint4* __restrict__ src,
                                                       const float* __restrict__ bias) {
    int tid = threadIdx.x;
    int f4 = tid & 15;
    int ts = tid >> 4;
    int n0 = blockIdx.x * 8;
    float b[16];
#pragma unroll
    for (int i = 0; i < 16; ++i) b[i] = bias[f4 * 16 + i];
    float pool[16];
#pragma unroll
    for (int i = 0; i < 16; ++i) pool[i] = 0.f;
    size_t pb = (size_t)ts * NN * 16;    // uint4 units
    for (int n = n0; n < n0 + 8; ++n) {
        int beg = d_rowptr[n], end = d_rowptr[n + 1];
        __half2 acc[8];
#pragma unroll
        for (int i = 0; i < 8; ++i) acc[i] = __floats2half2_rn(0.f, 0.f);
        int e = beg;
        for (; e + 2 <= end; e += 2) {
            int s0 = __ldg(&d_col[e]);
            int s1 = __ldg(&d_col[e + 1]);
            float w0 = __ldg(&d_nrm_enc[e]);
            float w1 = __ldg(&d_nrm_enc[e + 1]);
            __half2 w02 = __floats2half2_rn(w0, w0);
            __half2 w12 = __floats2half2_rn(w1, w1);
            uint4 v0 = __ldg(src + pb + (size_t)s0 * 16 + f4);
            uint4 v1 = __ldg(src + pb + (size_t)s1 * 16 + f4);
            const unsigned short* p0 = (const unsigned short*)&v0;
            const unsigned short* p1 = (const unsigned short*)&v1;
#pragma unroll
            for (int p = 0; p < 8; ++p) {
                acc[p] = __hfma2(fp8x2_h2(p0[p]), w02, acc[p]);
                acc[p] = __hfma2(fp8x2_h2(p1[p]), w12, acc[p]);
            }
        }
        if (e < end) {
            int s = __ldg(&d_col[e]);
            float w = __ldg(&d_nrm_enc[e]);
            __half2 w2 = __floats2half2_rn(w, w);
            uint4 v = __ldg(src + pb + (size_t)s * 16 + f4);
            const unsigned short* p = (const unsigned short*)&v;
#pragma unroll
            for (int q = 0; q < 8; ++q)
                acc[q] = __hfma2(fp8x2_h2(p[q]), w2, acc[q]);
        }
#pragma unroll
        for (int i = 0; i < 8; ++i) {
            float2 f = __half22float2(acc[i]);
            pool[2 * i]     += fmaxf(f.x + b[2 * i], 0.f);
            pool[2 * i + 1] += fmaxf(f.y + b[2 * i + 1], 0.f);
        }
    }
#pragma unroll
    for (int i = 0; i < 16; ++i)
        atomicAdd(&d_gpool[ts * HH + f4 * 16 + i], pool[i] * (1.0f / NN));
}

// ---------------- decoder CSR aggregation (fp16 src, fp32 accum): NPB nodes per block ----------------
template<int C2, int NPB, bool RELU, bool OUTF>
__global__ void agg_dec_kernel(const __half2* __restrict__ src, void* __restrict__ dstv,
                               const float* __restrict__ bias) {
    int tid = threadIdx.x;
    int n = blockIdx.x * NPB + tid / C2;
    int f2 = tid % C2;
    if (n >= NN) return;
    int beg = d_rowptr[n], end = d_rowptr[n + 1];
    float ax0 = 0.f, ay0 = 0.f, ax1 = 0.f, ay1 = 0.f;
    float ax2 = 0.f, ay2 = 0.f, ax3 = 0.f, ay3 = 0.f;
    int e = beg;
    for (; e + 4 <= end; e += 4) {
        int s0 = __ldg(&d_col[e]);
        int s1 = __ldg(&d_col[e + 1]);
        int s2 = __ldg(&d_col[e + 2]);
        int s3 = __ldg(&d_col[e + 3]);
        float w0 = __ldg(&d_nrm_dec[e]);
        float w1 = __ldg(&d_nrm_dec[e + 1]);
        float w2 = __ldg(&d_nrm_dec[e + 2]);
        float w3 = __ldg(&d_nrm_dec[e + 3]);
        float2 v0 = __half22float2(__ldg(&src[(size_t)s0 * C2 + f2]));
        float2 v1 = __half22float2(__ldg(&src[(size_t)s1 * C2 + f2]));
        float2 v2 = __half22float2(__ldg(&src[(size_t)s2 * C2 + f2]));
        float2 v3 = __half22float2(__ldg(&src[(size_t)s3 * C2 + f2]));
        ax0 += w0 * v0.x; ay0 += w0 * v0.y;
        ax1 += w1 * v1.x; ay1 += w1 * v1.y;
        ax2 += w2 * v2.x; ay2 += w2 * v2.y;
        ax3 += w3 * v3.x; ay3 += w3 * v3.y;
    }
    for (; e < end; ++e) {
        int s = __ldg(&d_col[e]);
        float w = __ldg(&d_nrm_dec[e]);
        float2 v = __half22float2(__ldg(&src[(size_t)s * C2 + f2]));
        ax0 += w * v.x; ay0 += w * v.y;
    }
    float vx = (ax0 + ax1) + (ax2 + ax3);
    float vy = (ay0 + ay1) + (ay2 + ay3);
    if (bias) { vx += bias[2 * f2]; vy += bias[2 * f2 + 1]; }
    if (RELU) { vx = fmaxf(vx, 0.f); vy = fmaxf(vy, 0.f); }
    if (OUTF) {
        ((float2*)dstv)[(size_t)n * C2 + f2] = make_float2(vx, vy);
    } else {
        ((__half2*)dstv)[(size_t)n * C2 + f2] = __floats2half2_rn(vx, vy);
    }
}

// ================= FP16 HMMA GEMM with 3-stage cp.async pipeline ==========
__device__ __forceinline__ void cp16(void* smem_dst, const void* gsrc) {
    unsigned d = (unsigned)__cvta_generic_to_shared(smem_dst);
    asm volatile("cp.async.cg.shared.global [%0], [%1], 16;" :: "r"(d), "l"(gsrc));
}
__device__ __forceinline__ void cp_commit() { asm volatile("cp.async.commit_group;"); }
__device__ __forceinline__ void cp_wait1() { asm volatile("cp.async.wait_group 1;"); }

__device__ __forceinline__ void ldsm4(unsigned& r0, unsigned& r1, unsigned& r2, unsigned& r3,
                                      const void* p) {
    unsigned a = (unsigned)__cvta_generic_to_shared(p);
    asm volatile("ldmatrix.sync.aligned.m8n8.x4.shared.b16 {%0,%1,%2,%3}, [%4];"
                 : "=r"(r0), "=r"(r1), "=r"(r2), "=r"(r3) : "r"(a));
}
__device__ __forceinline__ void ldsm4t(unsigned& r0, unsigned& r1, unsigned& r2, unsigned& r3,
                                       const void* p) {
    unsigned a = (unsigned)__cvta_generic_to_shared(p);
    asm volatile("ldmatrix.sync.aligned.m8n8.x4.trans.shared.b16 {%0,%1,%2,%3}, [%4];"
                 : "=r"(r0), "=r"(r1), "=r"(r2), "=r"(r3) : "r"(a));
}
__device__ __forceinline__ void mma16816(float* d, const unsigned* a, const unsigned* b) {
    asm volatile(
        "mma.sync.aligned.m16n8k16.row.col.f32.f16.f16.f32 "
        "{%0,%1,%2,%3},{%4,%5,%6,%7},{%8,%9},{%0,%1,%2,%3};\n"
        : "+f"(d[0]), "+f"(d[1]), "+f"(d[2]), "+f"(d[3])
        : "r"(a[0]), "r"(a[1]), "r"(a[2]), "r"(a[3]), "r"(b[0]), "r"(b[1]));
}

// OUTMODE: 0 = half, 1 = e4m3 fp8
template<bool HASBIAS, bool RELU, int OUTMODE>
__global__ __launch_bounds__(256) void hgemm(
    const __half* __restrict__ A, const __half* __restrict__ B,
    const float* __restrict__ bias, void* __restrict__ Cv,
    int M, int K, int Ncols)
{
    __shared__ __align__(16) __half As[3][128][40];
    __shared__ __align__(16) __half Bs[3][32][136];
    int tid = threadIdx.x;
    int bm = blockIdx.x * 128, bn = blockIdx.y * 128;
    int w = tid >> 5, lane = tid & 31;
    int wm = (w >> 2) * 64, wn = (w & 3) * 32;
    int lr16 = lane & 15, lh = lane >> 4;

    float acc[4][4][4];
#pragma unroll
    for (int mi = 0; mi < 4; ++mi)
#pragma unroll
        for (int nj = 0; nj < 4; ++nj)
#pragma unroll
            for (int q = 0; q < 4; ++q) acc[mi][nj][q] = 0.f;

    int ar = tid >> 2, ac = (tid & 3) * 8;
    int br = tid >> 4, bc = (tid & 15) * 8;
    const __half* Ap = A + (size_t)(bm + ar) * K + ac;
    const __half* Bp = B + (size_t)br * Ncols + bn + bc;

    int nstage = K >> 5;
    // prologue: commit g0 (stage 0), g1 (stage 1 or empty)
    cp16(&As[0][ar][ac], Ap);
    cp16(&As[0][ar + 64][ac], Ap + (size_t)64 * K);
    cp16(&Bs[0][br][bc], Bp);
    cp16(&Bs[0][br + 16][bc], Bp + (size_t)16 * Ncols);
    cp_commit();
    if (nstage > 1) {
        cp16(&As[1][ar][ac], Ap + 32);
        cp16(&As[1][ar + 64][ac], Ap + (size_t)64 * K + 32);
        cp16(&Bs[1][br][bc], Bp + (size_t)32 * Ncols);
        cp16(&Bs[1][br + 16][bc], Bp + (size_t)48 * Ncols);
    }
    cp_commit();

    for (int s = 0; s < nstage; ++s) {
        int cur = s % 3;
        cp_wait1();          // all groups except the most recent are done -> stage s ready
        __syncthreads();
        if (s + 2 < nstage) {
            int k0 = (s + 2) << 5;
            int nxt = (s + 2) % 3;
            cp16(&As[nxt][ar][ac], Ap + k0);
            cp16(&As[nxt][ar + 64][ac], Ap + (size_t)64 * K + k0);
            cp16(&Bs[nxt][br][bc], Bp + (size_t)k0 * Ncols);
            cp16(&Bs[nxt][br + 16][bc], Bp + (size_t)(k0 + 16) * Ncols);
        }
        cp_commit();         // one group per iteration (possibly empty)
#pragma unroll
        for (int k16 = 0; k16 < 2; ++k16) {
            unsigned af[4][4], bf[4][2];
#pragma unroll
            for (int mi = 0; mi < 4; ++mi)
                ldsm4(af[mi][0], af[mi][1], af[mi][2], af[mi][3],
                      &As[cur][wm + mi * 16 + lr16][k16 * 16 + lh * 8]);
#pragma unroll
            for (int p = 0; p < 2; ++p) {
                unsigned r0, r1, r2, r3;
                ldsm4t(r0, r1, r2, r3, &Bs[cur][k16 * 16 + lr16][wn + p * 16 + lh * 8]);
                bf[2 * p][0] = r0; bf[2 * p][1] = r1;
                bf[2 * p + 1][0] = r2; bf[2 * p + 1][1] = r3;
            }
#pragma unroll
            for (int mi = 0; mi < 4; ++mi)
#pragma unroll
                for (int nj = 0; nj < 4; ++nj)
                    mma16816(acc[mi][nj], af[mi], bf[nj]);
        }
    }

    __syncthreads();
    int lr = lane >> 2, lc = lane & 3;
#pragma unroll
    for (int mi = 0; mi < 4; ++mi) {
#pragma unroll
        for (int nj = 0; nj < 4; ++nj) {
            int row = bm + wm + mi * 16 + lr;
            int col = bn + wn + nj * 8 + 2 * lc;
            float b0 = 0.f, b1 = 0.f;
            if (HASBIAS) { b0 = bias[col]; b1 = bias[col + 1]; }
            float v0 = acc[mi][nj][0] + b0, v1 = acc[mi][nj][1] + b1;
            float v2 = acc[mi][nj][2] + b0, v3 = acc[mi][nj][3] + b1;
            if (RELU) {
                v0 = fmaxf(v0, 0.f); v1 = fmaxf(v1, 0.f);
                v2 = fmaxf(v2, 0.f); v3 = fmaxf(v3, 0.f);
            }
            if (OUTMODE == 0) {
                __half* C = (__half*)Cv;
                *(__half2*)(C + (size_t)row * Ncols + col) = __floats2half2_rn(v0, v1);
                *(__half2*)(C + (size_t)(row + 8) * Ncols + col) = __floats2half2_rn(v2, v3);
            } else {
                unsigned char* C8 = (unsigned char*)Cv;
                *(unsigned short*)(C8 + (size_t)row * Ncols + col) =
                    __nv_cvt_float2_to_fp8x2(make_float2(v0, v1), __NV_SATFINITE, __NV_E4M3);
                *(unsigned short*)(C8 + (size_t)(row + 8) * Ncols + col) =
                    __nv_cvt_float2_to_fp8x2(make_float2(v2, v3), __NV_SATFINITE, __NV_E4M3);
            }
        }
    }
}

// ---------------- z_t = g_t @ Wfce + bfce ----------------
__global__ __launch_bounds__(256) void proj_z_kernel(const float* __restrict__ Wfce,
                                                     const float* __restrict__ bfce) {
    __shared__ float part[256];
    int t = blockIdx.x;
    int tid = threadIdx.x;
    int j = tid & 63;
    int kq = tid >> 6;
    float a = 0.f;
#pragma unroll 8
    for (int k = kq * 64; k < kq * 64 + 64; ++k)
        a += d_gpool[t * HH + k] * __ldg(&Wfce[k * LL + j]);
    part[tid] = a;
    __syncthreads();
    if (tid < 64)
        d_zs[t * LL + tid] = part[tid] + part[64 + tid] + part[128 + tid] + part[192 + tid]
                             + bfce[tid];
}

// ---------------- persistent 2-layer LSTM + head (cluster of 8 CTAs, fp16 weights) ----------------
__device__ __forceinline__ float sigm(float x) { return 1.f / (1.f + expf(-x)); }

__device__ __forceinline__ void cluster_bar() {
    asm volatile("barrier.cluster.arrive.aligned;" ::: "memory");
    asm volatile("barrier.cluster.wait.aligned;" ::: "memory");
}

__global__ __launch_bounds__(256) __cluster_dims__(LSTM_BLOCKS, 1, 1) void lstm_kernel(
    const __half2* __restrict__ Wih0, const __half2* __restrict__ Whh0,
    const float* __restrict__ bih0, const float* __restrict__ bhh0,
    const __half2* __restrict__ Wih1, const __half2* __restrict__ Whh1,
    const float* __restrict__ bih1, const float* __restrict__ bhh1,
    const float* __restrict__ Whead, const float* __restrict__ bhead)
{
    __shared__ float x_sh[LL];
    __shared__ float h1_sh[HL];
    __shared__ float h2_sh[HL];
    __shared__ float2 part[256];
    int tid = threadIdx.x;
    int b = blockIdx.x;
    int p = tid & 63;
    int kq = tid >> 6;
    int jp = b * 64 + p;
    float c1 = 0.f, c2 = 0.f;
    if (tid < HL) { h1_sh[tid] = 0.f; h2_sh[tid] = 0.f; }
    __syncthreads();
    int round = 0;

    for (int t = 0; t < TT; ++t) {
        if (tid < LL) x_sh[tid] = d_zs[t * LL + tid];
        __syncthreads();

        float ax = 0.f, ay = 0.f;
#pragma unroll 8
        for (int k = kq * 64; k < kq * 64 + 64; ++k) {
            float h = h1_sh[k];
            float2 w = __half22float2(Whh0[(size_t)k * 512 + jp]);
            ax += h * w.x; ay += h * w.y;
        }
#pragma unroll 8
        for (int k = kq * 16; k < kq * 16 + 16; ++k) {
            float x = x_sh[k];
            float2 w = __half22float2(Wih0[(size_t)k * 512 + jp]);
            ax += x * w.x; ay += x * w.y;
        }
        part[tid] = make_float2(ax, ay);
        __syncthreads();
        int pb = round & 1;
        if (tid < 64) {
            float2 a0 = part[tid], a1 = part[64 + tid], a2 = part[128 + tid], a3 = part[192 + tid];
            float2 bi = ((const float2*)bih0)[b * 64 + tid];
            float2 bh = ((const float2*)bhh0)[b * 64 + tid];
            float2 g = make_float2(a0.x + a1.x + a2.x + a3.x + bi.x + bh.x,
                                   a0.y + a1.y + a2.y + a3.y + bi.y + bh.y);
            __stcg(&((float2*)&d_gates[pb][0])[b * 64 + tid], g);
        }
        round++;
        __threadfence();
        cluster_bar();
        {
            float gi = __ldcg(&d_gates[pb][tid]);
            float gf = __ldcg(&d_gates[pb][256 + tid]);
            float gg = __ldcg(&d_gates[pb][512 + tid]);
            float go = __ldcg(&d_gates[pb][768 + tid]);
            c1 = sigm(gf) * c1 + sigm(gi) * tanhf(gg);
            h1_sh[tid] = sigm(go) * tanhf(c1);
        }
        __syncthreads();

        ax = 0.f; ay = 0.f;
#pragma unroll 8
        for (int k = kq * 64; k < kq * 64 + 64; ++k) {
            float h2v = h2_sh[k];
            float h1v = h1_sh[k];
            float2 wh = __half22float2(Whh1[(size_t)k * 512 + jp]);
            float2 wi = __half22float2(Wih1[(size_t)k * 512 + jp]);
            ax += h2v * wh.x + h1v * wi.x;
            ay += h2v * wh.y + h1v * wi.y;
        }
        part[tid] = make_float2(ax, ay);
        __syncthreads();
        pb = round & 1;
        if (tid < 64) {
            float2 a0 = part[tid], a1 = part[64 + tid], a2 = part[128 + tid], a3 = part[192 + tid];
            float2 bi = ((const float2*)bih1)[b * 64 + tid];
            float2 bh = ((const float2*)bhh1)[b * 64 + tid];
            float2 g = make_float2(a0.x + a1.x + a2.x + a3.x + bi.x + bh.x,
                                   a0.y + a1.y + a2.y + a3.y + bi.y + bh.y);
            __stcg(&((float2*)&d_gates[pb][0])[b * 64 + tid], g);
        }
        round++;
        __threadfence();
        cluster_bar();
        {
            float gi = __ldcg(&d_gates[pb][tid]);
            float gf = __ldcg(&d_gates[pb][256 + tid]);
            float gg = __ldcg(&d_gates[pb][512 + tid]);
            float go = __ldcg(&d_gates[pb][768 + tid]);
            c2 = sigm(gf) * c2 + sigm(gi) * tanhf(gg);
            h2_sh[tid] = sigm(go) * tanhf(c2);
        }
        __syncthreads();
    }

    if (b == 0 && tid < LL) {
        float a = bhead[tid];
        for (int k = 0; k < HL; ++k)
            a += h2_sh[k] * Whead[k * LL + tid];
        d_zfin[tid] = a;
    }
}

// ---------------- decoder fc: relu(z @ Wfcd + bfcd) -> half [N, L] ----------------
__global__ void fcd_kernel(const float* __restrict__ Wfcd, const float* __restrict__ bfcd,
                           __half2* __restrict__ out) {
    __shared__ float z[LL];
    if (threadIdx.x < LL) z[threadIdx.x] = d_zfin[threadIdx.x];
    __syncthreads();
    int q = blockIdx.x * blockDim.x + threadIdx.x;
    if (q >= NN * LL / 2) return;
    float2 bb = ((const float2*)bfcd)[q];
    float ax = bb.x, ay = bb.y;
#pragma unroll 8
    for (int k = 0; k < LL; ++k) {
        float2 w = ((const float2*)(Wfcd + (size_t)k * (NN * LL)))[q];
        ax += z[k] * w.x;
        ay += z[k] * w.y;
    }
    out[q] = __floats2half2_rn(fmaxf(ax, 0.f), fmaxf(ay, 0.f));
}

// ---------------- launch ----------------
extern "C" void kernel_launch(void* const* d_in, const int* in_sizes, int n_in,
                              void* d_out, int out_size) {
    const float* xs        = (const float*)d_in[0];
    const float* edge_attr = (const float*)d_in[1];
    const float* We0  = (const float*)d_in[2];
    const float* be0  = (const float*)d_in[3];
    const float* We1  = (const float*)d_in[4];
    const float* be1  = (const float*)d_in[5];
    const float* Wfce = (const float*)d_in[6];
    const float* bfce = (const float*)d_in[7];
    const float* Wih0 = (const float*)d_in[8];
    const float* Whh0 = (const float*)d_in[9];
    const float* bih0 = (const float*)d_in[10];
    const float* bhh0 = (const float*)d_in[11];
    const float* Wih1 = (const float*)d_in[12];
    const float* Whh1 = (const float*)d_in[13];
    const float* bih1 = (const float*)d_in[14];
    const float* bhh1 = (const float*)d_in[15];
    const float* Whead = (const float*)d_in[16];
    const float* bhead = (const float*)d_in[17];
    const float* Wfcd = (const float*)d_in[18];
    const float* bfcd = (const float*)d_in[19];
    const float* Wd0  = (const float*)d_in[20];
    const float* bd0  = (const float*)d_in[21];
    const float* Wd1  = (const float*)d_in[22];
    const float* bd1  = (const float*)d_in[23];
    const float* Wd2  = (const float*)d_in[24];
    const float* bd2  = (const float*)d_in[25];
    const void*  eidx = d_in[26];

    float *buf0, *buf1;
    __half *hbuf, *we0h, *we1h, *wd0h, *wd1h, *wd2h, *wih0h, *whh0h, *wih1h, *whh1h;
    unsigned char *x8, *h8;
    cudaGetSymbolAddress((void**)&buf0, d_buf0);
    cudaGetSymbolAddress((void**)&buf1, d_buf1);
    cudaGetSymbolAddress((void**)&hbuf, d_hbuf);
    cudaGetSymbolAddress((void**)&x8, d_x8);
    cudaGetSymbolAddress((void**)&h8, d_h8);
    cudaGetSymbolAddress((void**)&we0h, d_We0h);
    cudaGetSymbolAddress((void**)&we1h, d_We1h);
    cudaGetSymbolAddress((void**)&wd0h, d_Wd0h);
    cudaGetSymbolAddress((void**)&wd1h, d_Wd1h);
    cudaGetSymbolAddress((void**)&wd2h, d_Wd2h);
    cudaGetSymbolAddress((void**)&wih0h, d_Wih0h);
    cudaGetSymbolAddress((void**)&whh0h, d_Whh0h);
    cudaGetSymbolAddress((void**)&wih1h, d_Wih1h);
    cudaGetSymbolAddress((void**)&whh1h, d_Whh1h);

    const int MPAD = 10112;

    static cudaStream_t s2 = [](){ cudaStream_t t; cudaStreamCreateWithFlags(&t, cudaStreamNonBlocking); return t; }();
    static cudaEvent_t evFork = [](){ cudaEvent_t e; cudaEventCreateWithFlags(&e, cudaEventDisableTiming); return e; }();
    static cudaEvent_t evJoin = [](){ cudaEvent_t e; cudaEventCreateWithFlags(&e, cudaEventDisableTiming); return e; }();

    cudaEventRecord(evFork, 0);
    cudaStreamWaitEvent(s2, evFork, 0);
    f2h_all_kernel<<<(N2_TOT + 255) / 256, 256, 0, s2>>>(
        xs, We0, We1, Wd0, Wd1, Wd2, Wih0, Whh0, Wih1, Whh1,
        (unsigned short*)x8, (__half2*)we0h, (__half2*)we1h,
        (__half2*)wd0h, (__half2*)wd1h, (__half2*)wd2h,
        (__half2*)wih0h, (__half2*)whh0h, (__half2*)wih1h, (__half2*)whh1h);
    cudaEventRecord(evJoin, s2);

    // ---- preprocessing (main stream) ----
    zero_kernel<<<(NN + 255) / 256, 256>>>(eidx);
    count_kernel<<<(EN + 255) / 256, 256>>>(eidx, edge_attr);
    scanA_kernel<<<10, 1024>>>();
    scanB_kernel<<<1, 32>>>();
    scanC_kernel<<<10, 1024>>>();
    fill_kernel<<<(EN + 255) / 256, 256>>>(eidx, edge_attr);

    cudaStreamWaitEvent(0, evJoin, 0);

    // ---- encoder (fp8 gathers, HFMA2 accumulate) ----
    agg_enc0_kernel<<<NN, 128>>>((const uint4*)x8, (uint4*)buf0);
    hgemm<true, true, 0><<<dim3(TT * NN / 128, HH / 128), 256>>>(
        (const __half*)buf0, we0h, be0, buf1, TT * NN, FF, HH);
    hgemm<false, false, 1><<<dim3(TT * NN / 128, HH / 128), 256>>>(
        (const __half*)buf1, we1h, nullptr, h8, TT * NN, HH, HH);
    agg_pool_kernel<<<1250, 256>>>((const uint4*)h8, be1);
    proj_z_kernel<<<TT, 256>>>(Wfce, bfce);

    // ---- LSTM + head ----
    lstm_kernel<<<LSTM_BLOCKS, 256>>>(
        (const __half2*)wih0h, (const __half2*)whh0h, bih0, bhh0,
        (const __half2*)wih1h, (const __half2*)whh1h, bih1, bhh1, Whead, bhead);

    // ---- decoder (fp16) ----
    fcd_kernel<<<(NN * LL / 2 + 255) / 256, 256>>>(Wfcd, bfcd, (__half2*)hbuf);
    agg_dec_kernel<LL / 2, 4, false, false><<<(NN + 3) / 4, 128>>>(
        (const __half2*)hbuf, (__half*)buf0, nullptr);
    hgemm<true, true, 0><<<dim3(MPAD / 128, HH / 128), 256>>>(
        (const __half*)buf0, wd0h, bd0, buf1, MPAD, LL, HH);
    hgemm<false, false, 0><<<dim3(MPAD / 128, HH / 128), 256>>>(
        (const __half*)buf1, wd1h, nullptr, hbuf, MPAD, HH, HH);
    agg_dec_kernel<HH / 2, 2, true, false><<<(NN + 1) / 2, 256>>>(
        (const __half2*)hbuf, (__half*)buf0, bd1);
    hgemm<false, false, 0><<<dim3(MPAD / 128, FF / 128), 256>>>(
        (const __half*)buf0, wd2h, nullptr, buf1, MPAD, HH, FF);
    agg_dec_kernel<FF / 2, 2, false, true><<<(NN + 1) / 2, 128>>>(
        (const __half2*)buf1, (float*)d_out, bd2);
}